// round 1
// baseline (speedup 1.0000x reference)
#include <cuda_runtime.h>
#include <cuda_bf16.h>
#include <cstdint>

// Problem constants
#define SEQ       128
#define BATCH     64
#define EMBED     512
#define HDIM      1024
#define NG        4096      // 4*H gate width
#define TSTEPS    127       // seq-1 LSTM steps
#define SEL_START 65        // num_unary + 2 = (128-2)/2 + 2
#define SEL_COUNT 62        // 127 - 65
#define VOCAB     32000

// ---------------- device scratch (no allocations allowed) ----------------
__device__ int   g_is64;
__device__ float g_X[TSTEPS * BATCH * EMBED];   // gathered embeddings (t-major)
__device__ float g_P[TSTEPS * BATCH * NG];      // x @ w_ih^T + b_ih + b_hh
__device__ float g_gates[BATCH * NG];
__device__ float g_h[BATCH * HDIM];
__device__ float g_c[BATCH * HDIM];

// ---------------- prob dtype detection (int32 vs int64) ----------------
// If prob is int64 (little-endian, values in [0,32000)), every odd 32-bit
// word of the buffer is zero. If int32, odd words are random tokens.
__global__ void detect_kernel(const int* __restrict__ prob32) {
    __shared__ int any;
    if (threadIdx.x == 0) any = 0;
    __syncthreads();
    int local = 0;
    for (int i = 2 * threadIdx.x + 1; i < BATCH * SEQ; i += 2 * blockDim.x)
        local |= prob32[i];
    if (local) atomicOr(&any, 1);
    __syncthreads();
    if (threadIdx.x == 0) g_is64 = (any == 0) ? 1 : 0;
}

// ---------------- state init ----------------
__global__ void init_state(const float* __restrict__ h0, const float* __restrict__ c0) {
    int i = blockIdx.x * blockDim.x + threadIdx.x;
    g_h[i] = h0[i];
    g_c[i] = c0[i];
}

// ---------------- embedding gather: X[t*64+b, :] = table[prob[b,t], :] ----
__global__ void gather_kernel(const void* __restrict__ prob,
                              const float* __restrict__ table) {
    int row = blockIdx.x;           // t*64 + b, t in [0,127)
    int t = row >> 6;
    int b = row & 63;
    long long tok;
    if (g_is64) tok = ((const long long*)prob)[b * SEQ + t];
    else        tok = (long long)((const int*)prob)[b * SEQ + t];
    const float4* src = (const float4*)(table + (size_t)tok * EMBED);
    float4* dst = (float4*)(g_X + (size_t)row * EMBED);
    dst[threadIdx.x] = src[threadIdx.x];   // 128 threads x float4 = 512 floats
}

// ---------------- bf16 3-split GEMM: C[M,N] = A[M,K] @ B[N,K]^T + addend --
// Tiles: BM=64, BN=64, BK=32. 8 warps (256 thr), warp grid 4(m) x 2(n),
// each warp computes 16x32 via 4 x mma.m16n8k16, 3 MMAs per (hi/lo split).
#define BM 64
#define BN 64
#define BK 32
#define LDK (BK + 8)

__device__ __forceinline__ void mma16816(float* c, const uint32_t* a, const uint32_t* b) {
    asm volatile(
        "mma.sync.aligned.m16n8k16.row.col.f32.bf16.bf16.f32 "
        "{%0,%1,%2,%3}, {%4,%5,%6,%7}, {%8,%9}, {%0,%1,%2,%3};\n"
        : "+f"(c[0]), "+f"(c[1]), "+f"(c[2]), "+f"(c[3])
        : "r"(a[0]), "r"(a[1]), "r"(a[2]), "r"(a[3]), "r"(b[0]), "r"(b[1]));
}

__device__ __forceinline__ void cvt_split(__nv_bfloat16* hi, __nv_bfloat16* lo, float v) {
    __nv_bfloat16 h = __float2bfloat16(v);
    *hi = h;
    *lo = __float2bfloat16(v - __bfloat162float(h));
}

__global__ __launch_bounds__(256)
void gemm_bf16split(const float* __restrict__ A,   // [M,K] row-major
                    const float* __restrict__ B,   // [N,K] row-major (used as B^T)
                    float* __restrict__ C,         // [M,N]
                    int M, int N, int K,
                    const float* __restrict__ bias1,  // per-col bias or null
                    const float* __restrict__ bias2,  // per-col bias or null
                    const float* __restrict__ addm)   // [M,N] matrix addend or null
{
    __shared__ __nv_bfloat16 Ahi[BM * LDK], Alo[BM * LDK];
    __shared__ __nv_bfloat16 Bhi[BN * LDK], Blo[BN * LDK];

    int tid  = threadIdx.x;
    int warp = tid >> 5, lane = tid & 31;
    int mw = (warp & 3) << 4;        // 0,16,32,48
    int nw = (warp >> 2) << 5;       // 0,32
    int gid = lane >> 2;             // 0..7
    int kb  = (lane & 3) << 1;       // 0,2,4,6

    int m0 = blockIdx.y * BM;
    int n0 = blockIdx.x * BN;

    int lrow = tid >> 2;             // 0..63
    int lk   = (tid & 3) << 3;       // 0,8,16,24

    float acc[4][4];
#pragma unroll
    for (int i = 0; i < 4; i++)
#pragma unroll
        for (int j = 0; j < 4; j++) acc[i][j] = 0.0f;

    for (int k0 = 0; k0 < K; k0 += BK) {
        // load + split A tile
        {
            const float* ap = A + (size_t)(m0 + lrow) * K + k0 + lk;
            float4 v0 = *(const float4*)ap;
            float4 v1 = *(const float4*)(ap + 4);
            __nv_bfloat16* h = &Ahi[lrow * LDK + lk];
            __nv_bfloat16* l = &Alo[lrow * LDK + lk];
            cvt_split(h + 0, l + 0, v0.x); cvt_split(h + 1, l + 1, v0.y);
            cvt_split(h + 2, l + 2, v0.z); cvt_split(h + 3, l + 3, v0.w);
            cvt_split(h + 4, l + 4, v1.x); cvt_split(h + 5, l + 5, v1.y);
            cvt_split(h + 6, l + 6, v1.z); cvt_split(h + 7, l + 7, v1.w);
        }
        // load + split B tile
        {
            const float* bp = B + (size_t)(n0 + lrow) * K + k0 + lk;
            float4 v0 = *(const float4*)bp;
            float4 v1 = *(const float4*)(bp + 4);
            __nv_bfloat16* h = &Bhi[lrow * LDK + lk];
            __nv_bfloat16* l = &Blo[lrow * LDK + lk];
            cvt_split(h + 0, l + 0, v0.x); cvt_split(h + 1, l + 1, v0.y);
            cvt_split(h + 2, l + 2, v0.z); cvt_split(h + 3, l + 3, v0.w);
            cvt_split(h + 4, l + 4, v1.x); cvt_split(h + 5, l + 5, v1.y);
            cvt_split(h + 6, l + 6, v1.z); cvt_split(h + 7, l + 7, v1.w);
        }
        __syncthreads();

#pragma unroll
        for (int ks = 0; ks < BK; ks += 16) {
            uint32_t ah[4], al[4];
            int r0 = (mw + gid) * LDK, r1 = (mw + gid + 8) * LDK;
            ah[0] = *(const uint32_t*)&Ahi[r0 + ks + kb];
            ah[1] = *(const uint32_t*)&Ahi[r1 + ks + kb];
            ah[2] = *(const uint32_t*)&Ahi[r0 + ks + kb + 8];
            ah[3] = *(const uint32_t*)&Ahi[r1 + ks + kb + 8];
            al[0] = *(const uint32_t*)&Alo[r0 + ks + kb];
            al[1] = *(const uint32_t*)&Alo[r1 + ks + kb];
            al[2] = *(const uint32_t*)&Alo[r0 + ks + kb + 8];
            al[3] = *(const uint32_t*)&Alo[r1 + ks + kb + 8];
#pragma unroll
            for (int nb = 0; nb < 4; nb++) {
                int nr = (nw + nb * 8 + gid) * LDK;
                uint32_t bh[2], bl[2];
                bh[0] = *(const uint32_t*)&Bhi[nr + ks + kb];
                bh[1] = *(const uint32_t*)&Bhi[nr + ks + kb + 8];
                bl[0] = *(const uint32_t*)&Blo[nr + ks + kb];
                bl[1] = *(const uint32_t*)&Blo[nr + ks + kb + 8];
                mma16816(acc[nb], ah, bh);   // hi*hi
                mma16816(acc[nb], ah, bl);   // hi*lo
                mma16816(acc[nb], al, bh);   // lo*hi
            }
        }
        __syncthreads();
    }

    // epilogue
#pragma unroll
    for (int nb = 0; nb < 4; nb++) {
        int col = n0 + nw + nb * 8 + kb;
        int row0 = m0 + mw + gid;
        int row1 = row0 + 8;
        float b0c = 0.0f, b1c = 0.0f;
        if (bias1) { b0c += bias1[col];  b1c += bias1[col + 1]; }
        if (bias2) { b0c += bias2[col];  b1c += bias2[col + 1]; }
        float e00 = b0c, e01 = b1c, e10 = b0c, e11 = b1c;
        if (addm) {
            e00 += addm[(size_t)row0 * N + col];
            e01 += addm[(size_t)row0 * N + col + 1];
            e10 += addm[(size_t)row1 * N + col];
            e11 += addm[(size_t)row1 * N + col + 1];
        }
        C[(size_t)row0 * N + col]     = acc[nb][0] + e00;
        C[(size_t)row0 * N + col + 1] = acc[nb][1] + e01;
        C[(size_t)row1 * N + col]     = acc[nb][2] + e10;
        C[(size_t)row1 * N + col + 1] = acc[nb][3] + e11;
    }
}

// ---------------- LSTM cell + fused output dot ----------------
__global__ __launch_bounds__(1024)
void lstm_cell(const float* __restrict__ w_ans, const float* __restrict__ b_ans,
               float* __restrict__ out, int t) {
    __shared__ float red[32];
    int b = blockIdx.x;
    int j = threadIdx.x;
    const float* g = g_gates + (size_t)b * NG;
    float gi = g[j], gf = g[j + HDIM], gg = g[j + 2 * HDIM], go = g[j + 3 * HDIM];
    float vi = 1.0f / (1.0f + expf(-gi));
    float vf = 1.0f / (1.0f + expf(-gf));
    float vg = tanhf(gg);
    float vo = 1.0f / (1.0f + expf(-go));
    float c = vf * g_c[b * HDIM + j] + vi * vg;
    float h = vo * tanhf(c);
    g_c[b * HDIM + j] = c;
    g_h[b * HDIM + j] = h;

    // reduce h . w_ans over 1024 lanes
    float p = h * w_ans[j];
#pragma unroll
    for (int off = 16; off; off >>= 1) p += __shfl_xor_sync(0xFFFFFFFFu, p, off);
    int warp = j >> 5, lane = j & 31;
    if (lane == 0) red[warp] = p;
    __syncthreads();
    if (warp == 0) {
        float v = red[lane];
#pragma unroll
        for (int off = 16; off; off >>= 1) v += __shfl_xor_sync(0xFFFFFFFFu, v, off);
        if (lane == 0 && t >= SEL_START)
            out[b * SEL_COUNT + (t - SEL_START)] = v + b_ans[0];
    }
}

// ---------------- launch ----------------
extern "C" void kernel_launch(void* const* d_in, const int* in_sizes, int n_in,
                              void* d_out, int out_size) {
    (void)in_sizes; (void)n_in; (void)out_size;
    const void*  prob   = d_in[0];
    // d_in[1] = ans (unused)
    const float* table  = (const float*)d_in[2];
    const float* w_ih   = (const float*)d_in[3];
    const float* w_hh   = (const float*)d_in[4];
    const float* b_ih   = (const float*)d_in[5];
    const float* b_hh   = (const float*)d_in[6];
    const float* w_ans  = (const float*)d_in[7];
    const float* b_ans  = (const float*)d_in[8];
    const float* h0     = (const float*)d_in[9];
    const float* c0     = (const float*)d_in[10];
    float* out = (float*)d_out;

    static float *pX = nullptr, *pP = nullptr, *pG = nullptr, *pH = nullptr;
    if (!pX) {
        cudaGetSymbolAddress((void**)&pX, g_X);
        cudaGetSymbolAddress((void**)&pP, g_P);
        cudaGetSymbolAddress((void**)&pG, g_gates);
        cudaGetSymbolAddress((void**)&pH, g_h);
    }

    detect_kernel<<<1, 256>>>((const int*)prob);
    init_state<<<BATCH, HDIM>>>(h0, c0);
    gather_kernel<<<TSTEPS * BATCH, 128>>>(prob, table);

    // P = X @ w_ih^T + (b_ih + b_hh)   [8128 x 4096]
    gemm_bf16split<<<dim3(NG / BN, (TSTEPS * BATCH) / BM), 256>>>(
        pX, w_ih, pP, TSTEPS * BATCH, NG, EMBED, b_ih, b_hh, nullptr);

    for (int t = 0; t < TSTEPS; t++) {
        // gates = h @ w_hh^T + P[t]   [64 x 4096]
        gemm_bf16split<<<dim3(NG / BN, 1), 256>>>(
            pH, w_hh, pG, BATCH, NG, HDIM, nullptr, nullptr,
            pP + (size_t)t * BATCH * NG);
        lstm_cell<<<BATCH, HDIM>>>(w_ans, b_ans, out, t);
    }
}

// round 2
// speedup vs baseline: 2.7699x; 2.7699x over previous
#include <cuda_runtime.h>
#include <cuda_bf16.h>
#include <cstdint>

#define SEQ       128
#define BATCH     64
#define EMBED     512
#define HDIM      1024
#define NG        4096
#define TSTEPS    127
#define SEL_START 65
#define SEL_COUNT 62
#define MPAD      8192          // 127*64=8128 padded to 8192 (pad rows stay zero)

// ---------------- device scratch ----------------
__device__ __nv_bfloat16 g_Xhi[MPAD * EMBED];
__device__ __nv_bfloat16 g_Xlo[MPAD * EMBED];
__device__ __nv_bfloat16 g_Wih_hi[NG * EMBED];
__device__ __nv_bfloat16 g_Wih_lo[NG * EMBED];
__device__ __nv_bfloat16 g_Whh_hi[NG * HDIM];
__device__ __nv_bfloat16 g_Whh_lo[NG * HDIM];
__device__ float g_bsum[NG];
__device__ float g_P[TSTEPS * BATCH * NG];     // preactivations, gate-interleaved cols
__device__ __nv_bfloat16 g_hhi[BATCH * HDIM];
__device__ __nv_bfloat16 g_hlo[BATCH * HDIM];
__device__ float g_c[BATCH * HDIM];
__device__ int   g_is64;

// ---------------- helpers ----------------
__device__ __forceinline__ void cvt_split(__nv_bfloat16* hi, __nv_bfloat16* lo, float v) {
    __nv_bfloat16 h = __float2bfloat16(v);
    *hi = h;
    *lo = __float2bfloat16(v - __bfloat162float(h));
}

__device__ __forceinline__ void mma16816(float* c, const uint32_t* a, const uint32_t* b) {
    asm volatile(
        "mma.sync.aligned.m16n8k16.row.col.f32.bf16.bf16.f32 "
        "{%0,%1,%2,%3}, {%4,%5,%6,%7}, {%8,%9}, {%0,%1,%2,%3};\n"
        : "+f"(c[0]), "+f"(c[1]), "+f"(c[2]), "+f"(c[3])
        : "r"(a[0]), "r"(a[1]), "r"(a[2]), "r"(a[3]), "r"(b[0]), "r"(b[1]));
}

__device__ __forceinline__ void cpa16(void* smem, const void* g) {
    uint32_t s = (uint32_t)__cvta_generic_to_shared(smem);
    asm volatile("cp.async.cg.shared.global [%0], [%1], 16;\n" :: "r"(s), "l"(g));
}
__device__ __forceinline__ void cpa_commit() { asm volatile("cp.async.commit_group;\n"); }
__device__ __forceinline__ void cpa_wait1()  { asm volatile("cp.async.wait_group 1;\n"); }
__device__ __forceinline__ void cpa_wait0()  { asm volatile("cp.async.wait_group 0;\n"); }

__device__ __forceinline__ uint32_t ld32(const __nv_bfloat16* p) {
    return *(const uint32_t*)p;
}

// ---------------- dtype detection ----------------
__global__ void detect_kernel(const int* __restrict__ prob32) {
    __shared__ int any;
    if (threadIdx.x == 0) any = 0;
    __syncthreads();
    int local = 0;
    for (int i = 2 * threadIdx.x + 1; i < BATCH * SEQ; i += 2 * blockDim.x)
        local |= prob32[i];
    if (local) atomicOr(&any, 1);
    __syncthreads();
    if (threadIdx.x == 0) g_is64 = (any == 0) ? 1 : 0;
}

// ---------------- init ----------------
__global__ void init_state(const float* __restrict__ h0, const float* __restrict__ c0) {
    int i = blockIdx.x * blockDim.x + threadIdx.x;
    cvt_split(&g_hhi[i], &g_hlo[i], h0[i]);
    g_c[i] = c0[i];
}

__global__ void init_out(float* __restrict__ out, const float* __restrict__ b_ans) {
    int i = blockIdx.x * blockDim.x + threadIdx.x;
    if (i < BATCH * SEL_COUNT) out[i] = b_ans[0];
}

// ---------------- embedding gather + split ----------------
__global__ void gather_split(const void* __restrict__ prob, const float* __restrict__ table) {
    int row = blockIdx.x;            // t*64 + b
    int t = row >> 6, b = row & 63;
    long long tok;
    if (g_is64) tok = ((const long long*)prob)[b * SEQ + t];
    else        tok = (long long)((const int*)prob)[b * SEQ + t];
    float4 v = ((const float4*)(table + (size_t)tok * EMBED))[threadIdx.x];
    int o = row * EMBED + threadIdx.x * 4;
    cvt_split(&g_Xhi[o + 0], &g_Xlo[o + 0], v.x);
    cvt_split(&g_Xhi[o + 1], &g_Xlo[o + 1], v.y);
    cvt_split(&g_Xhi[o + 2], &g_Xlo[o + 2], v.z);
    cvt_split(&g_Xhi[o + 3], &g_Xlo[o + 3], v.w);
}

// ---------------- weight conversion (gate-interleave reorder: n = 4*j + g) --
__global__ void convert_wih(const float* __restrict__ w_ih,
                            const float* __restrict__ b_ih,
                            const float* __restrict__ b_hh) {
    int n = blockIdx.x;
    int j = n >> 2, g = n & 3;
    int r = g * HDIM + j;
    float4 v = ((const float4*)(w_ih + (size_t)r * EMBED))[threadIdx.x];
    int o = n * EMBED + threadIdx.x * 4;
    cvt_split(&g_Wih_hi[o + 0], &g_Wih_lo[o + 0], v.x);
    cvt_split(&g_Wih_hi[o + 1], &g_Wih_lo[o + 1], v.y);
    cvt_split(&g_Wih_hi[o + 2], &g_Wih_lo[o + 2], v.z);
    cvt_split(&g_Wih_hi[o + 3], &g_Wih_lo[o + 3], v.w);
    if (threadIdx.x == 0) g_bsum[n] = b_ih[r] + b_hh[r];
}

__global__ void convert_whh(const float* __restrict__ w_hh) {
    int n = blockIdx.x;
    int j = n >> 2, g = n & 3;
    int r = g * HDIM + j;
    float4 v = ((const float4*)(w_hh + (size_t)r * HDIM))[threadIdx.x];
    int o = n * HDIM + threadIdx.x * 4;
    cvt_split(&g_Whh_hi[o + 0], &g_Whh_lo[o + 0], v.x);
    cvt_split(&g_Whh_hi[o + 1], &g_Whh_lo[o + 1], v.y);
    cvt_split(&g_Whh_hi[o + 2], &g_Whh_lo[o + 2], v.z);
    cvt_split(&g_Whh_hi[o + 3], &g_Whh_lo[o + 3], v.w);
}

// ---------------- pre-GEMM: P = X @ Wih^T + bsum  [8192x4096, K=512] ------
// BM=128 BN=128 BK=32, 256 threads, cp.async double-buffered.
#define LDKp 40
#define PSTG 20480   // bf16 elems per stage: 4 bufs * 128*40

__global__ __launch_bounds__(256, 1)
void gemm_pre() {
    extern __shared__ __nv_bfloat16 dsm[];
    const int tid = threadIdx.x, warp = tid >> 5, lane = tid & 31;
    const int gid = lane >> 2, kb = (lane & 3) << 1;
    const int m_off = (warp >> 2) << 6;   // 0,64
    const int n_off = (warp & 3) << 5;    // 0,32,64,96
    const int m0 = blockIdx.y << 7;
    const int n0 = blockIdx.x << 7;

    float acc[4][4][4];
#pragma unroll
    for (int a = 0; a < 4; a++)
#pragma unroll
        for (int b = 0; b < 4; b++)
#pragma unroll
            for (int cc = 0; cc < 4; cc++) acc[a][b][cc] = 0.0f;

    auto load_stage = [&](int s, int k0) {
        __nv_bfloat16* base = dsm + s * PSTG;
#pragma unroll
        for (int it = 0; it < 8; it++) {
            int op = it * 256 + tid;        // 0..2047
            int buf = op >> 9;              // 0..3
            int r = (op & 511) >> 2;        // 0..127
            int c = op & 3;                 // 0..3
            __nv_bfloat16* dst = base + buf * 5120 + r * LDKp + c * 8;
            const __nv_bfloat16* src;
            if (buf == 0)      src = g_Xhi    + (size_t)(m0 + r) * EMBED + k0 + c * 8;
            else if (buf == 1) src = g_Xlo    + (size_t)(m0 + r) * EMBED + k0 + c * 8;
            else if (buf == 2) src = g_Wih_hi + (size_t)(n0 + r) * EMBED + k0 + c * 8;
            else               src = g_Wih_lo + (size_t)(n0 + r) * EMBED + k0 + c * 8;
            cpa16(dst, src);
        }
        cpa_commit();
    };

    auto compute = [&](int s) {
        const __nv_bfloat16* Ahi = dsm + s * PSTG;
        const __nv_bfloat16* Alo = Ahi + 5120;
        const __nv_bfloat16* Bhi = Ahi + 10240;
        const __nv_bfloat16* Blo = Ahi + 15360;
#pragma unroll
        for (int ks = 0; ks < 32; ks += 16) {
            uint32_t ah[4][4], al[4][4];
#pragma unroll
            for (int mf = 0; mf < 4; mf++) {
                int ra = (m_off + mf * 16 + gid) * LDKp + ks + kb;
                int rb = ra + 8 * LDKp;
                ah[mf][0] = ld32(Ahi + ra);     ah[mf][1] = ld32(Ahi + rb);
                ah[mf][2] = ld32(Ahi + ra + 8); ah[mf][3] = ld32(Ahi + rb + 8);
                al[mf][0] = ld32(Alo + ra);     al[mf][1] = ld32(Alo + rb);
                al[mf][2] = ld32(Alo + ra + 8); al[mf][3] = ld32(Alo + rb + 8);
            }
#pragma unroll
            for (int nf = 0; nf < 4; nf++) {
                int rn = (n_off + nf * 8 + gid) * LDKp + ks + kb;
                uint32_t bh[2] = { ld32(Bhi + rn), ld32(Bhi + rn + 8) };
                uint32_t bl[2] = { ld32(Blo + rn), ld32(Blo + rn + 8) };
#pragma unroll
                for (int mf = 0; mf < 4; mf++) {
                    mma16816(acc[mf][nf], ah[mf], bh);
                    mma16816(acc[mf][nf], ah[mf], bl);
                    mma16816(acc[mf][nf], al[mf], bh);
                }
            }
        }
    };

    const int KT = EMBED / 32;  // 16
    load_stage(0, 0);
    for (int kt = 0; kt < KT; kt++) {
        if (kt + 1 < KT) load_stage((kt + 1) & 1, (kt + 1) * 32);
        if (kt + 1 < KT) cpa_wait1(); else cpa_wait0();
        __syncthreads();
        compute(kt & 1);
        __syncthreads();
    }

#pragma unroll
    for (int mf = 0; mf < 4; mf++)
#pragma unroll
        for (int nf = 0; nf < 4; nf++) {
            int row = m0 + m_off + mf * 16 + gid;
            int col = n0 + n_off + nf * 8 + kb;
            float b0 = g_bsum[col], b1 = g_bsum[col + 1];
            if (row < TSTEPS * BATCH) {
                g_P[(size_t)row * NG + col]     = acc[mf][nf][0] + b0;
                g_P[(size_t)row * NG + col + 1] = acc[mf][nf][1] + b1;
            }
            if (row + 8 < TSTEPS * BATCH) {
                g_P[(size_t)(row + 8) * NG + col]     = acc[mf][nf][2] + b0;
                g_P[(size_t)(row + 8) * NG + col + 1] = acc[mf][nf][3] + b1;
            }
        }
}

// ---------------- fused recurrent step: gates GEMM + LSTM cell + out dot --
// C[64, 32] = h[64,1024] @ Whh_tile^T, BK=64, 256 threads, grid 128 CTAs.
#define LDKr 72
#define RSTG 13824   // bf16 elems per stage: 2*(64*72) + 2*(32*72)

__global__ __launch_bounds__(256, 1)
void lstm_fused(const float* __restrict__ w_ans, float* __restrict__ out, int t) {
    extern __shared__ __nv_bfloat16 dsm[];
    const int tid = threadIdx.x, warp = tid >> 5, lane = tid & 31;
    const int gid = lane >> 2, kb = (lane & 3) << 1;
    const int m_off = (warp & 3) << 4;    // 0..48
    const int n_off = (warp >> 2) << 4;   // 0,16
    const int n0 = blockIdx.x << 5;

    float acc[2][4];
#pragma unroll
    for (int i = 0; i < 2; i++)
#pragma unroll
        for (int j = 0; j < 4; j++) acc[i][j] = 0.0f;

    auto load_stage = [&](int s, int k0) {
        __nv_bfloat16* base = dsm + s * RSTG;
#pragma unroll
        for (int it = 0; it < 6; it++) {
            int op = it * 256 + tid;        // 0..1535
            __nv_bfloat16* dst;
            const __nv_bfloat16* src;
            if (op < 1024) {                // A = h hi/lo, 64 rows x 8 chunks
                int h = op >> 9;
                int r = (op & 511) >> 3, c = op & 7;
                dst = base + h * 4608 + r * LDKr + c * 8;
                src = (h ? g_hlo : g_hhi) + r * HDIM + k0 + c * 8;
            } else {                        // B = Whh hi/lo, 32 rows x 8 chunks
                int o = op - 1024;
                int h = o >> 8;
                int r = (o & 255) >> 3, c = o & 7;
                dst = base + 9216 + h * 2304 + r * LDKr + c * 8;
                src = (h ? g_Whh_lo : g_Whh_hi) + (size_t)(n0 + r) * HDIM + k0 + c * 8;
            }
            cpa16(dst, src);
        }
        cpa_commit();
    };

    auto compute = [&](int s) {
        const __nv_bfloat16* Ahi = dsm + s * RSTG;
        const __nv_bfloat16* Alo = Ahi + 4608;
        const __nv_bfloat16* Bhi = Ahi + 9216;
        const __nv_bfloat16* Blo = Ahi + 11520;
#pragma unroll
        for (int ks = 0; ks < 64; ks += 16) {
            uint32_t ah[4], al[4];
            int ra = (m_off + gid) * LDKr + ks + kb;
            int rb = ra + 8 * LDKr;
            ah[0] = ld32(Ahi + ra);     ah[1] = ld32(Ahi + rb);
            ah[2] = ld32(Ahi + ra + 8); ah[3] = ld32(Ahi + rb + 8);
            al[0] = ld32(Alo + ra);     al[1] = ld32(Alo + rb);
            al[2] = ld32(Alo + ra + 8); al[3] = ld32(Alo + rb + 8);
#pragma unroll
            for (int nf = 0; nf < 2; nf++) {
                int rn = (n_off + nf * 8 + gid) * LDKr + ks + kb;
                uint32_t bh[2] = { ld32(Bhi + rn), ld32(Bhi + rn + 8) };
                uint32_t bl[2] = { ld32(Blo + rn), ld32(Blo + rn + 8) };
                mma16816(acc[nf], ah, bh);
                mma16816(acc[nf], ah, bl);
                mma16816(acc[nf], al, bh);
            }
        }
    };

    const int KT = HDIM / 64;   // 16
    load_stage(0, 0);
    for (int kt = 0; kt < KT; kt++) {
        if (kt + 1 < KT) load_stage((kt + 1) & 1, (kt + 1) * 64);
        if (kt + 1 < KT) cpa_wait1(); else cpa_wait0();
        __syncthreads();
        compute(kt & 1);
        __syncthreads();
    }

    // write raw gate tile to shared (aliases stage-0 A buffer, nobody reads it)
    float* Cs = (float*)dsm;    // [64][36]
#pragma unroll
    for (int nf = 0; nf < 2; nf++) {
        int col = n_off + nf * 8 + kb;
        int row = m_off + gid;
        Cs[row * 36 + col]           = acc[nf][0];
        Cs[row * 36 + col + 1]       = acc[nf][1];
        Cs[(row + 8) * 36 + col]     = acc[nf][2];
        Cs[(row + 8) * 36 + col + 1] = acc[nf][3];
    }
    __syncthreads();

    // fused LSTM cell + answer dot. 512 cells: b in [0,64), jl in [0,8)
    const float* Pb = g_P + (size_t)t * BATCH * NG;
#pragma unroll
    for (int half = 0; half < 2; half++) {
        int idx = tid + half * 256;
        int b = idx >> 3, jl = idx & 7;
        float4 pv = *(const float4*)(Pb + (size_t)b * NG + n0 + (jl << 2));
        float gi = Cs[b * 36 + jl * 4 + 0] + pv.x;
        float gf = Cs[b * 36 + jl * 4 + 1] + pv.y;
        float gg = Cs[b * 36 + jl * 4 + 2] + pv.z;
        float go = Cs[b * 36 + jl * 4 + 3] + pv.w;
        float vi = 1.0f / (1.0f + expf(-gi));
        float vf = 1.0f / (1.0f + expf(-gf));
        float vg = tanhf(gg);
        float vo = 1.0f / (1.0f + expf(-go));
        int jg = (n0 >> 2) + jl;
        float c = vf * g_c[b * HDIM + jg] + vi * vg;
        float h = vo * tanhf(c);
        g_c[b * HDIM + jg] = c;
        __nv_bfloat16 hh = __float2bfloat16(h);
        g_hhi[b * HDIM + jg] = hh;
        g_hlo[b * HDIM + jg] = __float2bfloat16(h - __bfloat162float(hh));
        float p = h * w_ans[jg];
        p += __shfl_xor_sync(0xFFFFFFFFu, p, 4);
        p += __shfl_xor_sync(0xFFFFFFFFu, p, 2);
        p += __shfl_xor_sync(0xFFFFFFFFu, p, 1);
        if (t >= SEL_START && (lane & 7) == 0)
            atomicAdd(&out[b * SEL_COUNT + (t - SEL_START)], p);
    }
}

// ---------------- launch ----------------
extern "C" void kernel_launch(void* const* d_in, const int* in_sizes, int n_in,
                              void* d_out, int out_size) {
    (void)in_sizes; (void)n_in; (void)out_size;
    const void*  prob  = d_in[0];
    const float* table = (const float*)d_in[2];
    const float* w_ih  = (const float*)d_in[3];
    const float* w_hh  = (const float*)d_in[4];
    const float* b_ih  = (const float*)d_in[5];
    const float* b_hh  = (const float*)d_in[6];
    const float* w_ans = (const float*)d_in[7];
    const float* b_ans = (const float*)d_in[8];
    const float* h0    = (const float*)d_in[9];
    const float* c0    = (const float*)d_in[10];
    float* out = (float*)d_out;

    static bool inited = false;
    if (!inited) {
        cudaFuncSetAttribute(gemm_pre,   cudaFuncAttributeMaxDynamicSharedMemorySize, 2 * PSTG * 2);
        cudaFuncSetAttribute(lstm_fused, cudaFuncAttributeMaxDynamicSharedMemorySize, 2 * RSTG * 2);
        inited = true;
    }

    detect_kernel<<<1, 256>>>((const int*)prob);
    init_state<<<BATCH, HDIM>>>(h0, c0);
    init_out<<<16, 256>>>(out, b_ans);
    gather_split<<<TSTEPS * BATCH, 128>>>(prob, table);
    convert_wih<<<NG, 128>>>(w_ih, b_ih, b_hh);
    convert_whh<<<NG, 256>>>(w_hh);

    gemm_pre<<<dim3(NG / 128, MPAD / 128), 256, 2 * PSTG * 2>>>();

    for (int t = 0; t < TSTEPS; t++)
        lstm_fused<<<128, 256, 2 * RSTG * 2>>>(w_ans, out, t);
}

// round 3
// speedup vs baseline: 3.2410x; 1.1701x over previous
#include <cuda_runtime.h>
#include <cuda_bf16.h>
#include <cstdint>

#define SEQ       128
#define BATCH     64
#define EMBED     512
#define HDIM      1024
#define NG        4096
#define TSTEPS    127
#define SEL_START 65
#define SEL_COUNT 62
#define MPAD      8192
#define NCTA      128

// ---------------- device scratch ----------------
__device__ __nv_bfloat16 g_Xhi[MPAD * EMBED];
__device__ __nv_bfloat16 g_Xlo[MPAD * EMBED];
__device__ __nv_bfloat16 g_Wih_hi[NG * EMBED];
__device__ __nv_bfloat16 g_Wih_lo[NG * EMBED];
__device__ __nv_bfloat16 g_Whh_hi[NG * HDIM];
__device__ __nv_bfloat16 g_Whh_lo[NG * HDIM];
__device__ float g_bsum[NG];
__device__ float g_P[TSTEPS * BATCH * NG];          // preacts, gate-interleaved cols
__device__ __nv_bfloat16 g_h2hi[2 * BATCH * HDIM];  // ping-pong h (hi)
__device__ __nv_bfloat16 g_h2lo[2 * BATCH * HDIM];  // ping-pong h (lo)
__device__ unsigned g_arrive;
__device__ int g_is64;

// ---------------- helpers ----------------
__device__ __forceinline__ void cvt_split(__nv_bfloat16* hi, __nv_bfloat16* lo, float v) {
    __nv_bfloat16 h = __float2bfloat16(v);
    *hi = h;
    *lo = __float2bfloat16(v - __bfloat162float(h));
}
__device__ __forceinline__ void mma16816(float* c, const uint32_t* a, const uint32_t* b) {
    asm volatile(
        "mma.sync.aligned.m16n8k16.row.col.f32.bf16.bf16.f32 "
        "{%0,%1,%2,%3}, {%4,%5,%6,%7}, {%8,%9}, {%0,%1,%2,%3};\n"
        : "+f"(c[0]), "+f"(c[1]), "+f"(c[2]), "+f"(c[3])
        : "r"(a[0]), "r"(a[1]), "r"(a[2]), "r"(a[3]), "r"(b[0]), "r"(b[1]));
}
__device__ __forceinline__ void cpa16(void* smem, const void* g) {
    uint32_t s = (uint32_t)__cvta_generic_to_shared(smem);
    asm volatile("cp.async.cg.shared.global [%0], [%1], 16;\n" :: "r"(s), "l"(g));
}
__device__ __forceinline__ void cpa_commit() { asm volatile("cp.async.commit_group;\n"); }
__device__ __forceinline__ void cpa_wait1()  { asm volatile("cp.async.wait_group 1;\n"); }
__device__ __forceinline__ void cpa_wait0()  { asm volatile("cp.async.wait_group 0;\n"); }
__device__ __forceinline__ uint32_t ld32(const __nv_bfloat16* p) { return *(const uint32_t*)p; }
__device__ __forceinline__ unsigned ldv(const unsigned* p) { return *(volatile const unsigned*)p; }

// ---------------- dtype detection ----------------
__global__ void detect_kernel(const int* __restrict__ prob32) {
    __shared__ int any;
    if (threadIdx.x == 0) any = 0;
    __syncthreads();
    int local = 0;
    for (int i = 2 * threadIdx.x + 1; i < BATCH * SEQ; i += 2 * blockDim.x)
        local |= prob32[i];
    if (local) atomicOr(&any, 1);
    __syncthreads();
    if (threadIdx.x == 0) g_is64 = (any == 0) ? 1 : 0;
}

// ---------------- init ----------------
__global__ void init_state(const float* __restrict__ h0) {
    int i = blockIdx.x * blockDim.x + threadIdx.x;
    cvt_split(&g_h2hi[i], &g_h2lo[i], h0[i]);
    if (i == 0) g_arrive = 0u;
}
__global__ void init_out(float* __restrict__ out, const float* __restrict__ b_ans) {
    int i = blockIdx.x * blockDim.x + threadIdx.x;
    if (i < BATCH * SEL_COUNT) out[i] = b_ans[0];
}

// ---------------- embedding gather + split ----------------
__global__ void gather_split(const void* __restrict__ prob, const float* __restrict__ table) {
    int row = blockIdx.x;            // t*64 + b
    int t = row >> 6, b = row & 63;
    long long tok;
    if (g_is64) tok = ((const long long*)prob)[b * SEQ + t];
    else        tok = (long long)((const int*)prob)[b * SEQ + t];
    float4 v = ((const float4*)(table + (size_t)tok * EMBED))[threadIdx.x];
    int o = row * EMBED + threadIdx.x * 4;
    cvt_split(&g_Xhi[o + 0], &g_Xlo[o + 0], v.x);
    cvt_split(&g_Xhi[o + 1], &g_Xlo[o + 1], v.y);
    cvt_split(&g_Xhi[o + 2], &g_Xlo[o + 2], v.z);
    cvt_split(&g_Xhi[o + 3], &g_Xlo[o + 3], v.w);
}

// ---------------- weight conversion (gate-interleave: n = 4*j + g) -------
__global__ void convert_wih(const float* __restrict__ w_ih,
                            const float* __restrict__ b_ih,
                            const float* __restrict__ b_hh) {
    int n = blockIdx.x;
    int j = n >> 2, g = n & 3;
    int r = g * HDIM + j;
    float4 v = ((const float4*)(w_ih + (size_t)r * EMBED))[threadIdx.x];
    int o = n * EMBED + threadIdx.x * 4;
    cvt_split(&g_Wih_hi[o + 0], &g_Wih_lo[o + 0], v.x);
    cvt_split(&g_Wih_hi[o + 1], &g_Wih_lo[o + 1], v.y);
    cvt_split(&g_Wih_hi[o + 2], &g_Wih_lo[o + 2], v.z);
    cvt_split(&g_Wih_hi[o + 3], &g_Wih_lo[o + 3], v.w);
    if (threadIdx.x == 0) g_bsum[n] = b_ih[r] + b_hh[r];
}
__global__ void convert_whh(const float* __restrict__ w_hh) {
    int n = blockIdx.x;
    int j = n >> 2, g = n & 3;
    int r = g * HDIM + j;
    float4 v = ((const float4*)(w_hh + (size_t)r * HDIM))[threadIdx.x];
    int o = n * HDIM + threadIdx.x * 4;
    cvt_split(&g_Whh_hi[o + 0], &g_Whh_lo[o + 0], v.x);
    cvt_split(&g_Whh_hi[o + 1], &g_Whh_lo[o + 1], v.y);
    cvt_split(&g_Whh_hi[o + 2], &g_Whh_lo[o + 2], v.z);
    cvt_split(&g_Whh_hi[o + 3], &g_Whh_lo[o + 3], v.w);
}

// ---------------- pre-GEMM: P = X @ Wih^T + bsum  [8192x4096, K=512] ------
#define LDKp 40
#define PSTG 20480

__global__ __launch_bounds__(256, 1)
void gemm_pre() {
    extern __shared__ __nv_bfloat16 dsm[];
    const int tid = threadIdx.x, warp = tid >> 5, lane = tid & 31;
    const int gid = lane >> 2, kb = (lane & 3) << 1;
    const int m_off = (warp >> 2) << 6;
    const int n_off = (warp & 3) << 5;
    const int m0 = blockIdx.y << 7;
    const int n0 = blockIdx.x << 7;

    float acc[4][4][4];
#pragma unroll
    for (int a = 0; a < 4; a++)
#pragma unroll
        for (int b = 0; b < 4; b++)
#pragma unroll
            for (int cc = 0; cc < 4; cc++) acc[a][b][cc] = 0.0f;

    auto load_stage = [&](int s, int k0) {
        __nv_bfloat16* base = dsm + s * PSTG;
#pragma unroll
        for (int it = 0; it < 8; it++) {
            int op = it * 256 + tid;
            int buf = op >> 9;
            int r = (op & 511) >> 2;
            int c = op & 3;
            __nv_bfloat16* dst = base + buf * 5120 + r * LDKp + c * 8;
            const __nv_bfloat16* src;
            if (buf == 0)      src = g_Xhi    + (size_t)(m0 + r) * EMBED + k0 + c * 8;
            else if (buf == 1) src = g_Xlo    + (size_t)(m0 + r) * EMBED + k0 + c * 8;
            else if (buf == 2) src = g_Wih_hi + (size_t)(n0 + r) * EMBED + k0 + c * 8;
            else               src = g_Wih_lo + (size_t)(n0 + r) * EMBED + k0 + c * 8;
            cpa16(dst, src);
        }
        cpa_commit();
    };

    auto compute = [&](int s) {
        const __nv_bfloat16* Ahi = dsm + s * PSTG;
        const __nv_bfloat16* Alo = Ahi + 5120;
        const __nv_bfloat16* Bhi = Ahi + 10240;
        const __nv_bfloat16* Blo = Ahi + 15360;
#pragma unroll
        for (int ks = 0; ks < 32; ks += 16) {
            uint32_t ah[4][4], al[4][4];
#pragma unroll
            for (int mf = 0; mf < 4; mf++) {
                int ra = (m_off + mf * 16 + gid) * LDKp + ks + kb;
                int rb = ra + 8 * LDKp;
                ah[mf][0] = ld32(Ahi + ra);     ah[mf][1] = ld32(Ahi + rb);
                ah[mf][2] = ld32(Ahi + ra + 8); ah[mf][3] = ld32(Ahi + rb + 8);
                al[mf][0] = ld32(Alo + ra);     al[mf][1] = ld32(Alo + rb);
                al[mf][2] = ld32(Alo + ra + 8); al[mf][3] = ld32(Alo + rb + 8);
            }
#pragma unroll
            for (int nf = 0; nf < 4; nf++) {
                int rn = (n_off + nf * 8 + gid) * LDKp + ks + kb;
                uint32_t bh[2] = { ld32(Bhi + rn), ld32(Bhi + rn + 8) };
                uint32_t bl[2] = { ld32(Blo + rn), ld32(Blo + rn + 8) };
#pragma unroll
                for (int mf = 0; mf < 4; mf++) {
                    mma16816(acc[mf][nf], ah[mf], bh);
                    mma16816(acc[mf][nf], ah[mf], bl);
                    mma16816(acc[mf][nf], al[mf], bh);
                }
            }
        }
    };

    const int KT = EMBED / 32;
    load_stage(0, 0);
    for (int kt = 0; kt < KT; kt++) {
        if (kt + 1 < KT) load_stage((kt + 1) & 1, (kt + 1) * 32);
        if (kt + 1 < KT) cpa_wait1(); else cpa_wait0();
        __syncthreads();
        compute(kt & 1);
        __syncthreads();
    }

#pragma unroll
    for (int mf = 0; mf < 4; mf++)
#pragma unroll
        for (int nf = 0; nf < 4; nf++) {
            int row = m0 + m_off + mf * 16 + gid;
            int col = n0 + n_off + nf * 8 + kb;
            float b0 = g_bsum[col], b1 = g_bsum[col + 1];
            if (row < TSTEPS * BATCH) {
                g_P[(size_t)row * NG + col]     = acc[mf][nf][0] + b0;
                g_P[(size_t)row * NG + col + 1] = acc[mf][nf][1] + b1;
            }
            if (row + 8 < TSTEPS * BATCH) {
                g_P[(size_t)(row + 8) * NG + col]     = acc[mf][nf][2] + b0;
                g_P[(size_t)(row + 8) * NG + col + 1] = acc[mf][nf][3] + b1;
            }
        }
}

// ---------------- persistent recurrent kernel ----------------------------
// 128 CTAs, each owns 32 gate-interleaved columns of Whh (hi/lo resident in
// smem, 129KB). Per step: load h (ping-pong, cp.async L1-bypass), 3-split
// MMA 64x32xK1024, fused cell + answer dot, software grid barrier.
//
// smem layout (bytes):
//   Whi  [32][1032] bf16   @ 0       size 66048
//   Wlo  [32][1032] bf16   @ 66048   size 66048
//   Hst  [2][2][64][72]    @ 132096  size 36864
//   Ps   [64][32] f32      @ 168960  size 8192
//   Cs   [64][36] f32      @ 177152  size 9216
//   cs   [64][8]  f32      @ 186368  size 2048
//   was  [8]      f32      @ 188416  size 32
#define SMEM_PERSIST 188448

__global__ __launch_bounds__(256, 1)
void lstm_persist(const float* __restrict__ c0, const float* __restrict__ w_ans,
                  float* __restrict__ out) {
    extern __shared__ char smc[];
    __nv_bfloat16* Whi = (__nv_bfloat16*)smc;
    __nv_bfloat16* Wlo = Whi + 33024;
    __nv_bfloat16* Hst = Wlo + 33024;
    float* Ps  = (float*)(smc + 168960);
    float* Cs  = (float*)(smc + 177152);
    float* cs  = (float*)(smc + 186368);
    float* was = (float*)(smc + 188416);

    const int tid = threadIdx.x, warp = tid >> 5, lane = tid & 31;
    const int gid = lane >> 2, kb = (lane & 3) << 1;
    const int m_off = (warp & 3) << 4;    // 0..48
    const int n_off = (warp >> 2) << 4;   // 0,16
    const int n0 = blockIdx.x << 5;
    const int j0 = blockIdx.x << 3;

    // ---- preload resident Whh tile (hi/lo) ----
#pragma unroll
    for (int it = 0; it < 16; it++) {
        int op = it * 256 + tid;          // 0..4095
        int r = op >> 7, c = op & 127;
        cpa16(Whi + r * 1032 + c * 8, g_Whh_hi + (size_t)(n0 + r) * HDIM + c * 8);
        cpa16(Wlo + r * 1032 + c * 8, g_Whh_lo + (size_t)(n0 + r) * HDIM + c * 8);
    }
    cpa_commit();
    // c slice + w_ans slice
    if (tid < 128) {
        int b = tid >> 1, q = tid & 1;
        float4 v = *(const float4*)(c0 + (size_t)b * HDIM + j0 + q * 4);
        *(float4*)(cs + b * 8 + q * 4) = v;
    }
    if (tid < 8) was[tid] = w_ans[j0 + tid];
    cpa_wait0();
    __syncthreads();

    for (int t = 0; t < TSTEPS; t++) {
        const __nv_bfloat16* hhi = g_h2hi + (size_t)(t & 1) * (BATCH * HDIM);
        const __nv_bfloat16* hlo = g_h2lo + (size_t)(t & 1) * (BATCH * HDIM);
        __nv_bfloat16* nhhi = g_h2hi + (size_t)((t + 1) & 1) * (BATCH * HDIM);
        __nv_bfloat16* nhlo = g_h2lo + (size_t)((t + 1) & 1) * (BATCH * HDIM);

        float acc[2][4];
#pragma unroll
        for (int i = 0; i < 2; i++)
#pragma unroll
            for (int j = 0; j < 4; j++) acc[i][j] = 0.0f;

        auto load_h = [&](int s, int k0) {
            __nv_bfloat16* base = Hst + s * 9216;
#pragma unroll
            for (int it = 0; it < 4; it++) {
                int op = it * 256 + tid;                 // 0..1023
                int h = op >> 9, r = (op & 511) >> 3, c = op & 7;
                cpa16(base + h * 4608 + r * 72 + c * 8,
                      (h ? hlo : hhi) + (size_t)r * HDIM + k0 + c * 8);
            }
        };

        // stage 0 + P tile (group 0), stage 1 (group 1)
        load_h(0, 0);
#pragma unroll
        for (int it = 0; it < 2; it++) {
            int op = it * 256 + tid;                     // 0..511
            int r = op >> 3, c = op & 7;
            cpa16(Ps + r * 32 + c * 4,
                  g_P + ((size_t)t * BATCH + r) * NG + n0 + c * 4);
        }
        cpa_commit();
        load_h(1, 64);
        cpa_commit();

        const __nv_bfloat16* WhiB = Whi;
        const __nv_bfloat16* WloB = Wlo;

        for (int kt = 0; kt < 16; kt++) {
            if (kt < 15) cpa_wait1(); else cpa_wait0();
            __syncthreads();
            {
                const __nv_bfloat16* Ahi = Hst + (kt & 1) * 9216;
                const __nv_bfloat16* Alo = Ahi + 4608;
                const int kg0 = kt * 64;
#pragma unroll
                for (int ks = 0; ks < 64; ks += 16) {
                    uint32_t ah[4], al[4];
                    int ra = (m_off + gid) * 72 + ks + kb;
                    int rb = ra + 8 * 72;
                    ah[0] = ld32(Ahi + ra);     ah[1] = ld32(Ahi + rb);
                    ah[2] = ld32(Ahi + ra + 8); ah[3] = ld32(Ahi + rb + 8);
                    al[0] = ld32(Alo + ra);     al[1] = ld32(Alo + rb);
                    al[2] = ld32(Alo + ra + 8); al[3] = ld32(Alo + rb + 8);
#pragma unroll
                    for (int nf = 0; nf < 2; nf++) {
                        int rn = (n_off + nf * 8 + gid) * 1032 + kg0 + ks + kb;
                        uint32_t bh[2] = { ld32(WhiB + rn), ld32(WhiB + rn + 8) };
                        uint32_t bl[2] = { ld32(WloB + rn), ld32(WloB + rn + 8) };
                        mma16816(acc[nf], ah, bh);
                        mma16816(acc[nf], ah, bl);
                        mma16816(acc[nf], al, bh);
                    }
                }
            }
            __syncthreads();
            if (kt + 2 < 16) { load_h(kt & 1, (kt + 2) * 64); cpa_commit(); }
        }

        // gate tile -> shared
#pragma unroll
        for (int nf = 0; nf < 2; nf++) {
            int col = n_off + nf * 8 + kb;
            int row = m_off + gid;
            Cs[row * 36 + col]           = acc[nf][0];
            Cs[row * 36 + col + 1]       = acc[nf][1];
            Cs[(row + 8) * 36 + col]     = acc[nf][2];
            Cs[(row + 8) * 36 + col + 1] = acc[nf][3];
        }
        __syncthreads();

        // fused cell + answer dot: 512 items = (b, jl)
#pragma unroll
        for (int half = 0; half < 2; half++) {
            int idx = tid + half * 256;
            int b = idx >> 3, jl = idx & 7;
            float gi = Cs[b * 36 + jl * 4 + 0] + Ps[b * 32 + jl * 4 + 0];
            float gf = Cs[b * 36 + jl * 4 + 1] + Ps[b * 32 + jl * 4 + 1];
            float gg = Cs[b * 36 + jl * 4 + 2] + Ps[b * 32 + jl * 4 + 2];
            float go = Cs[b * 36 + jl * 4 + 3] + Ps[b * 32 + jl * 4 + 3];
            float vi = 1.0f / (1.0f + expf(-gi));
            float vf = 1.0f / (1.0f + expf(-gf));
            float vg = tanhf(gg);
            float vo = 1.0f / (1.0f + expf(-go));
            float c = vf * cs[b * 8 + jl] + vi * vg;
            cs[b * 8 + jl] = c;
            float h = vo * tanhf(c);
            __nv_bfloat16 hh = __float2bfloat16(h);
            nhhi[(size_t)b * HDIM + j0 + jl] = hh;
            nhlo[(size_t)b * HDIM + j0 + jl] = __float2bfloat16(h - __bfloat162float(hh));
            float p = h * was[jl];
            p += __shfl_xor_sync(0xFFFFFFFFu, p, 4);
            p += __shfl_xor_sync(0xFFFFFFFFu, p, 2);
            p += __shfl_xor_sync(0xFFFFFFFFu, p, 1);
            if (t >= SEL_START && (lane & 7) == 0)
                atomicAdd(&out[b * SEL_COUNT + (t - SEL_START)], p);
        }

        // ---- grid-wide barrier (all 128 CTAs co-resident: 1 CTA/SM) ----
        __threadfence();
        __syncthreads();
        if (tid == 0) {
            atomicAdd(&g_arrive, 1u);
            unsigned tgt = (unsigned)(t + 1) * NCTA;
            while (ldv(&g_arrive) < tgt) __nanosleep(64);
            __threadfence();
        }
        __syncthreads();
    }
}

// ---------------- launch ----------------
extern "C" void kernel_launch(void* const* d_in, const int* in_sizes, int n_in,
                              void* d_out, int out_size) {
    (void)in_sizes; (void)n_in; (void)out_size;
    const void*  prob  = d_in[0];
    const float* table = (const float*)d_in[2];
    const float* w_ih  = (const float*)d_in[3];
    const float* w_hh  = (const float*)d_in[4];
    const float* b_ih  = (const float*)d_in[5];
    const float* b_hh  = (const float*)d_in[6];
    const float* w_ans = (const float*)d_in[7];
    const float* b_ans = (const float*)d_in[8];
    const float* h0    = (const float*)d_in[9];
    const float* c0    = (const float*)d_in[10];
    float* out = (float*)d_out;

    static bool inited = false;
    if (!inited) {
        cudaFuncSetAttribute(gemm_pre,     cudaFuncAttributeMaxDynamicSharedMemorySize, 2 * PSTG * 2);
        cudaFuncSetAttribute(lstm_persist, cudaFuncAttributeMaxDynamicSharedMemorySize, SMEM_PERSIST);
        inited = true;
    }

    detect_kernel<<<1, 256>>>((const int*)prob);
    init_state<<<BATCH, HDIM>>>(h0);
    init_out<<<16, 256>>>(out, b_ans);
    gather_split<<<TSTEPS * BATCH, 128>>>(prob, table);
    convert_wih<<<NG, 128>>>(w_ih, b_ih, b_hh);
    convert_whh<<<NG, 256>>>(w_hh);

    gemm_pre<<<dim3(NG / 128, MPAD / 128), 256, 2 * PSTG * 2>>>();

    lstm_persist<<<NCTA, 256, SMEM_PERSIST>>>(c0, w_ans, out);
}

// round 4
// speedup vs baseline: 3.3430x; 1.0315x over previous
#include <cuda_runtime.h>
#include <cuda_bf16.h>
#include <cstdint>

#define SEQ       128
#define BATCH     64
#define EMBED     512
#define HDIM      1024
#define NG        4096
#define TSTEPS    127
#define SEL_START 65
#define SEL_COUNT 62
#define MPAD      8192
#define NCTA      128

// ---------------- device scratch ----------------
__device__ __nv_bfloat16 g_Xhi[MPAD * EMBED];
__device__ __nv_bfloat16 g_Xlo[MPAD * EMBED];
__device__ __nv_bfloat16 g_Wih_hi[NG * EMBED];
__device__ __nv_bfloat16 g_Wih_lo[NG * EMBED];
__device__ __nv_bfloat16 g_Whh_hi[NG * HDIM];
__device__ __nv_bfloat16 g_Whh_lo[NG * HDIM];
__device__ float g_bsum[NG];
__device__ float g_P[TSTEPS * BATCH * NG];          // preacts, gate-interleaved cols
__device__ __nv_bfloat16 g_h2hi[2 * BATCH * HDIM];  // ping-pong h (hi)
__device__ __nv_bfloat16 g_h2lo[2 * BATCH * HDIM];  // ping-pong h (lo)
__device__ unsigned g_arrive;
__device__ int g_is64;

// ---------------- helpers ----------------
__device__ __forceinline__ void cvt_split(__nv_bfloat16* hi, __nv_bfloat16* lo, float v) {
    __nv_bfloat16 h = __float2bfloat16(v);
    *hi = h;
    *lo = __float2bfloat16(v - __bfloat162float(h));
}
__device__ __forceinline__ void mma16816(float* c, const uint32_t* a, const uint32_t* b) {
    asm volatile(
        "mma.sync.aligned.m16n8k16.row.col.f32.bf16.bf16.f32 "
        "{%0,%1,%2,%3}, {%4,%5,%6,%7}, {%8,%9}, {%0,%1,%2,%3};\n"
        : "+f"(c[0]), "+f"(c[1]), "+f"(c[2]), "+f"(c[3])
        : "r"(a[0]), "r"(a[1]), "r"(a[2]), "r"(a[3]), "r"(b[0]), "r"(b[1]));
}
__device__ __forceinline__ void ldsm4(uint32_t* r, uint32_t saddr) {
    asm volatile("ldmatrix.sync.aligned.m8n8.x4.shared.b16 {%0,%1,%2,%3}, [%4];"
        : "=r"(r[0]), "=r"(r[1]), "=r"(r[2]), "=r"(r[3]) : "r"(saddr));
}
__device__ __forceinline__ uint32_t sptr(const void* p) {
    return (uint32_t)__cvta_generic_to_shared(p);
}
__device__ __forceinline__ void cpa16(void* smem, const void* g) {
    uint32_t s = sptr(smem);
    asm volatile("cp.async.cg.shared.global [%0], [%1], 16;\n" :: "r"(s), "l"(g));
}
__device__ __forceinline__ void cpa_commit() { asm volatile("cp.async.commit_group;\n"); }
__device__ __forceinline__ void cpa_wait2()  { asm volatile("cp.async.wait_group 2;\n"); }
__device__ __forceinline__ void cpa_wait1()  { asm volatile("cp.async.wait_group 1;\n"); }
__device__ __forceinline__ void cpa_wait0()  { asm volatile("cp.async.wait_group 0;\n"); }
__device__ __forceinline__ unsigned ldv(const unsigned* p) { return *(volatile const unsigned*)p; }

// ---------------- fused init: detect dtype + init h/c state + init out ----
__global__ void fused_init(const int* __restrict__ prob32, const float* __restrict__ h0,
                           float* __restrict__ out, const float* __restrict__ b_ans) {
    int bid = blockIdx.x;
    if (bid == 0) {
        __shared__ int any;
        if (threadIdx.x == 0) any = 0;
        __syncthreads();
        int local = 0;
        for (int i = 2 * threadIdx.x + 1; i < BATCH * SEQ; i += 2 * blockDim.x)
            local |= prob32[i];
        if (local) atomicOr(&any, 1);
        __syncthreads();
        if (threadIdx.x == 0) { g_is64 = (any == 0) ? 1 : 0; g_arrive = 0u; }
    } else if (bid <= 64) {
        int i = (bid - 1) * 1024 + threadIdx.x;
        cvt_split(&g_h2hi[i], &g_h2lo[i], h0[i]);
    } else {
        int i = (bid - 65) * 1024 + threadIdx.x;
        if (i < BATCH * SEL_COUNT) out[i] = b_ans[0];
    }
}

// ---------------- embedding gather + split ----------------
__global__ void gather_split(const void* __restrict__ prob, const float* __restrict__ table) {
    int row = blockIdx.x;            // t*64 + b
    int t = row >> 6, b = row & 63;
    long long tok;
    if (g_is64) tok = ((const long long*)prob)[b * SEQ + t];
    else        tok = (long long)((const int*)prob)[b * SEQ + t];
    float4 v = ((const float4*)(table + (size_t)tok * EMBED))[threadIdx.x];
    int o = row * EMBED + threadIdx.x * 4;
    cvt_split(&g_Xhi[o + 0], &g_Xlo[o + 0], v.x);
    cvt_split(&g_Xhi[o + 1], &g_Xlo[o + 1], v.y);
    cvt_split(&g_Xhi[o + 2], &g_Xlo[o + 2], v.z);
    cvt_split(&g_Xhi[o + 3], &g_Xlo[o + 3], v.w);
}

// ---------------- weight conversion (gate-interleave: n = 4*j + g) -------
__global__ void convert_wih(const float* __restrict__ w_ih,
                            const float* __restrict__ b_ih,
                            const float* __restrict__ b_hh) {
    int n = blockIdx.x;
    int j = n >> 2, g = n & 3;
    int r = g * HDIM + j;
    float4 v = ((const float4*)(w_ih + (size_t)r * EMBED))[threadIdx.x];
    int o = n * EMBED + threadIdx.x * 4;
    cvt_split(&g_Wih_hi[o + 0], &g_Wih_lo[o + 0], v.x);
    cvt_split(&g_Wih_hi[o + 1], &g_Wih_lo[o + 1], v.y);
    cvt_split(&g_Wih_hi[o + 2], &g_Wih_lo[o + 2], v.z);
    cvt_split(&g_Wih_hi[o + 3], &g_Wih_lo[o + 3], v.w);
    if (threadIdx.x == 0) g_bsum[n] = b_ih[r] + b_hh[r];
}
__global__ void convert_whh(const float* __restrict__ w_hh) {
    int n = blockIdx.x;
    int j = n >> 2, g = n & 3;
    int r = g * HDIM + j;
    float4 v = ((const float4*)(w_hh + (size_t)r * HDIM))[threadIdx.x];
    int o = n * HDIM + threadIdx.x * 4;
    cvt_split(&g_Whh_hi[o + 0], &g_Whh_lo[o + 0], v.x);
    cvt_split(&g_Whh_hi[o + 1], &g_Whh_lo[o + 1], v.y);
    cvt_split(&g_Whh_hi[o + 2], &g_Whh_lo[o + 2], v.z);
    cvt_split(&g_Whh_hi[o + 3], &g_Whh_lo[o + 3], v.w);
}

// ---------------- pre-GEMM: P = X @ Wih^T + bsum  [8192x4096, K=512] ------
#define LDKp 40
#define PSTG 20480

__global__ __launch_bounds__(256, 1)
void gemm_pre() {
    extern __shared__ __nv_bfloat16 dsm[];
    const int tid = threadIdx.x, warp = tid >> 5, lane = tid & 31;
    const int gid = lane >> 2, kb = (lane & 3) << 1;
    const int m_off = (warp >> 2) << 6;
    const int n_off = (warp & 3) << 5;
    const int m0 = blockIdx.y << 7;
    const int n0 = blockIdx.x << 7;
    // ldmatrix lane->row/col mapping
    const int a_r = (lane & 7) + (lane & 8);
    const int a_c = (lane & 16) >> 1;
    const int b_r = (lane & 7) + ((lane & 16) >> 1);
    const int b_c = (lane & 8);

    float acc[4][4][4];
#pragma unroll
    for (int a = 0; a < 4; a++)
#pragma unroll
        for (int b = 0; b < 4; b++)
#pragma unroll
            for (int cc = 0; cc < 4; cc++) acc[a][b][cc] = 0.0f;

    auto load_stage = [&](int s, int k0) {
        __nv_bfloat16* base = dsm + s * PSTG;
#pragma unroll
        for (int it = 0; it < 8; it++) {
            int op = it * 256 + tid;
            int buf = op >> 9;
            int r = (op & 511) >> 2;
            int c = op & 3;
            __nv_bfloat16* dst = base + buf * 5120 + r * LDKp + c * 8;
            const __nv_bfloat16* src;
            if (buf == 0)      src = g_Xhi    + (size_t)(m0 + r) * EMBED + k0 + c * 8;
            else if (buf == 1) src = g_Xlo    + (size_t)(m0 + r) * EMBED + k0 + c * 8;
            else if (buf == 2) src = g_Wih_hi + (size_t)(n0 + r) * EMBED + k0 + c * 8;
            else               src = g_Wih_lo + (size_t)(n0 + r) * EMBED + k0 + c * 8;
            cpa16(dst, src);
        }
        cpa_commit();
    };

    auto compute = [&](int s) {
        uint32_t sA = sptr(dsm + s * PSTG);
        uint32_t aoff = (uint32_t)((m_off + a_r) * LDKp + a_c) * 2;
        uint32_t boff = (uint32_t)((n_off + b_r) * LDKp + b_c) * 2;
        uint32_t sAhi = sA + aoff,            sAlo = sA + 5120 * 2 + aoff;
        uint32_t sBhi = sA + 10240 * 2 + boff, sBlo = sA + 15360 * 2 + boff;
#pragma unroll
        for (int ks = 0; ks < 32; ks += 16) {
            uint32_t ah[4][4], al[4][4], bh4[2][4], bl4[2][4];
#pragma unroll
            for (int mf = 0; mf < 4; mf++) {
                ldsm4(ah[mf], sAhi + (uint32_t)(mf * 16 * LDKp + ks) * 2);
                ldsm4(al[mf], sAlo + (uint32_t)(mf * 16 * LDKp + ks) * 2);
            }
#pragma unroll
            for (int nh = 0; nh < 2; nh++) {
                ldsm4(bh4[nh], sBhi + (uint32_t)(nh * 16 * LDKp + ks) * 2);
                ldsm4(bl4[nh], sBlo + (uint32_t)(nh * 16 * LDKp + ks) * 2);
            }
#pragma unroll
            for (int nf = 0; nf < 4; nf++) {
                const uint32_t* bh = &bh4[nf >> 1][(nf & 1) * 2];
                const uint32_t* bl = &bl4[nf >> 1][(nf & 1) * 2];
#pragma unroll
                for (int mf = 0; mf < 4; mf++) {
                    mma16816(acc[mf][nf], ah[mf], bh);
                    mma16816(acc[mf][nf], ah[mf], bl);
                    mma16816(acc[mf][nf], al[mf], bh);
                }
            }
        }
    };

    const int KT = EMBED / 32;
    load_stage(0, 0);
    for (int kt = 0; kt < KT; kt++) {
        if (kt + 1 < KT) load_stage((kt + 1) & 1, (kt + 1) * 32);
        if (kt + 1 < KT) cpa_wait1(); else cpa_wait0();
        __syncthreads();
        compute(kt & 1);
        __syncthreads();
    }

    // epilogue: acc index mapping (gid row, kb col) as in manual-fragment version
#pragma unroll
    for (int mf = 0; mf < 4; mf++)
#pragma unroll
        for (int nf = 0; nf < 4; nf++) {
            int row = m0 + m_off + mf * 16 + gid;
            int col = n0 + n_off + nf * 8 + kb;
            float b0 = g_bsum[col], b1 = g_bsum[col + 1];
            if (row < TSTEPS * BATCH) {
                g_P[(size_t)row * NG + col]     = acc[mf][nf][0] + b0;
                g_P[(size_t)row * NG + col + 1] = acc[mf][nf][1] + b1;
            }
            if (row + 8 < TSTEPS * BATCH) {
                g_P[(size_t)(row + 8) * NG + col]     = acc[mf][nf][2] + b0;
                g_P[(size_t)(row + 8) * NG + col + 1] = acc[mf][nf][3] + b1;
            }
        }
}

// ---------------- persistent recurrent kernel ----------------------------
// smem layout (bytes):
//   Whi [32][1032] bf16 @ 0        66048
//   Wlo [32][1032] bf16 @ 66048    66048
//   Hst 4 stages x (hi+lo 64x72)   @ 132096  73728
//   Ps  [64][32] f32    @ 205824   8192
//   Cs  [64][36] f32    @ 214016   9216
//   cs  [64][8]  f32    @ 223232   2048
//   was [8]      f32    @ 225280   32
#define SMEM_PERSIST 225312

__global__ __launch_bounds__(256, 1)
void lstm_persist(const float* __restrict__ c0, const float* __restrict__ w_ans,
                  float* __restrict__ out) {
    extern __shared__ char smc[];
    __nv_bfloat16* Whi = (__nv_bfloat16*)smc;
    __nv_bfloat16* Wlo = Whi + 33024;
    __nv_bfloat16* Hst = Wlo + 33024;
    float* Ps  = (float*)(smc + 205824);
    float* Cs  = (float*)(smc + 214016);
    float* cs  = (float*)(smc + 223232);
    float* was = (float*)(smc + 225280);

    const int tid = threadIdx.x, warp = tid >> 5, lane = tid & 31;
    const int gid = lane >> 2, kb = (lane & 3) << 1;
    const int m_off = (warp & 3) << 4;    // 0..48
    const int n_off = (warp >> 2) << 4;   // 0,16
    const int n0 = blockIdx.x << 5;
    const int j0 = blockIdx.x << 3;
    const int a_r = (lane & 7) + (lane & 8);
    const int a_c = (lane & 16) >> 1;
    const int b_r = (lane & 7) + ((lane & 16) >> 1);
    const int b_c = (lane & 8);

    // ---- preload resident Whh tile (hi/lo) ----
#pragma unroll
    for (int it = 0; it < 16; it++) {
        int op = it * 256 + tid;          // 0..4095
        int r = op >> 7, c = op & 127;
        cpa16(Whi + r * 1032 + c * 8, g_Whh_hi + (size_t)(n0 + r) * HDIM + c * 8);
        cpa16(Wlo + r * 1032 + c * 8, g_Whh_lo + (size_t)(n0 + r) * HDIM + c * 8);
    }
    cpa_commit();
    if (tid < 128) {
        int b = tid >> 1, q = tid & 1;
        float4 v = *(const float4*)(c0 + (size_t)b * HDIM + j0 + q * 4);
        *(float4*)(cs + b * 8 + q * 4) = v;
    }
    if (tid < 8) was[tid] = w_ans[j0 + tid];
    cpa_wait0();
    __syncthreads();

    // per-warp invariant B (weights) ldmatrix base addrs
    const uint32_t wBoff = (uint32_t)((n_off + b_r) * 1032 + b_c) * 2;
    const uint32_t sWhi = sptr(Whi) + wBoff;
    const uint32_t sWlo = sptr(Wlo) + wBoff;
    const uint32_t aoff = (uint32_t)((m_off + a_r) * 72 + a_c) * 2;

    for (int t = 0; t < TSTEPS; t++) {
        const __nv_bfloat16* hhi = g_h2hi + (size_t)(t & 1) * (BATCH * HDIM);
        const __nv_bfloat16* hlo = g_h2lo + (size_t)(t & 1) * (BATCH * HDIM);
        __nv_bfloat16* nhhi = g_h2hi + (size_t)((t + 1) & 1) * (BATCH * HDIM);
        __nv_bfloat16* nhlo = g_h2lo + (size_t)((t + 1) & 1) * (BATCH * HDIM);

        float acc[2][4];
#pragma unroll
        for (int i = 0; i < 2; i++)
#pragma unroll
            for (int j = 0; j < 4; j++) acc[i][j] = 0.0f;

        auto load_h = [&](int s, int k0) {
            __nv_bfloat16* base = Hst + s * 9216;
#pragma unroll
            for (int it = 0; it < 4; it++) {
                int op = it * 256 + tid;                 // 0..1023
                int h = op >> 9, r = (op & 511) >> 3, c = op & 7;
                cpa16(base + h * 4608 + r * 72 + c * 8,
                      (h ? hlo : hhi) + (size_t)r * HDIM + k0 + c * 8);
            }
        };

        // prologue: 3 stages in flight; P tile rides with stage 0
        load_h(0, 0);
#pragma unroll
        for (int it = 0; it < 2; it++) {
            int op = it * 256 + tid;                     // 0..511
            int r = op >> 3, c = op & 7;
            cpa16(Ps + r * 32 + c * 4,
                  g_P + ((size_t)t * BATCH + r) * NG + n0 + c * 4);
        }
        cpa_commit();
        load_h(1, 64);  cpa_commit();
        load_h(2, 128); cpa_commit();

        for (int kt = 0; kt < 16; kt++) {
            int rem = 15 - kt;
            if (rem >= 2) cpa_wait2();
            else if (rem == 1) cpa_wait1();
            else cpa_wait0();
            __syncthreads();
            if (kt + 3 < 16) { load_h((kt + 3) & 3, (kt + 3) * 64); cpa_commit(); }

            uint32_t sA = sptr(Hst + (kt & 3) * 9216);
            uint32_t sAhi = sA + aoff;
            uint32_t sAlo = sA + 9216 + aoff;   // 4608 elems * 2B
            uint32_t sBh = sWhi + (uint32_t)(kt * 64) * 2;
            uint32_t sBl = sWlo + (uint32_t)(kt * 64) * 2;
#pragma unroll
            for (int ks = 0; ks < 64; ks += 16) {
                uint32_t ah[4], al[4], bh4[4], bl4[4];
                ldsm4(ah,  sAhi + ks * 2);
                ldsm4(al,  sAlo + ks * 2);
                ldsm4(bh4, sBh + ks * 2);
                ldsm4(bl4, sBl + ks * 2);
                mma16816(acc[0], ah, &bh4[0]);
                mma16816(acc[0], ah, &bl4[0]);
                mma16816(acc[0], al, &bh4[0]);
                mma16816(acc[1], ah, &bh4[2]);
                mma16816(acc[1], ah, &bl4[2]);
                mma16816(acc[1], al, &bh4[2]);
            }
        }

        // gate tile -> shared
#pragma unroll
        for (int nf = 0; nf < 2; nf++) {
            int col = n_off + nf * 8 + kb;
            int row = m_off + gid;
            Cs[row * 36 + col]           = acc[nf][0];
            Cs[row * 36 + col + 1]       = acc[nf][1];
            Cs[(row + 8) * 36 + col]     = acc[nf][2];
            Cs[(row + 8) * 36 + col + 1] = acc[nf][3];
        }
        __syncthreads();

        // fused cell + answer dot: 512 items = (b, jl)
#pragma unroll
        for (int half = 0; half < 2; half++) {
            int idx = tid + half * 256;
            int b = idx >> 3, jl = idx & 7;
            float gi = Cs[b * 36 + jl * 4 + 0] + Ps[b * 32 + jl * 4 + 0];
            float gf = Cs[b * 36 + jl * 4 + 1] + Ps[b * 32 + jl * 4 + 1];
            float gg = Cs[b * 36 + jl * 4 + 2] + Ps[b * 32 + jl * 4 + 2];
            float go = Cs[b * 36 + jl * 4 + 3] + Ps[b * 32 + jl * 4 + 3];
            float vi = 1.0f / (1.0f + expf(-gi));
            float vf = 1.0f / (1.0f + expf(-gf));
            float vg = tanhf(gg);
            float vo = 1.0f / (1.0f + expf(-go));
            float c = vf * cs[b * 8 + jl] + vi * vg;
            cs[b * 8 + jl] = c;
            float h = vo * tanhf(c);
            __nv_bfloat16 hh = __float2bfloat16(h);
            nhhi[(size_t)b * HDIM + j0 + jl] = hh;
            nhlo[(size_t)b * HDIM + j0 + jl] = __float2bfloat16(h - __bfloat162float(hh));
            float p = h * was[jl];
            p += __shfl_xor_sync(0xFFFFFFFFu, p, 4);
            p += __shfl_xor_sync(0xFFFFFFFFu, p, 2);
            p += __shfl_xor_sync(0xFFFFFFFFu, p, 1);
            if (t >= SEL_START && (lane & 7) == 0)
                atomicAdd(&out[b * SEL_COUNT + (t - SEL_START)], p);
        }

        // ---- grid-wide barrier (128 CTAs, 1/SM, single wave) ----
        __threadfence();
        __syncthreads();
        if (tid == 0) {
            atomicAdd(&g_arrive, 1u);
            unsigned tgt = (unsigned)(t + 1) * NCTA;
            while (ldv(&g_arrive) < tgt) __nanosleep(64);
            __threadfence();
        }
        __syncthreads();
    }
}

// ---------------- launch ----------------
extern "C" void kernel_launch(void* const* d_in, const int* in_sizes, int n_in,
                              void* d_out, int out_size) {
    (void)in_sizes; (void)n_in; (void)out_size;
    const void*  prob  = d_in[0];
    const float* table = (const float*)d_in[2];
    const float* w_ih  = (const float*)d_in[3];
    const float* w_hh  = (const float*)d_in[4];
    const float* b_ih  = (const float*)d_in[5];
    const float* b_hh  = (const float*)d_in[6];
    const float* w_ans = (const float*)d_in[7];
    const float* b_ans = (const float*)d_in[8];
    const float* h0    = (const float*)d_in[9];
    const float* c0    = (const float*)d_in[10];
    float* out = (float*)d_out;

    static bool inited = false;
    if (!inited) {
        cudaFuncSetAttribute(gemm_pre,     cudaFuncAttributeMaxDynamicSharedMemorySize, 2 * PSTG * 2);
        cudaFuncSetAttribute(lstm_persist, cudaFuncAttributeMaxDynamicSharedMemorySize, SMEM_PERSIST);
        inited = true;
    }

    fused_init<<<69, 1024>>>((const int*)prob, h0, out, b_ans);
    gather_split<<<TSTEPS * BATCH, 128>>>(prob, table);
    convert_wih<<<NG, 128>>>(w_ih, b_ih, b_hh);
    convert_whh<<<NG, 256>>>(w_hh);

    gemm_pre<<<dim3(NG / 128, MPAD / 128), 256, 2 * PSTG * 2>>>();

    lstm_persist<<<NCTA, 256, SMEM_PERSIST>>>(c0, w_ans, out);
}

// round 6
// speedup vs baseline: 3.3873x; 1.0132x over previous
#include <cuda_runtime.h>
#include <cuda_bf16.h>
#include <cstdint>

#define SEQ       128
#define BATCH     64
#define EMBED     512
#define HDIM      1024
#define NG        4096
#define TSTEPS    127
#define SEL_START 65
#define SEL_COUNT 62
#define MPAD      8192
#define NCTA      128

// ---------------- device scratch ----------------
__device__ __nv_bfloat16 g_Xhi[MPAD * EMBED];
__device__ __nv_bfloat16 g_Xlo[MPAD * EMBED];
__device__ __nv_bfloat16 g_Wih_hi[NG * EMBED];
__device__ __nv_bfloat16 g_Wih_lo[NG * EMBED];
__device__ __nv_bfloat16 g_Whh_hi[NG * HDIM];
__device__ __nv_bfloat16 g_Whh_lo[NG * HDIM];
__device__ float g_bsum[NG];
__device__ float g_P[TSTEPS * BATCH * NG];          // preacts, gate-interleaved cols
__device__ __nv_bfloat16 g_h2hi[2 * BATCH * HDIM];  // ping-pong h (hi)
__device__ __nv_bfloat16 g_h2lo[2 * BATCH * HDIM];  // ping-pong h (lo)
__device__ unsigned g_arrive;
__device__ int g_is64;

// ---------------- helpers ----------------
__device__ __forceinline__ void cvt_split(__nv_bfloat16* hi, __nv_bfloat16* lo, float v) {
    __nv_bfloat16 h = __float2bfloat16(v);
    *hi = h;
    *lo = __float2bfloat16(v - __bfloat162float(h));
}
__device__ __forceinline__ void mma16816(float* c, const uint32_t* a, const uint32_t* b) {
    asm volatile(
        "mma.sync.aligned.m16n8k16.row.col.f32.bf16.bf16.f32 "
        "{%0,%1,%2,%3}, {%4,%5,%6,%7}, {%8,%9}, {%0,%1,%2,%3};\n"
        : "+f"(c[0]), "+f"(c[1]), "+f"(c[2]), "+f"(c[3])
        : "r"(a[0]), "r"(a[1]), "r"(a[2]), "r"(a[3]), "r"(b[0]), "r"(b[1]));
}
__device__ __forceinline__ void ldsm4(uint32_t* r, uint32_t saddr) {
    asm volatile("ldmatrix.sync.aligned.m8n8.x4.shared.b16 {%0,%1,%2,%3}, [%4];"
        : "=r"(r[0]), "=r"(r[1]), "=r"(r[2]), "=r"(r[3]) : "r"(saddr));
}
__device__ __forceinline__ uint32_t sptr(const void* p) {
    return (uint32_t)__cvta_generic_to_shared(p);
}
__device__ __forceinline__ void cpa16(void* smem, const void* g) {
    uint32_t s = sptr(smem);
    asm volatile("cp.async.cg.shared.global [%0], [%1], 16;\n" :: "r"(s), "l"(g));
}
__device__ __forceinline__ void cpa_commit() { asm volatile("cp.async.commit_group;\n"); }
__device__ __forceinline__ void cpa_wait2()  { asm volatile("cp.async.wait_group 2;\n"); }
__device__ __forceinline__ void cpa_wait1()  { asm volatile("cp.async.wait_group 1;\n"); }
__device__ __forceinline__ void cpa_wait0()  { asm volatile("cp.async.wait_group 0;\n"); }
__device__ __forceinline__ unsigned ldv(const unsigned* p) { return *(volatile const unsigned*)p; }
__device__ __forceinline__ float ex2f(float x) {
    float y; asm("ex2.approx.f32 %0, %1;" : "=f"(y) : "f"(x)); return y;
}
__device__ __forceinline__ float rcpf(float x) {
    float y; asm("rcp.approx.f32 %0, %1;" : "=f"(y) : "f"(x)); return y;
}
#define L2E  1.4426950408889634f
#define L2E2 2.8853900817779268f

// ---------------- fused init ----------------
__global__ void fused_init(const int* __restrict__ prob32, const float* __restrict__ h0,
                           float* __restrict__ out, const float* __restrict__ b_ans) {
    int bid = blockIdx.x;
    if (bid == 0) {
        __shared__ int any;
        if (threadIdx.x == 0) any = 0;
        __syncthreads();
        int local = 0;
        for (int i = 2 * threadIdx.x + 1; i < BATCH * SEQ; i += 2 * blockDim.x)
            local |= prob32[i];
        if (local) atomicOr(&any, 1);
        __syncthreads();
        if (threadIdx.x == 0) { g_is64 = (any == 0) ? 1 : 0; g_arrive = 0u; }
    } else if (bid <= 64) {
        int i = (bid - 1) * 1024 + threadIdx.x;
        cvt_split(&g_h2hi[i], &g_h2lo[i], h0[i]);
    } else {
        int i = (bid - 65) * 1024 + threadIdx.x;
        if (i < BATCH * SEL_COUNT) out[i] = b_ans[0];
    }
}

// ---------------- embedding gather + split ----------------
__global__ void gather_split(const void* __restrict__ prob, const float* __restrict__ table) {
    int row = blockIdx.x;            // t*64 + b
    int t = row >> 6, b = row & 63;
    long long tok;
    if (g_is64) tok = ((const long long*)prob)[b * SEQ + t];
    else        tok = (long long)((const int*)prob)[b * SEQ + t];
    float4 v = ((const float4*)(table + (size_t)tok * EMBED))[threadIdx.x];
    int o = row * EMBED + threadIdx.x * 4;
    cvt_split(&g_Xhi[o + 0], &g_Xlo[o + 0], v.x);
    cvt_split(&g_Xhi[o + 1], &g_Xlo[o + 1], v.y);
    cvt_split(&g_Xhi[o + 2], &g_Xlo[o + 2], v.z);
    cvt_split(&g_Xhi[o + 3], &g_Xlo[o + 3], v.w);
}

// ---------------- weight conversion (gate-interleave: n = 4*j + g) -------
__global__ void convert_wih(const float* __restrict__ w_ih,
                            const float* __restrict__ b_ih,
                            const float* __restrict__ b_hh) {
    int n = blockIdx.x;
    int j = n >> 2, g = n & 3;
    int r = g * HDIM + j;
    float4 v = ((const float4*)(w_ih + (size_t)r * EMBED))[threadIdx.x];
    int o = n * EMBED + threadIdx.x * 4;
    cvt_split(&g_Wih_hi[o + 0], &g_Wih_lo[o + 0], v.x);
    cvt_split(&g_Wih_hi[o + 1], &g_Wih_lo[o + 1], v.y);
    cvt_split(&g_Wih_hi[o + 2], &g_Wih_lo[o + 2], v.z);
    cvt_split(&g_Wih_hi[o + 3], &g_Wih_lo[o + 3], v.w);
    if (threadIdx.x == 0) g_bsum[n] = b_ih[r] + b_hh[r];
}
__global__ void convert_whh(const float* __restrict__ w_hh) {
    int n = blockIdx.x;
    int j = n >> 2, g = n & 3;
    int r = g * HDIM + j;
    float4 v = ((const float4*)(w_hh + (size_t)r * HDIM))[threadIdx.x];
    int o = n * HDIM + threadIdx.x * 4;
    cvt_split(&g_Whh_hi[o + 0], &g_Whh_lo[o + 0], v.x);
    cvt_split(&g_Whh_hi[o + 1], &g_Whh_lo[o + 1], v.y);
    cvt_split(&g_Whh_hi[o + 2], &g_Whh_lo[o + 2], v.z);
    cvt_split(&g_Whh_hi[o + 3], &g_Whh_lo[o + 3], v.w);
}

// ---------------- pre-GEMM: P = X @ Wih^T + bsum  [8192x4096, K=512] ------
#define LDKp 40
#define PSTG 20480

__global__ __launch_bounds__(256, 1)
void gemm_pre() {
    extern __shared__ __nv_bfloat16 dsm[];
    const int tid = threadIdx.x, warp = tid >> 5, lane = tid & 31;
    const int gid = lane >> 2, kb = (lane & 3) << 1;
    const int m_off = (warp >> 2) << 6;
    const int n_off = (warp & 3) << 5;
    const int m0 = blockIdx.y << 7;
    const int n0 = blockIdx.x << 7;
    const int a_r = (lane & 7) + (lane & 8);
    const int a_c = (lane & 16) >> 1;
    const int b_r = (lane & 7) + ((lane & 16) >> 1);
    const int b_c = (lane & 8);

    float acc[4][4][4];
#pragma unroll
    for (int a = 0; a < 4; a++)
#pragma unroll
        for (int b = 0; b < 4; b++)
#pragma unroll
            for (int cc = 0; cc < 4; cc++) acc[a][b][cc] = 0.0f;

    auto load_stage = [&](int s, int k0) {
        __nv_bfloat16* base = dsm + s * PSTG;
#pragma unroll
        for (int it = 0; it < 8; it++) {
            int op = it * 256 + tid;
            int buf = op >> 9;
            int r = (op & 511) >> 2;
            int c = op & 3;
            __nv_bfloat16* dst = base + buf * 5120 + r * LDKp + c * 8;
            const __nv_bfloat16* src;
            if (buf == 0)      src = g_Xhi    + (size_t)(m0 + r) * EMBED + k0 + c * 8;
            else if (buf == 1) src = g_Xlo    + (size_t)(m0 + r) * EMBED + k0 + c * 8;
            else if (buf == 2) src = g_Wih_hi + (size_t)(n0 + r) * EMBED + k0 + c * 8;
            else               src = g_Wih_lo + (size_t)(n0 + r) * EMBED + k0 + c * 8;
            cpa16(dst, src);
        }
        cpa_commit();
    };

    auto compute = [&](int s) {
        uint32_t sA = sptr(dsm + s * PSTG);
        uint32_t aoff = (uint32_t)((m_off + a_r) * LDKp + a_c) * 2;
        uint32_t boff = (uint32_t)((n_off + b_r) * LDKp + b_c) * 2;
        uint32_t sAhi = sA + aoff,             sAlo = sA + 5120 * 2 + aoff;
        uint32_t sBhi = sA + 10240 * 2 + boff, sBlo = sA + 15360 * 2 + boff;
#pragma unroll
        for (int ks = 0; ks < 32; ks += 16) {
            uint32_t ah[4][4], al[4][4], bh4[2][4], bl4[2][4];
#pragma unroll
            for (int mf = 0; mf < 4; mf++) {
                ldsm4(ah[mf], sAhi + (uint32_t)(mf * 16 * LDKp + ks) * 2);
                ldsm4(al[mf], sAlo + (uint32_t)(mf * 16 * LDKp + ks) * 2);
            }
#pragma unroll
            for (int nh = 0; nh < 2; nh++) {
                ldsm4(bh4[nh], sBhi + (uint32_t)(nh * 16 * LDKp + ks) * 2);
                ldsm4(bl4[nh], sBlo + (uint32_t)(nh * 16 * LDKp + ks) * 2);
            }
#pragma unroll
            for (int nf = 0; nf < 4; nf++) {
                const uint32_t* bh = &bh4[nf >> 1][(nf & 1) * 2];
                const uint32_t* bl = &bl4[nf >> 1][(nf & 1) * 2];
#pragma unroll
                for (int mf = 0; mf < 4; mf++) {
                    mma16816(acc[mf][nf], ah[mf], bh);
                    mma16816(acc[mf][nf], ah[mf], bl);
                    mma16816(acc[mf][nf], al[mf], bh);
                }
            }
        }
    };

    const int KT = EMBED / 32;
    load_stage(0, 0);
    for (int kt = 0; kt < KT; kt++) {
        if (kt + 1 < KT) load_stage((kt + 1) & 1, (kt + 1) * 32);
        if (kt + 1 < KT) cpa_wait1(); else cpa_wait0();
        __syncthreads();
        compute(kt & 1);
        __syncthreads();
    }

#pragma unroll
    for (int mf = 0; mf < 4; mf++)
#pragma unroll
        for (int nf = 0; nf < 4; nf++) {
            int row = m0 + m_off + mf * 16 + gid;
            int col = n0 + n_off + nf * 8 + kb;
            float b0 = g_bsum[col], b1 = g_bsum[col + 1];
            if (row < TSTEPS * BATCH) {
                g_P[(size_t)row * NG + col]     = acc[mf][nf][0] + b0;
                g_P[(size_t)row * NG + col + 1] = acc[mf][nf][1] + b1;
            }
            if (row + 8 < TSTEPS * BATCH) {
                g_P[(size_t)(row + 8) * NG + col]     = acc[mf][nf][2] + b0;
                g_P[(size_t)(row + 8) * NG + col + 1] = acc[mf][nf][3] + b1;
            }
        }
}

// ---------------- persistent recurrent kernel ----------------------------
// smem layout (bytes):
//   Whi [32][1032] bf16 @ 0        66048
//   Wlo [32][1032] bf16 @ 66048    66048
//   Hst 4 stages x (hi+lo 64x72)   @ 132096  73728
//   Ps  [64][32] f32    @ 205824   8192
//   Cs  [64][36] f32    @ 214016   9216
//   cs  [64][8]  f32    @ 223232   2048
//   was [8]      f32    @ 225280   32
#define SMEM_PERSIST 225312

__global__ __launch_bounds__(256, 1)
void lstm_persist(const float* __restrict__ c0, const float* __restrict__ w_ans,
                  float* __restrict__ out) {
    extern __shared__ char smc[];
    __nv_bfloat16* Whi = (__nv_bfloat16*)smc;
    __nv_bfloat16* Wlo = Whi + 33024;
    __nv_bfloat16* Hst = Wlo + 33024;
    float* Ps  = (float*)(smc + 205824);
    float* Cs  = (float*)(smc + 214016);
    float* cs  = (float*)(smc + 223232);
    float* was = (float*)(smc + 225280);

    const int tid = threadIdx.x, warp = tid >> 5, lane = tid & 31;
    const int gid = lane >> 2, kb = (lane & 3) << 1;
    const int m_off = (warp & 3) << 4;    // 0..48
    const int n_off = (warp >> 2) << 4;   // 0,16
    const int n0 = blockIdx.x << 5;
    const int j0 = blockIdx.x << 3;
    const int a_r = (lane & 7) + (lane & 8);
    const int a_c = (lane & 16) >> 1;
    const int b_r = (lane & 7) + ((lane & 16) >> 1);
    const int b_c = (lane & 8);

    // ---- preload resident Whh tile (hi/lo) ----
#pragma unroll
    for (int it = 0; it < 16; it++) {
        int op = it * 256 + tid;          // 0..4095
        int r = op >> 7, c = op & 127;
        cpa16(Whi + r * 1032 + c * 8, g_Whh_hi + (size_t)(n0 + r) * HDIM + c * 8);
        cpa16(Wlo + r * 1032 + c * 8, g_Whh_lo + (size_t)(n0 + r) * HDIM + c * 8);
    }
    cpa_commit();
    if (tid < 128) {
        int b = tid >> 1, q = tid & 1;
        float4 v = *(const float4*)(c0 + (size_t)b * HDIM + j0 + q * 4);
        *(float4*)(cs + b * 8 + q * 4) = v;
    }
    if (tid < 8) was[tid] = w_ans[j0 + tid];
    cpa_wait0();
    __syncthreads();

    const uint32_t wBoff = (uint32_t)((n_off + b_r) * 1032 + b_c) * 2;
    const uint32_t sWhi = sptr(Whi) + wBoff;
    const uint32_t sWlo = sptr(Wlo) + wBoff;
    const uint32_t aoff = (uint32_t)((m_off + a_r) * 72 + a_c) * 2;

    for (int t = 0; t < TSTEPS; t++) {
        const __nv_bfloat16* hhi = g_h2hi + (size_t)(t & 1) * (BATCH * HDIM);
        const __nv_bfloat16* hlo = g_h2lo + (size_t)(t & 1) * (BATCH * HDIM);
        __nv_bfloat16* nhhi = g_h2hi + (size_t)((t + 1) & 1) * (BATCH * HDIM);
        __nv_bfloat16* nhlo = g_h2lo + (size_t)((t + 1) & 1) * (BATCH * HDIM);

        float acc[2][4];
#pragma unroll
        for (int i = 0; i < 2; i++)
#pragma unroll
            for (int j = 0; j < 4; j++) acc[i][j] = 0.0f;

        auto load_h = [&](int s, int k0) {
            __nv_bfloat16* base = Hst + s * 9216;
#pragma unroll
            for (int it = 0; it < 4; it++) {
                int op = it * 256 + tid;                 // 0..1023
                int h = op >> 9, r = (op & 511) >> 3, c = op & 7;
                cpa16(base + h * 4608 + r * 72 + c * 8,
                      (h ? hlo : hhi) + (size_t)r * HDIM + k0 + c * 8);
            }
        };

        // prologue: 3 stages in flight; P tile rides with stage 0
        load_h(0, 0);
#pragma unroll
        for (int it = 0; it < 2; it++) {
            int op = it * 256 + tid;                     // 0..511
            int r = op >> 3, c = op & 7;
            cpa16(Ps + r * 32 + c * 4,
                  g_P + ((size_t)t * BATCH + r) * NG + n0 + c * 4);
        }
        cpa_commit();
        load_h(1, 64);  cpa_commit();
        load_h(2, 128); cpa_commit();

        for (int kt = 0; kt < 16; kt++) {
            int rem = 15 - kt;
            if (rem >= 2) cpa_wait2();
            else if (rem == 1) cpa_wait1();
            else cpa_wait0();
            __syncthreads();
            if (kt + 3 < 16) { load_h((kt + 3) & 3, (kt + 3) * 64); cpa_commit(); }

            uint32_t sA = sptr(Hst + (kt & 3) * 9216);
            uint32_t sAhi = sA + aoff;
            uint32_t sAlo = sA + 9216 + aoff;   // 4608 elems * 2B
            uint32_t sBh = sWhi + (uint32_t)(kt * 64) * 2;
            uint32_t sBl = sWlo + (uint32_t)(kt * 64) * 2;
#pragma unroll
            for (int ks = 0; ks < 64; ks += 16) {
                uint32_t ah[4], al[4], bh4[4], bl4[4];
                ldsm4(ah,  sAhi + ks * 2);
                ldsm4(al,  sAlo + ks * 2);
                ldsm4(bh4, sBh + ks * 2);
                ldsm4(bl4, sBl + ks * 2);
                mma16816(acc[0], ah, &bh4[0]);
                mma16816(acc[0], ah, &bl4[0]);
                mma16816(acc[0], al, &bh4[0]);
                mma16816(acc[1], ah, &bh4[2]);
                mma16816(acc[1], ah, &bl4[2]);
                mma16816(acc[1], al, &bh4[2]);
            }
        }

        // gate tile -> shared
#pragma unroll
        for (int nf = 0; nf < 2; nf++) {
            int col = n_off + nf * 8 + kb;
            int row = m_off + gid;
            Cs[row * 36 + col]           = acc[nf][0];
            Cs[row * 36 + col + 1]       = acc[nf][1];
            Cs[(row + 8) * 36 + col]     = acc[nf][2];
            Cs[(row + 8) * 36 + col + 1] = acc[nf][3];
        }
        __syncthreads();

        // fused cell + answer dot: 512 items = (b, jl), MUFU-optimized
#pragma unroll
        for (int half = 0; half < 2; half++) {
            int idx = tid + half * 256;
            int b = idx >> 3, jl = idx & 7;
            float gi = Cs[b * 36 + jl * 4 + 0] + Ps[b * 32 + jl * 4 + 0];
            float gf = Cs[b * 36 + jl * 4 + 1] + Ps[b * 32 + jl * 4 + 1];
            float gg = Cs[b * 36 + jl * 4 + 2] + Ps[b * 32 + jl * 4 + 2];
            float go = Cs[b * 36 + jl * 4 + 3] + Ps[b * 32 + jl * 4 + 3];
            gi = fminf(fmaxf(gi, -15.0f), 15.0f);
            gf = fminf(fmaxf(gf, -15.0f), 15.0f);
            gg = fminf(fmaxf(gg, -15.0f), 15.0f);
            go = fminf(fmaxf(go, -15.0f), 15.0f);
            // sigmoids via shared reciprocal: s = 1/(1+e^-x)
            float ei = ex2f(-gi * L2E);
            float ef = ex2f(-gf * L2E);
            float eo = ex2f(-go * L2E);
            float d1 = 1.0f + ei, d2 = 1.0f + ef, d3 = 1.0f + eo;
            float m12 = d1 * d2, m23 = d2 * d3, m13 = d1 * d3;
            float r = rcpf(m12 * d3);
            float si = r * m23, sf = r * m13, so = r * m12;
            // tanh(gg) = (e^{2x}-1)/(e^{2x}+1)
            float eg = ex2f(gg * L2E2);
            float tg = (eg - 1.0f) * rcpf(eg + 1.0f);
            float c = sf * cs[b * 8 + jl] + si * tg;
            cs[b * 8 + jl] = c;
            float ac = fminf(fmaxf(c * L2E2, -60.0f), 60.0f);
            float ec = ex2f(ac);
            float tc = (ec - 1.0f) * rcpf(ec + 1.0f);
            float h = so * tc;
            __nv_bfloat16 hh = __float2bfloat16(h);
            nhhi[(size_t)b * HDIM + j0 + jl] = hh;
            nhlo[(size_t)b * HDIM + j0 + jl] = __float2bfloat16(h - __bfloat162float(hh));
            float p = h * was[jl];
            p += __shfl_xor_sync(0xFFFFFFFFu, p, 4);
            p += __shfl_xor_sync(0xFFFFFFFFu, p, 2);
            p += __shfl_xor_sync(0xFFFFFFFFu, p, 1);
            if (t >= SEL_START && (lane & 7) == 0)
                atomicAdd(&out[b * SEL_COUNT + (t - SEL_START)], p);
        }

        // ---- grid-wide barrier (128 CTAs, 1/SM, single wave, hard spin) ----
        __threadfence();
        __syncthreads();
        if (tid == 0) {
            atomicAdd(&g_arrive, 1u);
            unsigned tgt = (unsigned)(t + 1) * NCTA;
            while (ldv(&g_arrive) < tgt) { }
            __threadfence();
        }
        __syncthreads();
    }
}

// ---------------- launch ----------------
extern "C" void kernel_launch(void* const* d_in, const int* in_sizes, int n_in,
                              void* d_out, int out_size) {
    (void)in_sizes; (void)n_in; (void)out_size;
    const void*  prob  = d_in[0];
    const float* table = (const float*)d_in[2];
    const float* w_ih  = (const float*)d_in[3];
    const float* w_hh  = (const float*)d_in[4];
    const float* b_ih  = (const float*)d_in[5];
    const float* b_hh  = (const float*)d_in[6];
    const float* w_ans = (const float*)d_in[7];
    const float* b_ans = (const float*)d_in[8];
    const float* h0    = (const float*)d_in[9];
    const float* c0    = (const float*)d_in[10];
    float* out = (float*)d_out;

    static bool inited = false;
    if (!inited) {
        cudaFuncSetAttribute(gemm_pre,     cudaFuncAttributeMaxDynamicSharedMemorySize, 2 * PSTG * 2);
        cudaFuncSetAttribute(lstm_persist, cudaFuncAttributeMaxDynamicSharedMemorySize, SMEM_PERSIST);
        inited = true;
    }

    fused_init<<<69, 1024>>>((const int*)prob, h0, out, b_ans);
    gather_split<<<TSTEPS * BATCH, 128>>>(prob, table);
    convert_wih<<<NG, 128>>>(w_ih, b_ih, b_hh);
    convert_whh<<<NG, 256>>>(w_hh);

    gemm_pre<<<dim3(NG / 128, MPAD / 128), 256, 2 * PSTG * 2>>>();

    lstm_persist<<<NCTA, 256, SMEM_PERSIST>>>(c0, w_ans, out);
}

// round 7
// speedup vs baseline: 3.4235x; 1.0107x over previous
#include <cuda_runtime.h>
#include <cuda_bf16.h>
#include <cuda_fp16.h>
#include <cstdint>

#define SEQ       128
#define BATCH     64
#define EMBED     512
#define HDIM      1024
#define NG        4096
#define TSTEPS    127
#define SEL_START 65
#define SEL_COUNT 62
#define NCTA      128

// ---------------- device scratch ----------------
__device__ __nv_bfloat16 g_Xhi[TSTEPS * BATCH * EMBED];
__device__ __nv_bfloat16 g_Xlo[TSTEPS * BATCH * EMBED];
__device__ __nv_bfloat16 g_Wih_hi[NG * EMBED];
__device__ __nv_bfloat16 g_Wih_lo[NG * EMBED];
__device__ __half        g_Whh_hi[NG * HDIM];
__device__ __half        g_Whh_lo[NG * HDIM];
__device__ float g_bsum[NG];
__device__ float g_P[TSTEPS * BATCH * NG];     // preacts, gate-interleaved cols
__device__ __half g_h2[2 * BATCH * HDIM];      // ping-pong h (fp16)
__device__ unsigned g_arrive;
__device__ int g_is64;

// ---------------- smem layout (bytes) ----------------
// recurrence:
#define OFF_WHI 0        // fp16 [32][1032]  66048
#define OFF_WLO 66048    // fp16 [32][1032]  66048
#define OFF_HST 132096   // 4 stages x 64x72 fp16 (9216 each) = 36864
#define OFF_PS  168960   // 2 x [64][32] f32 = 16384
#define OFF_CS  185344   // [64][36] f32 = 9216
#define OFF_CC  194560   // [64][8] f32 = 2048
#define OFF_WAS 196608   // [8] f32 = 32
#define SMEM_PERSIST 196640
// phase-0 overlay: Bh bf16[32][520]@0 (33280), Bl@33280; A stages @OFF_HST (2x10240)

// ---------------- helpers ----------------
__device__ __forceinline__ void cvt_split(__nv_bfloat16* hi, __nv_bfloat16* lo, float v) {
    __nv_bfloat16 h = __float2bfloat16(v);
    *hi = h;
    *lo = __float2bfloat16(v - __bfloat162float(h));
}
__device__ __forceinline__ void cvt_split_h(__half* hi, __half* lo, float v) {
    __half h = __float2half_rn(v);
    *hi = h;
    *lo = __float2half_rn(v - __half2float(h));
}
__device__ __forceinline__ void mma16816(float* c, const uint32_t* a, const uint32_t* b) {
    asm volatile(
        "mma.sync.aligned.m16n8k16.row.col.f32.bf16.bf16.f32 "
        "{%0,%1,%2,%3}, {%4,%5,%6,%7}, {%8,%9}, {%0,%1,%2,%3};\n"
        : "+f"(c[0]), "+f"(c[1]), "+f"(c[2]), "+f"(c[3])
        : "r"(a[0]), "r"(a[1]), "r"(a[2]), "r"(a[3]), "r"(b[0]), "r"(b[1]));
}
__device__ __forceinline__ void mma16816h(float* c, const uint32_t* a, const uint32_t* b) {
    asm volatile(
        "mma.sync.aligned.m16n8k16.row.col.f32.f16.f16.f32 "
        "{%0,%1,%2,%3}, {%4,%5,%6,%7}, {%8,%9}, {%0,%1,%2,%3};\n"
        : "+f"(c[0]), "+f"(c[1]), "+f"(c[2]), "+f"(c[3])
        : "r"(a[0]), "r"(a[1]), "r"(a[2]), "r"(a[3]), "r"(b[0]), "r"(b[1]));
}
__device__ __forceinline__ void ldsm4(uint32_t* r, uint32_t saddr) {
    asm volatile("ldmatrix.sync.aligned.m8n8.x4.shared.b16 {%0,%1,%2,%3}, [%4];"
        : "=r"(r[0]), "=r"(r[1]), "=r"(r[2]), "=r"(r[3]) : "r"(saddr));
}
__device__ __forceinline__ uint32_t sptr(const void* p) {
    return (uint32_t)__cvta_generic_to_shared(p);
}
__device__ __forceinline__ void cpa16(void* smem, const void* g) {
    uint32_t s = sptr(smem);
    asm volatile("cp.async.cg.shared.global [%0], [%1], 16;\n" :: "r"(s), "l"(g));
}
__device__ __forceinline__ void cpa_commit() { asm volatile("cp.async.commit_group;\n"); }
__device__ __forceinline__ void cpa_wait2()  { asm volatile("cp.async.wait_group 2;\n"); }
__device__ __forceinline__ void cpa_wait1()  { asm volatile("cp.async.wait_group 1;\n"); }
__device__ __forceinline__ void cpa_wait0()  { asm volatile("cp.async.wait_group 0;\n"); }
__device__ __forceinline__ unsigned ldv(const unsigned* p) { return *(volatile const unsigned*)p; }
__device__ __forceinline__ float ex2f(float x) {
    float y; asm("ex2.approx.f32 %0, %1;" : "=f"(y) : "f"(x)); return y;
}
__device__ __forceinline__ float rcpf(float x) {
    float y; asm("rcp.approx.f32 %0, %1;" : "=f"(y) : "f"(x)); return y;
}
#define L2E  1.4426950408889634f
#define L2E2 2.8853900817779268f

// ---------------- fused init ----------------
__global__ void fused_init(const int* __restrict__ prob32, const float* __restrict__ h0,
                           float* __restrict__ out, const float* __restrict__ b_ans) {
    int bid = blockIdx.x;
    if (bid == 0) {
        __shared__ int any;
        if (threadIdx.x == 0) any = 0;
        __syncthreads();
        int local = 0;
        for (int i = 2 * threadIdx.x + 1; i < BATCH * SEQ; i += 2 * blockDim.x)
            local |= prob32[i];
        if (local) atomicOr(&any, 1);
        __syncthreads();
        if (threadIdx.x == 0) { g_is64 = (any == 0) ? 1 : 0; g_arrive = 0u; }
    } else if (bid <= 64) {
        int i = (bid - 1) * 1024 + threadIdx.x;
        g_h2[i] = __float2half_rn(h0[i]);
    } else {
        int i = (bid - 65) * 1024 + threadIdx.x;
        if (i < BATCH * SEL_COUNT) out[i] = b_ans[0];
    }
}

// ---------------- embedding gather + split ----------------
__global__ void gather_split(const void* __restrict__ prob, const float* __restrict__ table) {
    int row = blockIdx.x;            // t*64 + b
    int t = row >> 6, b = row & 63;
    long long tok;
    if (g_is64) tok = ((const long long*)prob)[b * SEQ + t];
    else        tok = (long long)((const int*)prob)[b * SEQ + t];
    float4 v = ((const float4*)(table + (size_t)tok * EMBED))[threadIdx.x];
    int o = row * EMBED + threadIdx.x * 4;
    cvt_split(&g_Xhi[o + 0], &g_Xlo[o + 0], v.x);
    cvt_split(&g_Xhi[o + 1], &g_Xlo[o + 1], v.y);
    cvt_split(&g_Xhi[o + 2], &g_Xlo[o + 2], v.z);
    cvt_split(&g_Xhi[o + 3], &g_Xlo[o + 3], v.w);
}

// ---------------- weight conversion (gate-interleave: n = 4*j + g) -------
__global__ void convert_all(const float* __restrict__ w_ih, const float* __restrict__ w_hh,
                            const float* __restrict__ b_ih, const float* __restrict__ b_hh) {
    int n = blockIdx.x;
    if (n < NG) {                    // w_ih -> bf16 hi/lo
        int j = n >> 2, g = n & 3;
        int r = g * HDIM + j;
        if (threadIdx.x < 128) {
            float4 v = ((const float4*)(w_ih + (size_t)r * EMBED))[threadIdx.x];
            int o = n * EMBED + threadIdx.x * 4;
            cvt_split(&g_Wih_hi[o + 0], &g_Wih_lo[o + 0], v.x);
            cvt_split(&g_Wih_hi[o + 1], &g_Wih_lo[o + 1], v.y);
            cvt_split(&g_Wih_hi[o + 2], &g_Wih_lo[o + 2], v.z);
            cvt_split(&g_Wih_hi[o + 3], &g_Wih_lo[o + 3], v.w);
        }
        if (threadIdx.x == 0) g_bsum[n] = b_ih[r] + b_hh[r];
    } else {                         // w_hh -> fp16 hi/lo
        n -= NG;
        int j = n >> 2, g = n & 3;
        int r = g * HDIM + j;
        float4 v = ((const float4*)(w_hh + (size_t)r * HDIM))[threadIdx.x];
        int o = n * HDIM + threadIdx.x * 4;
        cvt_split_h(&g_Whh_hi[o + 0], &g_Whh_lo[o + 0], v.x);
        cvt_split_h(&g_Whh_hi[o + 1], &g_Whh_lo[o + 1], v.y);
        cvt_split_h(&g_Whh_hi[o + 2], &g_Whh_lo[o + 2], v.z);
        cvt_split_h(&g_Whh_hi[o + 3], &g_Whh_lo[o + 3], v.w);
    }
}

// ---------------- persistent mega-kernel: pre-GEMM phase + recurrence ----
__global__ __launch_bounds__(256, 1)
void lstm_persist(const float* __restrict__ c0, const float* __restrict__ w_ans,
                  float* __restrict__ out) {
    extern __shared__ char smc[];
    const int tid = threadIdx.x, warp = tid >> 5, lane = tid & 31;
    const int gid = lane >> 2, kb = (lane & 3) << 1;
    const int m_off = (warp & 3) << 4;    // 0..48
    const int n_off = (warp >> 2) << 4;   // 0,16
    const int n0 = blockIdx.x << 5;
    const int j0 = blockIdx.x << 3;
    const int a_r = (lane & 7) + (lane & 8);
    const int a_c = (lane & 16) >> 1;
    const int b_r = (lane & 7) + ((lane & 16) >> 1);
    const int b_c = (lane & 8);

    // ================= PHASE 0: P = X @ Wih^T + bsum (own 32 cols) =======
    {
        // B tile: Wih rows n0..n0+31, K=512, bf16 hi @0 / lo @33280, stride 1040B
#pragma unroll
        for (int it = 0; it < 8; it++) {
            int op = it * 256 + tid;        // 0..2047
            int r = op >> 6, c = op & 63;
            cpa16(smc + (size_t)r * 1040 + c * 16,
                  g_Wih_hi + (size_t)(n0 + r) * EMBED + c * 8);
            cpa16(smc + 33280 + (size_t)r * 1040 + c * 16,
                  g_Wih_lo + (size_t)(n0 + r) * EMBED + c * 8);
        }
        cpa_commit();
        float* bs = (float*)(smc + OFF_CS);
        if (tid < 32) bs[tid] = g_bsum[n0 + tid];
        cpa_wait0();
        __syncthreads();

        const uint32_t aP  = (uint32_t)((m_off + a_r) * 40 + a_c) * 2;
        const uint32_t bP0 = sptr(smc) + (uint32_t)((n_off + b_r) * 520 + b_c) * 2;

        for (int mt = 0; mt < 127; mt++) {
            const int m0 = mt << 6;
            float acc0[2][4];
#pragma unroll
            for (int i = 0; i < 2; i++)
#pragma unroll
                for (int j = 0; j < 4; j++) acc0[i][j] = 0.0f;

            auto loadA = [&](int s, int k0) {
                char* base = smc + OFF_HST + s * 10240;
                int r = tid >> 2, c = tid & 3;
                cpa16(base + r * 80 + c * 16,
                      g_Xhi + (size_t)(m0 + r) * EMBED + k0 + c * 8);
                cpa16(base + 5120 + r * 80 + c * 16,
                      g_Xlo + (size_t)(m0 + r) * EMBED + k0 + c * 8);
                cpa_commit();
            };
            loadA(0, 0);
            for (int kt = 0; kt < 16; kt++) {
                if (kt < 15) { loadA((kt + 1) & 1, (kt + 1) * 32); cpa_wait1(); }
                else cpa_wait0();
                __syncthreads();
                uint32_t sA   = sptr(smc + OFF_HST + (kt & 1) * 10240);
                uint32_t sAhi = sA + aP, sAlo = sA + 5120 + aP;
                uint32_t kB   = (uint32_t)(kt * 32) * 2;
#pragma unroll
                for (int ks = 0; ks < 32; ks += 16) {
                    uint32_t ah[4], al[4], bh4[4], bl4[4];
                    ldsm4(ah,  sAhi + ks * 2);
                    ldsm4(al,  sAlo + ks * 2);
                    ldsm4(bh4, bP0 + kB + ks * 2);
                    ldsm4(bl4, bP0 + 33280 + kB + ks * 2);
                    mma16816(acc0[0], ah, &bh4[0]);
                    mma16816(acc0[0], ah, &bl4[0]);
                    mma16816(acc0[0], al, &bh4[0]);
                    mma16816(acc0[1], ah, &bh4[2]);
                    mma16816(acc0[1], ah, &bl4[2]);
                    mma16816(acc0[1], al, &bh4[2]);
                }
                __syncthreads();
            }
#pragma unroll
            for (int nf = 0; nf < 2; nf++) {
                int lc = n_off + nf * 8 + kb;
                int col = n0 + lc;
                int row = m0 + m_off + gid;
                float b0 = bs[lc], b1 = bs[lc + 1];
                g_P[(size_t)row * NG + col]           = acc0[nf][0] + b0;
                g_P[(size_t)row * NG + col + 1]       = acc0[nf][1] + b1;
                g_P[(size_t)(row + 8) * NG + col]     = acc0[nf][2] + b0;
                g_P[(size_t)(row + 8) * NG + col + 1] = acc0[nf][3] + b1;
            }
        }
        __syncthreads();
    }

    // ================= load resident Whh (fp16 hi/lo) + state ============
#pragma unroll
    for (int it = 0; it < 16; it++) {
        int op = it * 256 + tid;          // 0..4095
        int r = op >> 7, c = op & 127;
        cpa16(smc + OFF_WHI + (size_t)r * 2064 + c * 16,
              g_Whh_hi + (size_t)(n0 + r) * HDIM + c * 8);
        cpa16(smc + OFF_WLO + (size_t)r * 2064 + c * 16,
              g_Whh_lo + (size_t)(n0 + r) * HDIM + c * 8);
    }
    cpa_commit();
    float* Cs  = (float*)(smc + OFF_CS);
    float* cs  = (float*)(smc + OFF_CC);
    float* was = (float*)(smc + OFF_WAS);
    if (tid < 128) {
        int b = tid >> 1, q = tid & 1;
        float4 v = *(const float4*)(c0 + (size_t)b * HDIM + j0 + q * 4);
        *(float4*)(cs + b * 8 + q * 4) = v;
    }
    if (tid < 8) was[tid] = w_ans[j0 + tid];
    cpa_wait0();
    __syncthreads();

    // ================= recurrence =========================================
    const uint32_t wB   = (uint32_t)((n_off + b_r) * 1032 + b_c) * 2;
    const uint32_t sWhi = sptr(smc + OFF_WHI) + wB;
    const uint32_t sWlo = sptr(smc + OFF_WLO) + wB;
    const uint32_t aR   = (uint32_t)((m_off + a_r) * 72 + a_c) * 2;
    const uint32_t hst0 = sptr(smc + OFF_HST);

    // P(0) prologue load into Ps buf 0
    {
#pragma unroll
        for (int it = 0; it < 2; it++) {
            int op = it * 256 + tid;
            int r = op >> 3, c = op & 7;
            cpa16(smc + OFF_PS + r * 128 + c * 16, g_P + (size_t)r * NG + n0 + c * 4);
        }
        cpa_commit();
    }

    for (int t = 0; t < TSTEPS; t++) {
        const __half* hsrc = g_h2 + (size_t)(t & 1) * (BATCH * HDIM);
        __half* hdst = g_h2 + (size_t)((t + 1) & 1) * (BATCH * HDIM);

        float acc[2][4];
#pragma unroll
        for (int i = 0; i < 2; i++)
#pragma unroll
            for (int j = 0; j < 4; j++) acc[i][j] = 0.0f;

        auto load_h = [&](int s, int k0) {
            char* base = smc + OFF_HST + s * 9216;
#pragma unroll
            for (int it = 0; it < 2; it++) {
                int op = it * 256 + tid;                 // 0..511
                int r = op >> 3, c = op & 7;
                cpa16(base + r * 144 + c * 16, hsrc + (size_t)r * HDIM + k0 + c * 8);
            }
            cpa_commit();
        };
        load_h(0, 0);
        load_h(1, 64);
        load_h(2, 128);

        for (int kt = 0; kt < 16; kt++) {
            int rem = 15 - kt;
            if (rem >= 2) cpa_wait2();
            else if (rem == 1) cpa_wait1();
            else cpa_wait0();
            __syncthreads();
            if (kt + 3 < 16) load_h((kt + 3) & 3, (kt + 3) * 64);

            uint32_t sAh = hst0 + (uint32_t)((kt & 3) * 9216) + aR;
            uint32_t sBh = sWhi + (uint32_t)(kt * 64) * 2;
            uint32_t sBl = sWlo + (uint32_t)(kt * 64) * 2;
#pragma unroll
            for (int ks = 0; ks < 64; ks += 16) {
                uint32_t ah[4], bh4[4], bl4[4];
                ldsm4(ah,  sAh + ks * 2);
                ldsm4(bh4, sBh + ks * 2);
                ldsm4(bl4, sBl + ks * 2);
                mma16816h(acc[0], ah, &bh4[0]);
                mma16816h(acc[1], ah, &bh4[2]);
                mma16816h(acc[0], ah, &bl4[0]);
                mma16816h(acc[1], ah, &bl4[2]);
            }
        }

        // prefetch P(t+1) into the other Ps buffer (h-independent)
        if (t + 1 < TSTEPS) {
#pragma unroll
            for (int it = 0; it < 2; it++) {
                int op = it * 256 + tid;
                int r = op >> 3, c = op & 7;
                cpa16(smc + OFF_PS + ((t + 1) & 1) * 8192 + r * 128 + c * 16,
                      g_P + ((size_t)(t + 1) * BATCH + r) * NG + n0 + c * 4);
            }
            cpa_commit();
        }

        // gate tile -> shared
#pragma unroll
        for (int nf = 0; nf < 2; nf++) {
            int col = n_off + nf * 8 + kb;
            int row = m_off + gid;
            Cs[row * 36 + col]           = acc[nf][0];
            Cs[row * 36 + col + 1]       = acc[nf][1];
            Cs[(row + 8) * 36 + col]     = acc[nf][2];
            Cs[(row + 8) * 36 + col + 1] = acc[nf][3];
        }
        __syncthreads();

        // fused cell + answer dot (MUFU)
        const float* Ps = (const float*)(smc + OFF_PS + (t & 1) * 8192);
#pragma unroll
        for (int half = 0; half < 2; half++) {
            int idx = tid + half * 256;
            int b = idx >> 3, jl = idx & 7;
            float4 cv = *(const float4*)(Cs + b * 36 + jl * 4);
            float4 pv = *(const float4*)(Ps + b * 32 + jl * 4);
            float gi = cv.x + pv.x, gf = cv.y + pv.y;
            float gg = cv.z + pv.z, go = cv.w + pv.w;
            gi = fminf(fmaxf(gi, -15.0f), 15.0f);
            gf = fminf(fmaxf(gf, -15.0f), 15.0f);
            gg = fminf(fmaxf(gg, -15.0f), 15.0f);
            go = fminf(fmaxf(go, -15.0f), 15.0f);
            float ei = ex2f(-gi * L2E);
            float ef = ex2f(-gf * L2E);
            float eo = ex2f(-go * L2E);
            float d1 = 1.0f + ei, d2 = 1.0f + ef, d3 = 1.0f + eo;
            float m12 = d1 * d2, m23 = d2 * d3, m13 = d1 * d3;
            float r = rcpf(m12 * d3);
            float si = r * m23, sf = r * m13, so = r * m12;
            float eg = ex2f(gg * L2E2);
            float tg = (eg - 1.0f) * rcpf(eg + 1.0f);
            float c = sf * cs[b * 8 + jl] + si * tg;
            cs[b * 8 + jl] = c;
            float ac = fminf(fmaxf(c * L2E2, -60.0f), 60.0f);
            float ec = ex2f(ac);
            float tc = (ec - 1.0f) * rcpf(ec + 1.0f);
            float h = so * tc;
            hdst[(size_t)b * HDIM + j0 + jl] = __float2half_rn(h);
            float p = h * was[jl];
            p += __shfl_xor_sync(0xFFFFFFFFu, p, 4);
            p += __shfl_xor_sync(0xFFFFFFFFu, p, 2);
            p += __shfl_xor_sync(0xFFFFFFFFu, p, 1);
            if (t >= SEL_START && (lane & 7) == 0)
                atomicAdd(&out[b * SEL_COUNT + (t - SEL_START)], p);
        }

        // ---- grid-wide barrier (128 CTAs, 1/SM, single wave, hard spin) ----
        __threadfence();
        __syncthreads();
        if (tid == 0) {
            atomicAdd(&g_arrive, 1u);
            unsigned tgt = (unsigned)(t + 1) * NCTA;
            while (ldv(&g_arrive) < tgt) { }
            __threadfence();
        }
        __syncthreads();
    }
}

// ---------------- launch ----------------
extern "C" void kernel_launch(void* const* d_in, const int* in_sizes, int n_in,
                              void* d_out, int out_size) {
    (void)in_sizes; (void)n_in; (void)out_size;
    const void*  prob  = d_in[0];
    const float* table = (const float*)d_in[2];
    const float* w_ih  = (const float*)d_in[3];
    const float* w_hh  = (const float*)d_in[4];
    const float* b_ih  = (const float*)d_in[5];
    const float* b_hh  = (const float*)d_in[6];
    const float* w_ans = (const float*)d_in[7];
    const float* b_ans = (const float*)d_in[8];
    const float* h0    = (const float*)d_in[9];
    const float* c0    = (const float*)d_in[10];
    float* out = (float*)d_out;

    static bool inited = false;
    if (!inited) {
        cudaFuncSetAttribute(lstm_persist, cudaFuncAttributeMaxDynamicSharedMemorySize, SMEM_PERSIST);
        inited = true;
    }

    fused_init<<<69, 1024>>>((const int*)prob, h0, out, b_ans);
    gather_split<<<TSTEPS * BATCH, 128>>>(prob, table);
    convert_all<<<2 * NG, 256>>>(w_ih, w_hh, b_ih, b_hh);
    lstm_persist<<<NCTA, 256, SMEM_PERSIST>>>(c0, w_ans, out);
}

// round 8
// speedup vs baseline: 3.5487x; 1.0366x over previous
#include <cuda_runtime.h>
#include <cuda_bf16.h>
#include <cuda_fp16.h>
#include <cstdint>

#define SEQ       128
#define BATCH     64
#define EMBED     512
#define HDIM      1024
#define NG        4096
#define TSTEPS    127
#define SEL_START 65
#define SEL_COUNT 62
#define NCTA      128

// ---------------- device scratch ----------------
__device__ __nv_bfloat16 g_Xhi[TSTEPS * BATCH * EMBED];
__device__ __nv_bfloat16 g_Xlo[TSTEPS * BATCH * EMBED];
__device__ __nv_bfloat16 g_Wih_hi[NG * EMBED];
__device__ __nv_bfloat16 g_Wih_lo[NG * EMBED];
__device__ __half        g_Whh[NG * HDIM];     // fp16, gate-interleaved rows
__device__ float g_bsum[NG];
__device__ float g_P[TSTEPS * BATCH * NG];     // preacts, gate-interleaved cols
__device__ __half g_h2[2 * BATCH * HDIM];      // ping-pong h (fp16)
__device__ unsigned g_arrive;
__device__ int g_is64;

// ---------------- smem layout (bytes) ----------------
#define OFF_WHI 0        // fp16 [32][1032]  66048
#define OFF_H   66048    // fp16 [64][1032]  132096  (full-K h buffer)
#define OFF_PS  198144   // 2 x [64][32] f32 = 16384
#define OFF_CS  214528   // [64][36] f32 = 9216
#define OFF_CC  223744   // [64][8] f32 = 2048
#define OFF_WAS 225792   // [8] f32 = 32
#define SMEM_PERSIST 225824
// phase-0 overlay: Bh bf16[32][520]@0 (33280), Bl@33280; A stages @132096 (2x10240)

// ---------------- helpers ----------------
__device__ __forceinline__ void cvt_split(__nv_bfloat16* hi, __nv_bfloat16* lo, float v) {
    __nv_bfloat16 h = __float2bfloat16(v);
    *hi = h;
    *lo = __float2bfloat16(v - __bfloat162float(h));
}
__device__ __forceinline__ void mma16816(float* c, const uint32_t* a, const uint32_t* b) {
    asm volatile(
        "mma.sync.aligned.m16n8k16.row.col.f32.bf16.bf16.f32 "
        "{%0,%1,%2,%3}, {%4,%5,%6,%7}, {%8,%9}, {%0,%1,%2,%3};\n"
        : "+f"(c[0]), "+f"(c[1]), "+f"(c[2]), "+f"(c[3])
        : "r"(a[0]), "r"(a[1]), "r"(a[2]), "r"(a[3]), "r"(b[0]), "r"(b[1]));
}
__device__ __forceinline__ void mma16816h(float* c, const uint32_t* a, const uint32_t* b) {
    asm volatile(
        "mma.sync.aligned.m16n8k16.row.col.f32.f16.f16.f32 "
        "{%0,%1,%2,%3}, {%4,%5,%6,%7}, {%8,%9}, {%0,%1,%2,%3};\n"
        : "+f"(c[0]), "+f"(c[1]), "+f"(c[2]), "+f"(c[3])
        : "r"(a[0]), "r"(a[1]), "r"(a[2]), "r"(a[3]), "r"(b[0]), "r"(b[1]));
}
__device__ __forceinline__ void ldsm4(uint32_t* r, uint32_t saddr) {
    asm volatile("ldmatrix.sync.aligned.m8n8.x4.shared.b16 {%0,%1,%2,%3}, [%4];"
        : "=r"(r[0]), "=r"(r[1]), "=r"(r[2]), "=r"(r[3]) : "r"(saddr));
}
__device__ __forceinline__ uint32_t sptr(const void* p) {
    return (uint32_t)__cvta_generic_to_shared(p);
}
__device__ __forceinline__ void cpa16(void* smem, const void* g) {
    uint32_t s = sptr(smem);
    asm volatile("cp.async.cg.shared.global [%0], [%1], 16;\n" :: "r"(s), "l"(g));
}
__device__ __forceinline__ void cpa_commit() { asm volatile("cp.async.commit_group;\n"); }
__device__ __forceinline__ void cpa_wait1()  { asm volatile("cp.async.wait_group 1;\n"); }
__device__ __forceinline__ void cpa_wait0()  { asm volatile("cp.async.wait_group 0;\n"); }
__device__ __forceinline__ unsigned ldv(const unsigned* p) { return *(volatile const unsigned*)p; }
__device__ __forceinline__ float ex2f(float x) {
    float y; asm("ex2.approx.f32 %0, %1;" : "=f"(y) : "f"(x)); return y;
}
__device__ __forceinline__ float rcpf(float x) {
    float y; asm("rcp.approx.f32 %0, %1;" : "=f"(y) : "f"(x)); return y;
}
#define L2E  1.4426950408889634f
#define L2E2 2.8853900817779268f

// ---------------- fused init ----------------
__global__ void fused_init(const int* __restrict__ prob32, const float* __restrict__ h0,
                           float* __restrict__ out, const float* __restrict__ b_ans) {
    int bid = blockIdx.x;
    if (bid == 0) {
        __shared__ int any;
        if (threadIdx.x == 0) any = 0;
        __syncthreads();
        int local = 0;
        for (int i = 2 * threadIdx.x + 1; i < BATCH * SEQ; i += 2 * blockDim.x)
            local |= prob32[i];
        if (local) atomicOr(&any, 1);
        __syncthreads();
        if (threadIdx.x == 0) { g_is64 = (any == 0) ? 1 : 0; g_arrive = 0u; }
    } else if (bid <= 64) {
        int i = (bid - 1) * 1024 + threadIdx.x;
        g_h2[i] = __float2half_rn(h0[i]);
    } else {
        int i = (bid - 65) * 1024 + threadIdx.x;
        if (i < BATCH * SEL_COUNT) out[i] = b_ans[0];
    }
}

// ---------------- embedding gather + split ----------------
__global__ void gather_split(const void* __restrict__ prob, const float* __restrict__ table) {
    int row = blockIdx.x;            // t*64 + b
    int t = row >> 6, b = row & 63;
    long long tok;
    if (g_is64) tok = ((const long long*)prob)[b * SEQ + t];
    else        tok = (long long)((const int*)prob)[b * SEQ + t];
    float4 v = ((const float4*)(table + (size_t)tok * EMBED))[threadIdx.x];
    int o = row * EMBED + threadIdx.x * 4;
    cvt_split(&g_Xhi[o + 0], &g_Xlo[o + 0], v.x);
    cvt_split(&g_Xhi[o + 1], &g_Xlo[o + 1], v.y);
    cvt_split(&g_Xhi[o + 2], &g_Xlo[o + 2], v.z);
    cvt_split(&g_Xhi[o + 3], &g_Xlo[o + 3], v.w);
}

// ---------------- weight conversion (gate-interleave: n = 4*j + g) -------
__global__ void convert_all(const float* __restrict__ w_ih, const float* __restrict__ w_hh,
                            const float* __restrict__ b_ih, const float* __restrict__ b_hh) {
    int n = blockIdx.x;
    if (n < NG) {                    // w_ih -> bf16 hi/lo
        int j = n >> 2, g = n & 3;
        int r = g * HDIM + j;
        if (threadIdx.x < 128) {
            float4 v = ((const float4*)(w_ih + (size_t)r * EMBED))[threadIdx.x];
            int o = n * EMBED + threadIdx.x * 4;
            cvt_split(&g_Wih_hi[o + 0], &g_Wih_lo[o + 0], v.x);
            cvt_split(&g_Wih_hi[o + 1], &g_Wih_lo[o + 1], v.y);
            cvt_split(&g_Wih_hi[o + 2], &g_Wih_lo[o + 2], v.z);
            cvt_split(&g_Wih_hi[o + 3], &g_Wih_lo[o + 3], v.w);
        }
        if (threadIdx.x == 0) g_bsum[n] = b_ih[r] + b_hh[r];
    } else {                         // w_hh -> fp16
        n -= NG;
        int j = n >> 2, g = n & 3;
        int r = g * HDIM + j;
        float4 v = ((const float4*)(w_hh + (size_t)r * HDIM))[threadIdx.x];
        int o = n * HDIM + threadIdx.x * 4;
        g_Whh[o + 0] = __float2half_rn(v.x);
        g_Whh[o + 1] = __float2half_rn(v.y);
        g_Whh[o + 2] = __float2half_rn(v.z);
        g_Whh[o + 3] = __float2half_rn(v.w);
    }
}

// ---------------- persistent mega-kernel: pre-GEMM phase + recurrence ----
__global__ __launch_bounds__(256, 1)
void lstm_persist(const float* __restrict__ c0, const float* __restrict__ w_ans,
                  float* __restrict__ out) {
    extern __shared__ char smc[];
    const int tid = threadIdx.x, warp = tid >> 5, lane = tid & 31;
    const int gid = lane >> 2, kb = (lane & 3) << 1;
    const int m_off = (warp & 3) << 4;    // 0..48
    const int n_off = (warp >> 2) << 4;   // 0,16
    const int n0 = blockIdx.x << 5;
    const int j0 = blockIdx.x << 3;
    const int a_r = (lane & 7) + (lane & 8);
    const int a_c = (lane & 16) >> 1;
    const int b_r = (lane & 7) + ((lane & 16) >> 1);
    const int b_c = (lane & 8);

    // ================= PHASE 0: P = X @ Wih^T + bsum (own 32 cols) =======
    {
#pragma unroll
        for (int it = 0; it < 8; it++) {
            int op = it * 256 + tid;        // 0..2047
            int r = op >> 6, c = op & 63;
            cpa16(smc + (size_t)r * 1040 + c * 16,
                  g_Wih_hi + (size_t)(n0 + r) * EMBED + c * 8);
            cpa16(smc + 33280 + (size_t)r * 1040 + c * 16,
                  g_Wih_lo + (size_t)(n0 + r) * EMBED + c * 8);
        }
        cpa_commit();
        float* bs = (float*)(smc + OFF_CS);
        if (tid < 32) bs[tid] = g_bsum[n0 + tid];
        cpa_wait0();
        __syncthreads();

        const uint32_t aP  = (uint32_t)((m_off + a_r) * 40 + a_c) * 2;
        const uint32_t bP0 = sptr(smc) + (uint32_t)((n_off + b_r) * 520 + b_c) * 2;

        for (int mt = 0; mt < 127; mt++) {
            const int m0 = mt << 6;
            float acc0[2][4];
#pragma unroll
            for (int i = 0; i < 2; i++)
#pragma unroll
                for (int j = 0; j < 4; j++) acc0[i][j] = 0.0f;

            auto loadA = [&](int s, int k0) {
                char* base = smc + 132096 + s * 10240;
                int r = tid >> 2, c = tid & 3;
                cpa16(base + r * 80 + c * 16,
                      g_Xhi + (size_t)(m0 + r) * EMBED + k0 + c * 8);
                cpa16(base + 5120 + r * 80 + c * 16,
                      g_Xlo + (size_t)(m0 + r) * EMBED + k0 + c * 8);
                cpa_commit();
            };
            loadA(0, 0);
            for (int kt = 0; kt < 16; kt++) {
                if (kt < 15) { loadA((kt + 1) & 1, (kt + 1) * 32); cpa_wait1(); }
                else cpa_wait0();
                __syncthreads();
                uint32_t sA   = sptr(smc + 132096 + (kt & 1) * 10240);
                uint32_t sAhi = sA + aP, sAlo = sA + 5120 + aP;
                uint32_t kB   = (uint32_t)(kt * 32) * 2;
#pragma unroll
                for (int ks = 0; ks < 32; ks += 16) {
                    uint32_t ah[4], al[4], bh4[4], bl4[4];
                    ldsm4(ah,  sAhi + ks * 2);
                    ldsm4(al,  sAlo + ks * 2);
                    ldsm4(bh4, bP0 + kB + ks * 2);
                    ldsm4(bl4, bP0 + 33280 + kB + ks * 2);
                    mma16816(acc0[0], ah, &bh4[0]);
                    mma16816(acc0[0], ah, &bl4[0]);
                    mma16816(acc0[0], al, &bh4[0]);
                    mma16816(acc0[1], ah, &bh4[2]);
                    mma16816(acc0[1], ah, &bl4[2]);
                    mma16816(acc0[1], al, &bh4[2]);
                }
                __syncthreads();
            }
#pragma unroll
            for (int nf = 0; nf < 2; nf++) {
                int lc = n_off + nf * 8 + kb;
                int col = n0 + lc;
                int row = m0 + m_off + gid;
                float b0 = bs[lc], b1 = bs[lc + 1];
                g_P[(size_t)row * NG + col]           = acc0[nf][0] + b0;
                g_P[(size_t)row * NG + col + 1]       = acc0[nf][1] + b1;
                g_P[(size_t)(row + 8) * NG + col]     = acc0[nf][2] + b0;
                g_P[(size_t)(row + 8) * NG + col + 1] = acc0[nf][3] + b1;
            }
        }
        __syncthreads();
    }

    // ================= load resident Whh (fp16) + state ==================
#pragma unroll
    for (int it = 0; it < 16; it++) {
        int op = it * 256 + tid;          // 0..4095
        int r = op >> 7, c = op & 127;
        cpa16(smc + OFF_WHI + (size_t)r * 2064 + c * 16,
              g_Whh + (size_t)(n0 + r) * HDIM + c * 8);
    }
    cpa_commit();
    float* Cs  = (float*)(smc + OFF_CS);
    float* cs  = (float*)(smc + OFF_CC);
    float* was = (float*)(smc + OFF_WAS);
    if (tid < 128) {
        int b = tid >> 1, q = tid & 1;
        float4 v = *(const float4*)(c0 + (size_t)b * HDIM + j0 + q * 4);
        *(float4*)(cs + b * 8 + q * 4) = v;
    }
    if (tid < 8) was[tid] = w_ans[j0 + tid];
    cpa_wait0();
    __syncthreads();

    // ================= recurrence =========================================
    const uint32_t sWB = sptr(smc + OFF_WHI) + (uint32_t)((n_off + b_r) * 1032 + b_c) * 2;
    const uint32_t sAB = sptr(smc + OFF_H)   + (uint32_t)((m_off + a_r) * 1032 + a_c) * 2;

    // P(0) prologue load into Ps buf 0
    {
#pragma unroll
        for (int it = 0; it < 2; it++) {
            int op = it * 256 + tid;
            int r = op >> 3, c = op & 7;
            cpa16(smc + OFF_PS + r * 128 + c * 16, g_P + (size_t)r * NG + n0 + c * 4);
        }
        cpa_commit();
    }

    for (int t = 0; t < TSTEPS; t++) {
        const __half* hsrc = g_h2 + (size_t)(t & 1) * (BATCH * HDIM);
        __half* hdst = g_h2 + (size_t)((t + 1) & 1) * (BATCH * HDIM);

        float acc[2][4];
#pragma unroll
        for (int i = 0; i < 2; i++)
#pragma unroll
            for (int j = 0; j < 4; j++) acc[i][j] = 0.0f;

        // ---- load full h (2 chunks of k: 0..511, 512..1023) ----
#pragma unroll
        for (int ch = 0; ch < 2; ch++) {
#pragma unroll
            for (int it = 0; it < 16; it++) {
                int g = it * 256 + tid;          // 0..4095 within chunk
                int r = g >> 6, c = (g & 63) + ch * 64;
                cpa16(smc + OFF_H + (size_t)r * 2064 + c * 16,
                      hsrc + (size_t)r * HDIM + c * 8);
            }
            cpa_commit();
        }

        // ---- first half (k 0..511) ----
        cpa_wait1();
        __syncthreads();
#pragma unroll
        for (int kt = 0; kt < 8; kt++) {
#pragma unroll
            for (int ks = 0; ks < 64; ks += 16) {
                uint32_t koff = (uint32_t)(kt * 64 + ks) * 2;
                uint32_t ah[4], bh4[4];
                ldsm4(ah,  sAB + koff);
                ldsm4(bh4, sWB + koff);
                mma16816h(acc[0], ah, &bh4[0]);
                mma16816h(acc[1], ah, &bh4[2]);
            }
        }
        // ---- second half (k 512..1023) ----
        cpa_wait0();
        __syncthreads();
#pragma unroll
        for (int kt = 8; kt < 16; kt++) {
#pragma unroll
            for (int ks = 0; ks < 64; ks += 16) {
                uint32_t koff = (uint32_t)(kt * 64 + ks) * 2;
                uint32_t ah[4], bh4[4];
                ldsm4(ah,  sAB + koff);
                ldsm4(bh4, sWB + koff);
                mma16816h(acc[0], ah, &bh4[0]);
                mma16816h(acc[1], ah, &bh4[2]);
            }
        }

        // prefetch P(t+1) into the other Ps buffer (h-independent)
        if (t + 1 < TSTEPS) {
#pragma unroll
            for (int it = 0; it < 2; it++) {
                int op = it * 256 + tid;
                int r = op >> 3, c = op & 7;
                cpa16(smc + OFF_PS + ((t + 1) & 1) * 8192 + r * 128 + c * 16,
                      g_P + ((size_t)(t + 1) * BATCH + r) * NG + n0 + c * 4);
            }
            cpa_commit();
        }

        // gate tile -> shared
#pragma unroll
        for (int nf = 0; nf < 2; nf++) {
            int col = n_off + nf * 8 + kb;
            int row = m_off + gid;
            Cs[row * 36 + col]           = acc[nf][0];
            Cs[row * 36 + col + 1]       = acc[nf][1];
            Cs[(row + 8) * 36 + col]     = acc[nf][2];
            Cs[(row + 8) * 36 + col + 1] = acc[nf][3];
        }
        __syncthreads();

        // fused cell + answer dot (MUFU)
        const float* Ps = (const float*)(smc + OFF_PS + (t & 1) * 8192);
#pragma unroll
        for (int half = 0; half < 2; half++) {
            int idx = tid + half * 256;
            int b = idx >> 3, jl = idx & 7;
            float4 cv = *(const float4*)(Cs + b * 36 + jl * 4);
            float4 pv = *(const float4*)(Ps + b * 32 + jl * 4);
            float gi = cv.x + pv.x, gf = cv.y + pv.y;
            float gg = cv.z + pv.z, go = cv.w + pv.w;
            gi = fminf(fmaxf(gi, -15.0f), 15.0f);
            gf = fminf(fmaxf(gf, -15.0f), 15.0f);
            gg = fminf(fmaxf(gg, -15.0f), 15.0f);
            go = fminf(fmaxf(go, -15.0f), 15.0f);
            float ei = ex2f(-gi * L2E);
            float ef = ex2f(-gf * L2E);
            float eo = ex2f(-go * L2E);
            float d1 = 1.0f + ei, d2 = 1.0f + ef, d3 = 1.0f + eo;
            float m12 = d1 * d2, m23 = d2 * d3, m13 = d1 * d3;
            float r = rcpf(m12 * d3);
            float si = r * m23, sf = r * m13, so = r * m12;
            float eg = ex2f(gg * L2E2);
            float tg = (eg - 1.0f) * rcpf(eg + 1.0f);
            float c = sf * cs[b * 8 + jl] + si * tg;
            cs[b * 8 + jl] = c;
            float ac = fminf(fmaxf(c * L2E2, -60.0f), 60.0f);
            float ec = ex2f(ac);
            float tc = (ec - 1.0f) * rcpf(ec + 1.0f);
            float h = so * tc;
            hdst[(size_t)b * HDIM + j0 + jl] = __float2half_rn(h);
            float p = h * was[jl];
            p += __shfl_xor_sync(0xFFFFFFFFu, p, 4);
            p += __shfl_xor_sync(0xFFFFFFFFu, p, 2);
            p += __shfl_xor_sync(0xFFFFFFFFu, p, 1);
            if (t >= SEL_START && (lane & 7) == 0)
                atomicAdd(&out[b * SEL_COUNT + (t - SEL_START)], p);
        }

        // ---- grid-wide barrier (128 CTAs, 1/SM, single wave, hard spin) ----
        __threadfence();
        __syncthreads();
        if (tid == 0) {
            atomicAdd(&g_arrive, 1u);
            unsigned tgt = (unsigned)(t + 1) * NCTA;
            while (ldv(&g_arrive) < tgt) { }
            __threadfence();
        }
        __syncthreads();
    }
}

// ---------------- launch ----------------
extern "C" void kernel_launch(void* const* d_in, const int* in_sizes, int n_in,
                              void* d_out, int out_size) {
    (void)in_sizes; (void)n_in; (void)out_size;
    const void*  prob  = d_in[0];
    const float* table = (const float*)d_in[2];
    const float* w_ih  = (const float*)d_in[3];
    const float* w_hh  = (const float*)d_in[4];
    const float* b_ih  = (const float*)d_in[5];
    const float* b_hh  = (const float*)d_in[6];
    const float* w_ans = (const float*)d_in[7];
    const float* b_ans = (const float*)d_in[8];
    const float* h0    = (const float*)d_in[9];
    const float* c0    = (const float*)d_in[10];
    float* out = (float*)d_out;

    static bool inited = false;
    if (!inited) {
        cudaFuncSetAttribute(lstm_persist, cudaFuncAttributeMaxDynamicSharedMemorySize, SMEM_PERSIST);
        inited = true;
    }

    fused_init<<<69, 1024>>>((const int*)prob, h0, out, b_ans);
    gather_split<<<TSTEPS * BATCH, 128>>>(prob, table);
    convert_all<<<2 * NG, 256>>>(w_ih, w_hh, b_ih, b_hh);
    lstm_persist<<<NCTA, 256, SMEM_PERSIST>>>(c0, w_ans, out);
}

// round 9
// speedup vs baseline: 5.3121x; 1.4969x over previous
#include <cuda_runtime.h>
#include <cuda_bf16.h>
#include <cuda_fp16.h>
#include <cstdint>

#define SEQ       128
#define BATCH     64
#define EMBED     512
#define HDIM      1024
#define NG        4096
#define TSTEPS    127
#define SEL_START 65
#define SEL_COUNT 62
#define MPAD      8192
#define NCTA      128

// ---------------- device scratch ----------------
__device__ __nv_bfloat16 g_Xhi[MPAD * EMBED];
__device__ __nv_bfloat16 g_Xlo[MPAD * EMBED];
__device__ __nv_bfloat16 g_Wih_hi[NG * EMBED];
__device__ __nv_bfloat16 g_Wih_lo[NG * EMBED];
__device__ __half        g_Whh[NG * HDIM];     // fp16, gate-interleaved rows
__device__ float g_bsum[NG];
__device__ float g_P[TSTEPS * BATCH * NG];     // preacts, gate-interleaved cols
__device__ __half g_h2[2 * BATCH * HDIM];      // ping-pong h (fp16)
__device__ unsigned g_arrive;
__device__ int g_is64;

// ---------------- smem layout for lstm_persist (bytes) ----------------
#define OFF_WHI 0        // fp16 [32][1032] = 66048; after Breg load reused as partials [4][64][36] f32
#define OFF_H   66048    // fp16 [64][1032] = 132096  (full-K h buffer)
#define OFF_PS  198144   // 2 x [64][32] f32 = 16384
#define OFF_CC  214528   // [64][8] f32 = 2048
#define OFF_WAS 216576   // [8] f32 = 32
#define SMEM_PERSIST 216608

// ---------------- helpers ----------------
__device__ __forceinline__ void cvt_split(__nv_bfloat16* hi, __nv_bfloat16* lo, float v) {
    __nv_bfloat16 h = __float2bfloat16(v);
    *hi = h;
    *lo = __float2bfloat16(v - __bfloat162float(h));
}
__device__ __forceinline__ void mma16816(float* c, const uint32_t* a, const uint32_t* b) {
    asm volatile(
        "mma.sync.aligned.m16n8k16.row.col.f32.bf16.bf16.f32 "
        "{%0,%1,%2,%3}, {%4,%5,%6,%7}, {%8,%9}, {%0,%1,%2,%3};\n"
        : "+f"(c[0]), "+f"(c[1]), "+f"(c[2]), "+f"(c[3])
        : "r"(a[0]), "r"(a[1]), "r"(a[2]), "r"(a[3]), "r"(b[0]), "r"(b[1]));
}
__device__ __forceinline__ void mma16816h(float* c, const uint32_t* a, const uint32_t* b) {
    asm volatile(
        "mma.sync.aligned.m16n8k16.row.col.f32.f16.f16.f32 "
        "{%0,%1,%2,%3}, {%4,%5,%6,%7}, {%8,%9}, {%0,%1,%2,%3};\n"
        : "+f"(c[0]), "+f"(c[1]), "+f"(c[2]), "+f"(c[3])
        : "r"(a[0]), "r"(a[1]), "r"(a[2]), "r"(a[3]), "r"(b[0]), "r"(b[1]));
}
__device__ __forceinline__ void ldsm4(uint32_t* r, uint32_t saddr) {
    asm volatile("ldmatrix.sync.aligned.m8n8.x4.shared.b16 {%0,%1,%2,%3}, [%4];"
        : "=r"(r[0]), "=r"(r[1]), "=r"(r[2]), "=r"(r[3]) : "r"(saddr));
}
__device__ __forceinline__ uint32_t sptr(const void* p) {
    return (uint32_t)__cvta_generic_to_shared(p);
}
__device__ __forceinline__ void cpa16(void* smem, const void* g) {
    uint32_t s = sptr(smem);
    asm volatile("cp.async.cg.shared.global [%0], [%1], 16;\n" :: "r"(s), "l"(g));
}
__device__ __forceinline__ void cpa_commit() { asm volatile("cp.async.commit_group;\n"); }
__device__ __forceinline__ void cpa_wait1()  { asm volatile("cp.async.wait_group 1;\n"); }
__device__ __forceinline__ void cpa_wait0()  { asm volatile("cp.async.wait_group 0;\n"); }
__device__ __forceinline__ void barpair(int id) {
    asm volatile("bar.sync %0, 64;" :: "r"(id) : "memory");
}
__device__ __forceinline__ unsigned ldv(const unsigned* p) { return *(volatile const unsigned*)p; }
__device__ __forceinline__ float ex2f(float x) {
    float y; asm("ex2.approx.f32 %0, %1;" : "=f"(y) : "f"(x)); return y;
}
__device__ __forceinline__ float rcpf(float x) {
    float y; asm("rcp.approx.f32 %0, %1;" : "=f"(y) : "f"(x)); return y;
}
#define L2E  1.4426950408889634f
#define L2E2 2.8853900817779268f

// ---------------- fused init ----------------
__global__ void fused_init(const int* __restrict__ prob32, const float* __restrict__ h0,
                           float* __restrict__ out, const float* __restrict__ b_ans) {
    int bid = blockIdx.x;
    if (bid == 0) {
        __shared__ int any;
        if (threadIdx.x == 0) any = 0;
        __syncthreads();
        int local = 0;
        for (int i = 2 * threadIdx.x + 1; i < BATCH * SEQ; i += 2 * blockDim.x)
            local |= prob32[i];
        if (local) atomicOr(&any, 1);
        __syncthreads();
        if (threadIdx.x == 0) { g_is64 = (any == 0) ? 1 : 0; g_arrive = 0u; }
    } else if (bid <= 64) {
        int i = (bid - 1) * 1024 + threadIdx.x;
        g_h2[i] = __float2half_rn(h0[i]);
    } else {
        int i = (bid - 65) * 1024 + threadIdx.x;
        if (i < BATCH * SEL_COUNT) out[i] = b_ans[0];
    }
}

// ---------------- embedding gather + split ----------------
__global__ void gather_split(const void* __restrict__ prob, const float* __restrict__ table) {
    int row = blockIdx.x;            // t*64 + b
    int t = row >> 6, b = row & 63;
    long long tok;
    if (g_is64) tok = ((const long long*)prob)[b * SEQ + t];
    else        tok = (long long)((const int*)prob)[b * SEQ + t];
    float4 v = ((const float4*)(table + (size_t)tok * EMBED))[threadIdx.x];
    int o = row * EMBED + threadIdx.x * 4;
    cvt_split(&g_Xhi[o + 0], &g_Xlo[o + 0], v.x);
    cvt_split(&g_Xhi[o + 1], &g_Xlo[o + 1], v.y);
    cvt_split(&g_Xhi[o + 2], &g_Xlo[o + 2], v.z);
    cvt_split(&g_Xhi[o + 3], &g_Xlo[o + 3], v.w);
}

// ---------------- weight conversion (gate-interleave: n = 4*j + g) -------
__global__ void convert_all(const float* __restrict__ w_ih, const float* __restrict__ w_hh,
                            const float* __restrict__ b_ih, const float* __restrict__ b_hh) {
    int n = blockIdx.x;
    if (n < NG) {                    // w_ih -> bf16 hi/lo
        int j = n >> 2, g = n & 3;
        int r = g * HDIM + j;
        if (threadIdx.x < 128) {
            float4 v = ((const float4*)(w_ih + (size_t)r * EMBED))[threadIdx.x];
            int o = n * EMBED + threadIdx.x * 4;
            cvt_split(&g_Wih_hi[o + 0], &g_Wih_lo[o + 0], v.x);
            cvt_split(&g_Wih_hi[o + 1], &g_Wih_lo[o + 1], v.y);
            cvt_split(&g_Wih_hi[o + 2], &g_Wih_lo[o + 2], v.z);
            cvt_split(&g_Wih_hi[o + 3], &g_Wih_lo[o + 3], v.w);
        }
        if (threadIdx.x == 0) g_bsum[n] = b_ih[r] + b_hh[r];
    } else {                         // w_hh -> fp16
        n -= NG;
        int j = n >> 2, g = n & 3;
        int r = g * HDIM + j;
        float4 v = ((const float4*)(w_hh + (size_t)r * HDIM))[threadIdx.x];
        int o = n * HDIM + threadIdx.x * 4;
        g_Whh[o + 0] = __float2half_rn(v.x);
        g_Whh[o + 1] = __float2half_rn(v.y);
        g_Whh[o + 2] = __float2half_rn(v.z);
        g_Whh[o + 3] = __float2half_rn(v.w);
    }
}

// ---------------- pre-GEMM: P = X @ Wih^T + bsum  [8192x4096, K=512] ------
#define LDKp 40
#define PSTG 20480

__global__ __launch_bounds__(256, 1)
void gemm_pre() {
    extern __shared__ __nv_bfloat16 dsm[];
    const int tid = threadIdx.x, warp = tid >> 5, lane = tid & 31;
    const int gid = lane >> 2, kb = (lane & 3) << 1;
    const int m_off = (warp >> 2) << 6;
    const int n_off = (warp & 3) << 5;
    const int m0 = blockIdx.y << 7;
    const int n0 = blockIdx.x << 7;
    const int a_r = (lane & 7) + (lane & 8);
    const int a_c = (lane & 16) >> 1;
    const int b_r = (lane & 7) + ((lane & 16) >> 1);
    const int b_c = (lane & 8);

    float acc[4][4][4];
#pragma unroll
    for (int a = 0; a < 4; a++)
#pragma unroll
        for (int b = 0; b < 4; b++)
#pragma unroll
            for (int cc = 0; cc < 4; cc++) acc[a][b][cc] = 0.0f;

    auto load_stage = [&](int s, int k0) {
        __nv_bfloat16* base = dsm + s * PSTG;
#pragma unroll
        for (int it = 0; it < 8; it++) {
            int op = it * 256 + tid;
            int buf = op >> 9;
            int r = (op & 511) >> 2;
            int c = op & 3;
            __nv_bfloat16* dst = base + buf * 5120 + r * LDKp + c * 8;
            const __nv_bfloat16* src;
            if (buf == 0)      src = g_Xhi    + (size_t)(m0 + r) * EMBED + k0 + c * 8;
            else if (buf == 1) src = g_Xlo    + (size_t)(m0 + r) * EMBED + k0 + c * 8;
            else if (buf == 2) src = g_Wih_hi + (size_t)(n0 + r) * EMBED + k0 + c * 8;
            else               src = g_Wih_lo + (size_t)(n0 + r) * EMBED + k0 + c * 8;
            cpa16(dst, src);
        }
        cpa_commit();
    };

    auto compute = [&](int s) {
        uint32_t sA = sptr(dsm + s * PSTG);
        uint32_t aoff = (uint32_t)((m_off + a_r) * LDKp + a_c) * 2;
        uint32_t boff = (uint32_t)((n_off + b_r) * LDKp + b_c) * 2;
        uint32_t sAhi = sA + aoff,             sAlo = sA + 5120 * 2 + aoff;
        uint32_t sBhi = sA + 10240 * 2 + boff, sBlo = sA + 15360 * 2 + boff;
#pragma unroll
        for (int ks = 0; ks < 32; ks += 16) {
            uint32_t ah[4][4], al[4][4], bh4[2][4], bl4[2][4];
#pragma unroll
            for (int mf = 0; mf < 4; mf++) {
                ldsm4(ah[mf], sAhi + (uint32_t)(mf * 16 * LDKp + ks) * 2);
                ldsm4(al[mf], sAlo + (uint32_t)(mf * 16 * LDKp + ks) * 2);
            }
#pragma unroll
            for (int nh = 0; nh < 2; nh++) {
                ldsm4(bh4[nh], sBhi + (uint32_t)(nh * 16 * LDKp + ks) * 2);
                ldsm4(bl4[nh], sBlo + (uint32_t)(nh * 16 * LDKp + ks) * 2);
            }
#pragma unroll
            for (int nf = 0; nf < 4; nf++) {
                const uint32_t* bh = &bh4[nf >> 1][(nf & 1) * 2];
                const uint32_t* bl = &bl4[nf >> 1][(nf & 1) * 2];
#pragma unroll
                for (int mf = 0; mf < 4; mf++) {
                    mma16816(acc[mf][nf], ah[mf], bh);
                    mma16816(acc[mf][nf], ah[mf], bl);
                    mma16816(acc[mf][nf], al[mf], bh);
                }
            }
        }
    };

    const int KT = EMBED / 32;
    load_stage(0, 0);
    for (int kt = 0; kt < KT; kt++) {
        if (kt + 1 < KT) load_stage((kt + 1) & 1, (kt + 1) * 32);
        if (kt + 1 < KT) cpa_wait1(); else cpa_wait0();
        __syncthreads();
        compute(kt & 1);
        __syncthreads();
    }

#pragma unroll
    for (int mf = 0; mf < 4; mf++)
#pragma unroll
        for (int nf = 0; nf < 4; nf++) {
            int row = m0 + m_off + mf * 16 + gid;
            int col = n0 + n_off + nf * 8 + kb;
            float b0 = g_bsum[col], b1 = g_bsum[col + 1];
            if (row < TSTEPS * BATCH) {
                g_P[(size_t)row * NG + col]     = acc[mf][nf][0] + b0;
                g_P[(size_t)row * NG + col + 1] = acc[mf][nf][1] + b1;
            }
            if (row + 8 < TSTEPS * BATCH) {
                g_P[(size_t)(row + 8) * NG + col]     = acc[mf][nf][2] + b0;
                g_P[(size_t)(row + 8) * NG + col + 1] = acc[mf][nf][3] + b1;
            }
        }
}

// ---------------- persistent recurrent kernel -----------------------------
// 8 warps = 4 K-quarters (kq) x 2 N-halves (nh). Weight fragments register-
// resident across all steps; h loaded per kq-pair with named barriers;
// K-partials reduced through smem (reusing the dead W region).
__global__ __launch_bounds__(256, 1)
void lstm_persist(const float* __restrict__ c0, const float* __restrict__ w_ans,
                  float* __restrict__ out) {
    extern __shared__ char smc[];
    const int tid = threadIdx.x, warp = tid >> 5, lane = tid & 31;
    const int gid = lane >> 2, kb = (lane & 3) << 1;
    const int kq = warp >> 1;             // 0..3 K quarter
    const int nh = warp & 1;              // 0..1 N half (16 cols)
    const int n0 = blockIdx.x << 5;
    const int j0 = blockIdx.x << 3;
    const int a_r = (lane & 7) + (lane & 8);
    const int a_c = (lane & 16) >> 1;
    const int b_r = (lane & 7) + ((lane & 16) >> 1);
    const int b_c = (lane & 8);

    // ---- load W tile [32][1024] fp16 into smem (temporarily) ----
#pragma unroll
    for (int it = 0; it < 16; it++) {
        int op = it * 256 + tid;          // 0..4095
        int r = op >> 7, c = op & 127;
        cpa16(smc + OFF_WHI + (size_t)r * 2064 + c * 16,
              g_Whh + (size_t)(n0 + r) * HDIM + c * 8);
    }
    cpa_commit();
    float* cs  = (float*)(smc + OFF_CC);
    float* was = (float*)(smc + OFF_WAS);
    if (tid < 128) {
        int b = tid >> 1, q = tid & 1;
        float4 v = *(const float4*)(c0 + (size_t)b * HDIM + j0 + q * 4);
        *(float4*)(cs + b * 8 + q * 4) = v;
    }
    if (tid < 8) was[tid] = w_ans[j0 + tid];
    cpa_wait0();
    __syncthreads();

    // ---- load weight fragments into registers (resident for all steps) ----
    uint32_t Breg[16][4];
    {
        uint32_t sWB = sptr(smc + OFF_WHI) + (uint32_t)((nh * 16 + b_r) * 1032 + b_c) * 2;
#pragma unroll
        for (int kf = 0; kf < 16; kf++)
            ldsm4(Breg[kf], sWB + (uint32_t)(kq * 256 + kf * 16) * 2);
    }
    __syncthreads();   // all warps done reading W smem; region now reusable

    const uint32_t sAB = sptr(smc + OFF_H) + (uint32_t)(a_r * 1032 + a_c) * 2;
    float* part = (float*)(smc + OFF_WHI);      // [4][64][36] f32 partials

    // P(0) prologue load into Ps buf 0 (its own group)
    {
#pragma unroll
        for (int it = 0; it < 2; it++) {
            int op = it * 256 + tid;
            int r = op >> 3, c = op & 7;
            cpa16(smc + OFF_PS + r * 128 + c * 16, g_P + (size_t)r * NG + n0 + c * 4);
        }
        cpa_commit();
    }

    for (int t = 0; t < TSTEPS; t++) {
        const __half* hsrc = g_h2 + (size_t)(t & 1) * (BATCH * HDIM);
        __half* hdst = g_h2 + (size_t)((t + 1) & 1) * (BATCH * HDIM);

        // ---- kq pair loads its K-quarter of h: 64 rows x 256 cols fp16 ----
        {
            int l64 = tid & 63;
#pragma unroll
            for (int it = 0; it < 32; it++) {
                int idx = it * 64 + l64;      // 0..2047
                int r = idx >> 5, c = idx & 31;
                cpa16(smc + OFF_H + (size_t)r * 2064 + (size_t)(kq * 512 + c * 16),
                      hsrc + (size_t)r * HDIM + kq * 256 + c * 8);
            }
            cpa_commit();
        }
        // ---- prefetch P(t+1) (dummy t=0 tile at last step) ----
        {
            int tp = (t + 1 < TSTEPS) ? (t + 1) : 0;
#pragma unroll
            for (int it = 0; it < 2; it++) {
                int op = it * 256 + tid;
                int r = op >> 3, c = op & 7;
                cpa16(smc + OFF_PS + ((t + 1) & 1) * 8192 + r * 128 + c * 16,
                      g_P + ((size_t)tp * BATCH + r) * NG + n0 + c * 4);
            }
            cpa_commit();
        }
        cpa_wait1();          // h chunk (and everything older) landed; P(t+1) pending
        barpair(1 + kq);      // pair-visibility for the h chunk

        // ---- MMA: A ldsm only; B fragments resident ----
        float acc[4][2][4];
#pragma unroll
        for (int a = 0; a < 4; a++)
#pragma unroll
            for (int b = 0; b < 2; b++)
#pragma unroll
                for (int q = 0; q < 4; q++) acc[a][b][q] = 0.0f;

#pragma unroll
        for (int kf = 0; kf < 16; kf++) {
            uint32_t koff = (uint32_t)(kq * 256 + kf * 16) * 2;
            uint32_t ah[4][4];
#pragma unroll
            for (int mf = 0; mf < 4; mf++)
                ldsm4(ah[mf], sAB + (uint32_t)(mf * 16 * 1032) * 2 + koff);
#pragma unroll
            for (int mf = 0; mf < 4; mf++) {
                mma16816h(acc[mf][0], ah[mf], &Breg[kf][0]);
                mma16816h(acc[mf][1], ah[mf], &Breg[kf][2]);
            }
        }

        // ---- store K-partials to smem: part[kq][row][col], stride 36 ----
        {
            float* pk = part + kq * 2304;
#pragma unroll
            for (int mf = 0; mf < 4; mf++)
#pragma unroll
                for (int nf = 0; nf < 2; nf++) {
                    int col = nh * 16 + nf * 8 + kb;
                    int row = mf * 16 + gid;
                    *(float2*)(pk + row * 36 + col)       = make_float2(acc[mf][nf][0], acc[mf][nf][1]);
                    *(float2*)(pk + (row + 8) * 36 + col) = make_float2(acc[mf][nf][2], acc[mf][nf][3]);
                }
        }
        __syncthreads();

        // ---- reduce partials + cell + answer dot ----
        const float* Ps = (const float*)(smc + OFF_PS + (t & 1) * 8192);
#pragma unroll
        for (int half = 0; half < 2; half++) {
            int idx = tid + half * 256;
            int b = idx >> 3, jl = idx & 7;
            const float* pb = part + b * 36 + jl * 4;
            float4 s0 = *(const float4*)(pb);
            float4 s1 = *(const float4*)(pb + 2304);
            float4 s2 = *(const float4*)(pb + 4608);
            float4 s3 = *(const float4*)(pb + 6912);
            float4 pv = *(const float4*)(Ps + b * 32 + jl * 4);
            float gi = s0.x + s1.x + s2.x + s3.x + pv.x;
            float gf = s0.y + s1.y + s2.y + s3.y + pv.y;
            float gg = s0.z + s1.z + s2.z + s3.z + pv.z;
            float go = s0.w + s1.w + s2.w + s3.w + pv.w;
            gi = fminf(fmaxf(gi, -15.0f), 15.0f);
            gf = fminf(fmaxf(gf, -15.0f), 15.0f);
            gg = fminf(fmaxf(gg, -15.0f), 15.0f);
            go = fminf(fmaxf(go, -15.0f), 15.0f);
            float ei = ex2f(-gi * L2E);
            float ef = ex2f(-gf * L2E);
            float eo = ex2f(-go * L2E);
            float d1 = 1.0f + ei, d2 = 1.0f + ef, d3 = 1.0f + eo;
            float m12 = d1 * d2, m23 = d2 * d3, m13 = d1 * d3;
            float r = rcpf(m12 * d3);
            float si = r * m23, sf = r * m13, so = r * m12;
            float eg = ex2f(gg * L2E2);
            float tg = (eg - 1.0f) * rcpf(eg + 1.0f);
            float c = sf * cs[b * 8 + jl] + si * tg;
            cs[b * 8 + jl] = c;
            float ac = fminf(fmaxf(c * L2E2, -60.0f), 60.0f);
            float ec = ex2f(ac);
            float tc = (ec - 1.0f) * rcpf(ec + 1.0f);
            float h = so * tc;
            hdst[(size_t)b * HDIM + j0 + jl] = __float2half_rn(h);
            float p = h * was[jl];
            p += __shfl_xor_sync(0xFFFFFFFFu, p, 4);
            p += __shfl_xor_sync(0xFFFFFFFFu, p, 2);
            p += __shfl_xor_sync(0xFFFFFFFFu, p, 1);
            if (t >= SEL_START && (lane & 7) == 0)
                atomicAdd(&out[b * SEL_COUNT + (t - SEL_START)], p);
        }

        // ---- grid-wide barrier (128 CTAs, 1/SM, single wave, hard spin) ----
        __threadfence();
        __syncthreads();
        if (tid == 0) {
            atomicAdd(&g_arrive, 1u);
            unsigned tgt = (unsigned)(t + 1) * NCTA;
            while (ldv(&g_arrive) < tgt) { }
            __threadfence();
        }
        __syncthreads();
    }
}

// ---------------- launch ----------------
extern "C" void kernel_launch(void* const* d_in, const int* in_sizes, int n_in,
                              void* d_out, int out_size) {
    (void)in_sizes; (void)n_in; (void)out_size;
    const void*  prob  = d_in[0];
    const float* table = (const float*)d_in[2];
    const float* w_ih  = (const float*)d_in[3];
    const float* w_hh  = (const float*)d_in[4];
    const float* b_ih  = (const float*)d_in[5];
    const float* b_hh  = (const float*)d_in[6];
    const float* w_ans = (const float*)d_in[7];
    const float* b_ans = (const float*)d_in[8];
    const float* h0    = (const float*)d_in[9];
    const float* c0    = (const float*)d_in[10];
    float* out = (float*)d_out;

    static bool inited = false;
    if (!inited) {
        cudaFuncSetAttribute(gemm_pre,     cudaFuncAttributeMaxDynamicSharedMemorySize, 2 * PSTG * 2);
        cudaFuncSetAttribute(lstm_persist, cudaFuncAttributeMaxDynamicSharedMemorySize, SMEM_PERSIST);
        inited = true;
    }

    fused_init<<<69, 1024>>>((const int*)prob, h0, out, b_ans);
    gather_split<<<TSTEPS * BATCH, 128>>>(prob, table);
    convert_all<<<2 * NG, 256>>>(w_ih, w_hh, b_ih, b_hh);
    gemm_pre<<<dim3(NG / 128, MPAD / 128), 256, 2 * PSTG * 2>>>();
    lstm_persist<<<NCTA, 256, SMEM_PERSIST>>>(c0, w_ans, out);
}

// round 10
// speedup vs baseline: 6.7395x; 1.2687x over previous
#include <cuda_runtime.h>
#include <cuda_bf16.h>
#include <cuda_fp16.h>
#include <cstdint>

#define SEQ       128
#define BATCH     64
#define EMBED     512
#define HDIM      1024
#define NG        4096
#define TSTEPS    127
#define SEL_START 65
#define SEL_COUNT 62
#define MPAD      8192
#define NCTA      128

// ---------------- device scratch ----------------
__device__ __half g_Xh[MPAD * EMBED];          // fp16 embeddings (t-major)
__device__ __half g_Wih[NG * EMBED];           // fp16 w_ih, gate-interleaved rows
__device__ __half g_Whh[NG * HDIM];            // fp16 w_hh, gate-interleaved rows
__device__ float g_bsum[NG];
__device__ float g_P[TSTEPS * BATCH * NG];     // preacts, gate-interleaved cols
__device__ __half g_h2[2 * BATCH * HDIM];      // ping-pong h (fp16)
__device__ unsigned g_arrive;
__device__ int g_is64;

// ---------------- smem layout for lstm_persist (bytes) ----------------
#define OFF_WHI 0        // fp16 [32][1032] = 66048; after Breg load reused as partials [4][64][36] f32
#define OFF_H   66048    // fp16 [64][1032] = 132096  (full-K h buffer)
#define OFF_PS  198144   // 2 x [64][32] f32 = 16384
#define OFF_CC  214528   // [64][8] f32 = 2048
#define OFF_WAS 216576   // [8] f32 = 32
#define SMEM_PERSIST 216608

// ---------------- gemm_pre smem: 2 stages x (A[128][72] + B[128][72]) fp16
#define GP_STAGE 36864
#define GP_SMEM  73728

// ---------------- helpers ----------------
__device__ __forceinline__ void mma16816h(float* c, const uint32_t* a, const uint32_t* b) {
    asm volatile(
        "mma.sync.aligned.m16n8k16.row.col.f32.f16.f16.f32 "
        "{%0,%1,%2,%3}, {%4,%5,%6,%7}, {%8,%9}, {%0,%1,%2,%3};\n"
        : "+f"(c[0]), "+f"(c[1]), "+f"(c[2]), "+f"(c[3])
        : "r"(a[0]), "r"(a[1]), "r"(a[2]), "r"(a[3]), "r"(b[0]), "r"(b[1]));
}
__device__ __forceinline__ void ldsm4(uint32_t* r, uint32_t saddr) {
    asm volatile("ldmatrix.sync.aligned.m8n8.x4.shared.b16 {%0,%1,%2,%3}, [%4];"
        : "=r"(r[0]), "=r"(r[1]), "=r"(r[2]), "=r"(r[3]) : "r"(saddr));
}
__device__ __forceinline__ uint32_t sptr(const void* p) {
    return (uint32_t)__cvta_generic_to_shared(p);
}
__device__ __forceinline__ void cpa16(void* smem, const void* g) {
    uint32_t s = sptr(smem);
    asm volatile("cp.async.cg.shared.global [%0], [%1], 16;\n" :: "r"(s), "l"(g));
}
__device__ __forceinline__ void cpa_commit() { asm volatile("cp.async.commit_group;\n"); }
__device__ __forceinline__ void cpa_wait1()  { asm volatile("cp.async.wait_group 1;\n"); }
__device__ __forceinline__ void cpa_wait0()  { asm volatile("cp.async.wait_group 0;\n"); }
__device__ __forceinline__ unsigned ldv(const unsigned* p) { return *(volatile const unsigned*)p; }
__device__ __forceinline__ float ex2f(float x) {
    float y; asm("ex2.approx.f32 %0, %1;" : "=f"(y) : "f"(x)); return y;
}
__device__ __forceinline__ float rcpf(float x) {
    float y; asm("rcp.approx.f32 %0, %1;" : "=f"(y) : "f"(x)); return y;
}
#define L2E  1.4426950408889634f
#define L2E2 2.8853900817779268f

// ---------------- fused init ----------------
__global__ void fused_init(const int* __restrict__ prob32, const float* __restrict__ h0,
                           float* __restrict__ out, const float* __restrict__ b_ans) {
    int bid = blockIdx.x;
    if (bid == 0) {
        __shared__ int any;
        if (threadIdx.x == 0) any = 0;
        __syncthreads();
        int local = 0;
        for (int i = 2 * threadIdx.x + 1; i < BATCH * SEQ; i += 2 * blockDim.x)
            local |= prob32[i];
        if (local) atomicOr(&any, 1);
        __syncthreads();
        if (threadIdx.x == 0) { g_is64 = (any == 0) ? 1 : 0; g_arrive = 0u; }
    } else if (bid <= 64) {
        int i = (bid - 1) * 1024 + threadIdx.x;
        g_h2[i] = __float2half_rn(h0[i]);
    } else {
        int i = (bid - 65) * 1024 + threadIdx.x;
        if (i < BATCH * SEL_COUNT) out[i] = b_ans[0];
    }
}

// ---------------- embedding gather (fp16) ----------------
__global__ void gather_split(const void* __restrict__ prob, const float* __restrict__ table) {
    int row = blockIdx.x;            // t*64 + b
    int t = row >> 6, b = row & 63;
    long long tok;
    if (g_is64) tok = ((const long long*)prob)[b * SEQ + t];
    else        tok = (long long)((const int*)prob)[b * SEQ + t];
    float4 v = ((const float4*)(table + (size_t)tok * EMBED))[threadIdx.x];
    int o = row * EMBED + threadIdx.x * 4;
    g_Xh[o + 0] = __float2half_rn(v.x);
    g_Xh[o + 1] = __float2half_rn(v.y);
    g_Xh[o + 2] = __float2half_rn(v.z);
    g_Xh[o + 3] = __float2half_rn(v.w);
}

// ---------------- weight conversion (gate-interleave: n = 4*j + g) -------
__global__ void convert_all(const float* __restrict__ w_ih, const float* __restrict__ w_hh,
                            const float* __restrict__ b_ih, const float* __restrict__ b_hh) {
    int n = blockIdx.x;
    if (n < NG) {                    // w_ih -> fp16
        int j = n >> 2, g = n & 3;
        int r = g * HDIM + j;
        if (threadIdx.x < 128) {
            float4 v = ((const float4*)(w_ih + (size_t)r * EMBED))[threadIdx.x];
            int o = n * EMBED + threadIdx.x * 4;
            g_Wih[o + 0] = __float2half_rn(v.x);
            g_Wih[o + 1] = __float2half_rn(v.y);
            g_Wih[o + 2] = __float2half_rn(v.z);
            g_Wih[o + 3] = __float2half_rn(v.w);
        }
        if (threadIdx.x == 0) g_bsum[n] = b_ih[r] + b_hh[r];
    } else {                         // w_hh -> fp16
        n -= NG;
        int j = n >> 2, g = n & 3;
        int r = g * HDIM + j;
        float4 v = ((const float4*)(w_hh + (size_t)r * HDIM))[threadIdx.x];
        int o = n * HDIM + threadIdx.x * 4;
        g_Whh[o + 0] = __float2half_rn(v.x);
        g_Whh[o + 1] = __float2half_rn(v.y);
        g_Whh[o + 2] = __float2half_rn(v.z);
        g_Whh[o + 3] = __float2half_rn(v.w);
    }
}

// ---------------- pre-GEMM: P = Xh @ Wih^T + bsum  [8192x4096, K=512] -----
// fp16 single MMA. BM=128 BN=128 BK=64, 256 threads, 2 CTAs/SM.
__global__ __launch_bounds__(256, 2)
void gemm_pre() {
    extern __shared__ char gsm[];
    const int tid = threadIdx.x, warp = tid >> 5, lane = tid & 31;
    const int gid = lane >> 2, kb = (lane & 3) << 1;
    const int m_off = (warp >> 2) << 6;   // 0,64
    const int n_off = (warp & 3) << 5;    // 0,32,64,96
    const int m0 = blockIdx.y << 7;
    const int n0 = blockIdx.x << 7;
    const int a_r = (lane & 7) + (lane & 8);
    const int a_c = (lane & 16) >> 1;
    const int b_r = (lane & 7) + ((lane & 16) >> 1);
    const int b_c = (lane & 8);

    float acc[4][4][4];
#pragma unroll
    for (int a = 0; a < 4; a++)
#pragma unroll
        for (int b = 0; b < 4; b++)
#pragma unroll
            for (int cc = 0; cc < 4; cc++) acc[a][b][cc] = 0.0f;

    auto load_stage = [&](int s, int k0) {
        char* base = gsm + s * GP_STAGE;
#pragma unroll
        for (int it = 0; it < 8; it++) {
            int op = it * 256 + tid;          // 0..2047
            int r = (op & 1023) >> 3;         // 0..127
            int c = op & 7;                   // 0..7 (16B chunks)
            if (op < 1024)
                cpa16(base + r * 144 + c * 16,
                      g_Xh + (size_t)(m0 + r) * EMBED + k0 + c * 8);
            else
                cpa16(base + 18432 + r * 144 + c * 16,
                      g_Wih + (size_t)(n0 + r) * EMBED + k0 + c * 8);
        }
        cpa_commit();
    };

    auto compute = [&](int s) {
        uint32_t sA = sptr(gsm + s * GP_STAGE);
        uint32_t sAo = sA + (uint32_t)((m_off + a_r) * 72 + a_c) * 2;
        uint32_t sBo = sA + 18432 + (uint32_t)((n_off + b_r) * 72 + b_c) * 2;
#pragma unroll
        for (int ks = 0; ks < 64; ks += 16) {
            uint32_t ah[4][4], bh4[2][4];
#pragma unroll
            for (int mf = 0; mf < 4; mf++)
                ldsm4(ah[mf], sAo + (uint32_t)(mf * 16 * 72 + ks) * 2);
#pragma unroll
            for (int nh = 0; nh < 2; nh++)
                ldsm4(bh4[nh], sBo + (uint32_t)(nh * 16 * 72 + ks) * 2);
#pragma unroll
            for (int nf = 0; nf < 4; nf++) {
                const uint32_t* bh = &bh4[nf >> 1][(nf & 1) * 2];
#pragma unroll
                for (int mf = 0; mf < 4; mf++)
                    mma16816h(acc[mf][nf], ah[mf], bh);
            }
        }
    };

    const int KT = EMBED / 64;   // 8
    load_stage(0, 0);
    for (int kt = 0; kt < KT; kt++) {
        if (kt + 1 < KT) load_stage((kt + 1) & 1, (kt + 1) * 64);
        if (kt + 1 < KT) cpa_wait1(); else cpa_wait0();
        __syncthreads();
        compute(kt & 1);
        __syncthreads();
    }

#pragma unroll
    for (int mf = 0; mf < 4; mf++)
#pragma unroll
        for (int nf = 0; nf < 4; nf++) {
            int row = m0 + m_off + mf * 16 + gid;
            int col = n0 + n_off + nf * 8 + kb;
            float b0 = g_bsum[col], b1 = g_bsum[col + 1];
            if (row < TSTEPS * BATCH) {
                g_P[(size_t)row * NG + col]     = acc[mf][nf][0] + b0;
                g_P[(size_t)row * NG + col + 1] = acc[mf][nf][1] + b1;
            }
            if (row + 8 < TSTEPS * BATCH) {
                g_P[(size_t)(row + 8) * NG + col]     = acc[mf][nf][2] + b0;
                g_P[(size_t)(row + 8) * NG + col + 1] = acc[mf][nf][3] + b1;
            }
        }
}

// ---------------- persistent recurrent kernel -----------------------------
// 8 warps = 4 K-quarters (kq) x 2 N-halves (nh). Weight fragments register-
// resident across all steps; K-partials reduced through smem.
__global__ __launch_bounds__(256, 1)
void lstm_persist(const float* __restrict__ c0, const float* __restrict__ w_ans,
                  float* __restrict__ out) {
    extern __shared__ char smc[];
    const int tid = threadIdx.x, warp = tid >> 5, lane = tid & 31;
    const int gid = lane >> 2, kb = (lane & 3) << 1;
    const int kq = warp >> 1;             // 0..3 K quarter
    const int nh = warp & 1;              // 0..1 N half (16 cols)
    const int n0 = blockIdx.x << 5;
    const int j0 = blockIdx.x << 3;
    const int a_r = (lane & 7) + (lane & 8);
    const int a_c = (lane & 16) >> 1;
    const int b_r = (lane & 7) + ((lane & 16) >> 1);
    const int b_c = (lane & 8);

    // ---- load W tile [32][1024] fp16 into smem (temporarily) ----
#pragma unroll
    for (int it = 0; it < 16; it++) {
        int op = it * 256 + tid;          // 0..4095
        int r = op >> 7, c = op & 127;
        cpa16(smc + OFF_WHI + (size_t)r * 2064 + c * 16,
              g_Whh + (size_t)(n0 + r) * HDIM + c * 8);
    }
    cpa_commit();
    float* cs  = (float*)(smc + OFF_CC);
    float* was = (float*)(smc + OFF_WAS);
    if (tid < 128) {
        int b = tid >> 1, q = tid & 1;
        float4 v = *(const float4*)(c0 + (size_t)b * HDIM + j0 + q * 4);
        *(float4*)(cs + b * 8 + q * 4) = v;
    }
    if (tid < 8) was[tid] = w_ans[j0 + tid];
    cpa_wait0();
    __syncthreads();

    // ---- load weight fragments into registers (resident for all steps) ----
    uint32_t Breg[16][4];
    {
        uint32_t sWB = sptr(smc + OFF_WHI) + (uint32_t)((nh * 16 + b_r) * 1032 + b_c) * 2;
#pragma unroll
        for (int kf = 0; kf < 16; kf++)
            ldsm4(Breg[kf], sWB + (uint32_t)(kq * 256 + kf * 16) * 2);
    }
    __syncthreads();   // all warps done reading W smem; region now reusable

    const uint32_t sAB = sptr(smc + OFF_H) + (uint32_t)(a_r * 1032 + a_c) * 2;
    float* part = (float*)(smc + OFF_WHI);      // [4][64][36] f32 partials

    // P(0) prologue load into Ps buf 0 (its own group)
    {
#pragma unroll
        for (int it = 0; it < 2; it++) {
            int op = it * 256 + tid;
            int r = op >> 3, c = op & 7;
            cpa16(smc + OFF_PS + r * 128 + c * 16, g_P + (size_t)r * NG + n0 + c * 4);
        }
        cpa_commit();
    }

    for (int t = 0; t < TSTEPS; t++) {
        const __half* hsrc = g_h2 + (size_t)(t & 1) * (BATCH * HDIM);
        __half* hdst = g_h2 + (size_t)((t + 1) & 1) * (BATCH * HDIM);

        // ---- kq pair loads its K-quarter of h: 64 rows x 256 cols fp16 ----
        {
            int l64 = tid & 63;
#pragma unroll
            for (int it = 0; it < 32; it++) {
                int idx = it * 64 + l64;      // 0..2047
                int r = idx >> 5, c = idx & 31;
                cpa16(smc + OFF_H + (size_t)r * 2064 + (size_t)(kq * 512 + c * 16),
                      hsrc + (size_t)r * HDIM + kq * 256 + c * 8);
            }
            cpa_commit();
        }
        // ---- prefetch P(t+1) (dummy t=0 tile at last step) ----
        {
            int tp = (t + 1 < TSTEPS) ? (t + 1) : 0;
#pragma unroll
            for (int it = 0; it < 2; it++) {
                int op = it * 256 + tid;
                int r = op >> 3, c = op & 7;
                cpa16(smc + OFF_PS + ((t + 1) & 1) * 8192 + r * 128 + c * 16,
                      g_P + ((size_t)tp * BATCH + r) * NG + n0 + c * 4);
            }
            cpa_commit();
        }
        cpa_wait1();          // h chunk landed; P(t+1) pending
        asm volatile("bar.sync %0, 64;" :: "r"(1 + kq) : "memory");

        // ---- MMA: A ldsm only; B fragments resident ----
        float acc[4][2][4];
#pragma unroll
        for (int a = 0; a < 4; a++)
#pragma unroll
            for (int b = 0; b < 2; b++)
#pragma unroll
                for (int q = 0; q < 4; q++) acc[a][b][q] = 0.0f;

#pragma unroll
        for (int kf = 0; kf < 16; kf++) {
            uint32_t koff = (uint32_t)(kq * 256 + kf * 16) * 2;
            uint32_t ah[4][4];
#pragma unroll
            for (int mf = 0; mf < 4; mf++)
                ldsm4(ah[mf], sAB + (uint32_t)(mf * 16 * 1032) * 2 + koff);
#pragma unroll
            for (int mf = 0; mf < 4; mf++) {
                mma16816h(acc[mf][0], ah[mf], &Breg[kf][0]);
                mma16816h(acc[mf][1], ah[mf], &Breg[kf][2]);
            }
        }

        // ---- store K-partials to smem: part[kq][row][col], stride 36 ----
        {
            float* pk = part + kq * 2304;
#pragma unroll
            for (int mf = 0; mf < 4; mf++)
#pragma unroll
                for (int nf = 0; nf < 2; nf++) {
                    int col = nh * 16 + nf * 8 + kb;
                    int row = mf * 16 + gid;
                    *(float2*)(pk + row * 36 + col)       = make_float2(acc[mf][nf][0], acc[mf][nf][1]);
                    *(float2*)(pk + (row + 8) * 36 + col) = make_float2(acc[mf][nf][2], acc[mf][nf][3]);
                }
        }
        __syncthreads();

        // ---- reduce partials + cell + answer dot ----
        const float* Ps = (const float*)(smc + OFF_PS + (t & 1) * 8192);
#pragma unroll
        for (int half = 0; half < 2; half++) {
            int idx = tid + half * 256;
            int b = idx >> 3, jl = idx & 7;
            const float* pb = part + b * 36 + jl * 4;
            float4 s0 = *(const float4*)(pb);
            float4 s1 = *(const float4*)(pb + 2304);
            float4 s2 = *(const float4*)(pb + 4608);
            float4 s3 = *(const float4*)(pb + 6912);
            float4 pv = *(const float4*)(Ps + b * 32 + jl * 4);
            float gi = s0.x + s1.x + s2.x + s3.x + pv.x;
            float gf = s0.y + s1.y + s2.y + s3.y + pv.y;
            float gg = s0.z + s1.z + s2.z + s3.z + pv.z;
            float go = s0.w + s1.w + s2.w + s3.w + pv.w;
            gi = fminf(fmaxf(gi, -15.0f), 15.0f);
            gf = fminf(fmaxf(gf, -15.0f), 15.0f);
            gg = fminf(fmaxf(gg, -15.0f), 15.0f);
            go = fminf(fmaxf(go, -15.0f), 15.0f);
            float ei = ex2f(-gi * L2E);
            float ef = ex2f(-gf * L2E);
            float eo = ex2f(-go * L2E);
            float d1 = 1.0f + ei, d2 = 1.0f + ef, d3 = 1.0f + eo;
            float m12 = d1 * d2, m23 = d2 * d3, m13 = d1 * d3;
            float r = rcpf(m12 * d3);
            float si = r * m23, sf = r * m13, so = r * m12;
            float eg = ex2f(gg * L2E2);
            float tg = (eg - 1.0f) * rcpf(eg + 1.0f);
            float c = sf * cs[b * 8 + jl] + si * tg;
            cs[b * 8 + jl] = c;
            float ac = fminf(fmaxf(c * L2E2, -60.0f), 60.0f);
            float ec = ex2f(ac);
            float tc = (ec - 1.0f) * rcpf(ec + 1.0f);
            float h = so * tc;
            hdst[(size_t)b * HDIM + j0 + jl] = __float2half_rn(h);
            float p = h * was[jl];
            p += __shfl_xor_sync(0xFFFFFFFFu, p, 4);
            p += __shfl_xor_sync(0xFFFFFFFFu, p, 2);
            p += __shfl_xor_sync(0xFFFFFFFFu, p, 1);
            if (t >= SEL_START && (lane & 7) == 0)
                atomicAdd(&out[b * SEL_COUNT + (t - SEL_START)], p);
        }

        // ---- grid-wide barrier (128 CTAs, 1/SM, single wave, hard spin) ----
        __threadfence();
        __syncthreads();
        if (tid == 0) {
            atomicAdd(&g_arrive, 1u);
            unsigned tgt = (unsigned)(t + 1) * NCTA;
            while (ldv(&g_arrive) < tgt) { }
            __threadfence();
        }
        __syncthreads();
    }
}

// ---------------- launch ----------------
extern "C" void kernel_launch(void* const* d_in, const int* in_sizes, int n_in,
                              void* d_out, int out_size) {
    (void)in_sizes; (void)n_in; (void)out_size;
    const void*  prob  = d_in[0];
    const float* table = (const float*)d_in[2];
    const float* w_ih  = (const float*)d_in[3];
    const float* w_hh  = (const float*)d_in[4];
    const float* b_ih  = (const float*)d_in[5];
    const float* b_hh  = (const float*)d_in[6];
    const float* w_ans = (const float*)d_in[7];
    const float* b_ans = (const float*)d_in[8];
    const float* h0    = (const float*)d_in[9];
    const float* c0    = (const float*)d_in[10];
    float* out = (float*)d_out;

    static bool inited = false;
    if (!inited) {
        cudaFuncSetAttribute(gemm_pre,     cudaFuncAttributeMaxDynamicSharedMemorySize, GP_SMEM);
        cudaFuncSetAttribute(lstm_persist, cudaFuncAttributeMaxDynamicSharedMemorySize, SMEM_PERSIST);
        inited = true;
    }

    fused_init<<<69, 1024>>>((const int*)prob, h0, out, b_ans);
    gather_split<<<TSTEPS * BATCH, 128>>>(prob, table);
    convert_all<<<2 * NG, 256>>>(w_ih, w_hh, b_ih, b_hh);
    gemm_pre<<<dim3(NG / 128, MPAD / 128), 256, GP_SMEM>>>();
    lstm_persist<<<NCTA, 256, SMEM_PERSIST>>>(c0, w_ans, out);
}

// round 11
// speedup vs baseline: 8.4161x; 1.2488x over previous
#include <cuda_runtime.h>
#include <cuda_bf16.h>
#include <cuda_fp16.h>
#include <cstdint>

#define SEQ       128
#define BATCH     64
#define EMBED     512
#define HDIM      1024
#define NG        4096
#define TSTEPS    127
#define SEL_START 65
#define SEL_COUNT 62
#define MPAD      8192
#define NCTA      128

// ---------------- device scratch ----------------
__device__ __half g_Xh[MPAD * EMBED];          // fp16 embeddings (t-major)
__device__ __half g_Wih[NG * EMBED];           // fp16 w_ih, gate-interleaved rows
__device__ __half g_Whh[NG * HDIM];            // fp16 w_hh, gate-interleaved rows
__device__ float g_bsum[NG];
__device__ float g_P[TSTEPS * BATCH * NG];     // preacts, gate-interleaved cols
__device__ __half g_h2[2 * BATCH * HDIM];      // ping-pong h (fp16)
__device__ unsigned g_cnt[8][32];              // [quarter*2+half], 128B-spaced
__device__ int g_is64;

// ---------------- smem layout for lstm_persist (bytes) ----------------
// h buffer [32][1032] fp16 (also W staging before the loop)
#define OFF_H    0
#define OFF_PART 66048    // [4][32][68] f32 = 34816
#define OFF_PS   100864   // 2 x [32][64] f32 = 16384
#define OFF_CC   117248   // [32][16] f32 = 2048
#define OFF_WAS  119296   // [16] f32 = 64
#define SMEM_PERSIST 119360

// ---------------- gemm_pre smem: 2 stages x (A[128][72] + B[128][72]) fp16
#define GP_STAGE 36864
#define GP_SMEM  73728

// ---------------- helpers ----------------
__device__ __forceinline__ void mma16816h(float* c, const uint32_t* a, const uint32_t* b) {
    asm volatile(
        "mma.sync.aligned.m16n8k16.row.col.f32.f16.f16.f32 "
        "{%0,%1,%2,%3}, {%4,%5,%6,%7}, {%8,%9}, {%0,%1,%2,%3};\n"
        : "+f"(c[0]), "+f"(c[1]), "+f"(c[2]), "+f"(c[3])
        : "r"(a[0]), "r"(a[1]), "r"(a[2]), "r"(a[3]), "r"(b[0]), "r"(b[1]));
}
__device__ __forceinline__ void ldsm4(uint32_t* r, uint32_t saddr) {
    asm volatile("ldmatrix.sync.aligned.m8n8.x4.shared.b16 {%0,%1,%2,%3}, [%4];"
        : "=r"(r[0]), "=r"(r[1]), "=r"(r[2]), "=r"(r[3]) : "r"(saddr));
}
__device__ __forceinline__ uint32_t sptr(const void* p) {
    return (uint32_t)__cvta_generic_to_shared(p);
}
__device__ __forceinline__ void cpa16(void* smem, const void* g) {
    uint32_t s = sptr(smem);
    asm volatile("cp.async.cg.shared.global [%0], [%1], 16;\n" :: "r"(s), "l"(g));
}
__device__ __forceinline__ void cpa_commit() { asm volatile("cp.async.commit_group;\n"); }
__device__ __forceinline__ void cpa_wait1()  { asm volatile("cp.async.wait_group 1;\n"); }
__device__ __forceinline__ void cpa_wait0()  { asm volatile("cp.async.wait_group 0;\n"); }
__device__ __forceinline__ unsigned ldv(const unsigned* p) { return *(volatile const unsigned*)p; }
__device__ __forceinline__ float ex2f(float x) {
    float y; asm("ex2.approx.f32 %0, %1;" : "=f"(y) : "f"(x)); return y;
}
__device__ __forceinline__ float rcpf(float x) {
    float y; asm("rcp.approx.f32 %0, %1;" : "=f"(y) : "f"(x)); return y;
}
#define L2E  1.4426950408889634f
#define L2E2 2.8853900817779268f

// ---------------- fused init ----------------
__global__ void fused_init(const int* __restrict__ prob32, const float* __restrict__ h0,
                           float* __restrict__ out, const float* __restrict__ b_ans) {
    int bid = blockIdx.x;
    if (bid == 0) {
        __shared__ int any;
        if (threadIdx.x == 0) any = 0;
        __syncthreads();
        int local = 0;
        for (int i = 2 * threadIdx.x + 1; i < BATCH * SEQ; i += 2 * blockDim.x)
            local |= prob32[i];
        if (local) atomicOr(&any, 1);
        __syncthreads();
        if (threadIdx.x == 0) g_is64 = (any == 0) ? 1 : 0;
        if (threadIdx.x < 8) g_cnt[threadIdx.x][0] = 0u;
    } else if (bid <= 64) {
        int i = (bid - 1) * 1024 + threadIdx.x;
        g_h2[i] = __float2half_rn(h0[i]);
    } else {
        int i = (bid - 65) * 1024 + threadIdx.x;
        if (i < BATCH * SEL_COUNT) out[i] = b_ans[0];
    }
}

// ---------------- embedding gather (fp16) ----------------
__global__ void gather_split(const void* __restrict__ prob, const float* __restrict__ table) {
    int row = blockIdx.x;            // t*64 + b
    int t = row >> 6, b = row & 63;
    long long tok;
    if (g_is64) tok = ((const long long*)prob)[b * SEQ + t];
    else        tok = (long long)((const int*)prob)[b * SEQ + t];
    float4 v = ((const float4*)(table + (size_t)tok * EMBED))[threadIdx.x];
    int o = row * EMBED + threadIdx.x * 4;
    g_Xh[o + 0] = __float2half_rn(v.x);
    g_Xh[o + 1] = __float2half_rn(v.y);
    g_Xh[o + 2] = __float2half_rn(v.z);
    g_Xh[o + 3] = __float2half_rn(v.w);
}

// ---------------- weight conversion (gate-interleave: n = 4*j + g) -------
__global__ void convert_all(const float* __restrict__ w_ih, const float* __restrict__ w_hh,
                            const float* __restrict__ b_ih, const float* __restrict__ b_hh) {
    int n = blockIdx.x;
    if (n < NG) {                    // w_ih -> fp16
        int j = n >> 2, g = n & 3;
        int r = g * HDIM + j;
        if (threadIdx.x < 128) {
            float4 v = ((const float4*)(w_ih + (size_t)r * EMBED))[threadIdx.x];
            int o = n * EMBED + threadIdx.x * 4;
            g_Wih[o + 0] = __float2half_rn(v.x);
            g_Wih[o + 1] = __float2half_rn(v.y);
            g_Wih[o + 2] = __float2half_rn(v.z);
            g_Wih[o + 3] = __float2half_rn(v.w);
        }
        if (threadIdx.x == 0) g_bsum[n] = b_ih[r] + b_hh[r];
    } else {                         // w_hh -> fp16
        n -= NG;
        int j = n >> 2, g = n & 3;
        int r = g * HDIM + j;
        float4 v = ((const float4*)(w_hh + (size_t)r * HDIM))[threadIdx.x];
        int o = n * HDIM + threadIdx.x * 4;
        g_Whh[o + 0] = __float2half_rn(v.x);
        g_Whh[o + 1] = __float2half_rn(v.y);
        g_Whh[o + 2] = __float2half_rn(v.z);
        g_Whh[o + 3] = __float2half_rn(v.w);
    }
}

// ---------------- pre-GEMM: P = Xh @ Wih^T + bsum  [8192x4096, K=512] -----
__global__ __launch_bounds__(256, 2)
void gemm_pre() {
    extern __shared__ char gsm[];
    const int tid = threadIdx.x, warp = tid >> 5, lane = tid & 31;
    const int gid = lane >> 2, kb = (lane & 3) << 1;
    const int m_off = (warp >> 2) << 6;   // 0,64
    const int n_off = (warp & 3) << 5;    // 0,32,64,96
    const int m0 = blockIdx.y << 7;
    const int n0 = blockIdx.x << 7;
    const int a_r = (lane & 7) + (lane & 8);
    const int a_c = (lane & 16) >> 1;
    const int b_r = (lane & 7) + ((lane & 16) >> 1);
    const int b_c = (lane & 8);

    float acc[4][4][4];
#pragma unroll
    for (int a = 0; a < 4; a++)
#pragma unroll
        for (int b = 0; b < 4; b++)
#pragma unroll
            for (int cc = 0; cc < 4; cc++) acc[a][b][cc] = 0.0f;

    auto load_stage = [&](int s, int k0) {
        char* base = gsm + s * GP_STAGE;
#pragma unroll
        for (int it = 0; it < 8; it++) {
            int op = it * 256 + tid;
            int r = (op & 1023) >> 3;
            int c = op & 7;
            if (op < 1024)
                cpa16(base + r * 144 + c * 16,
                      g_Xh + (size_t)(m0 + r) * EMBED + k0 + c * 8);
            else
                cpa16(base + 18432 + r * 144 + c * 16,
                      g_Wih + (size_t)(n0 + r) * EMBED + k0 + c * 8);
        }
        cpa_commit();
    };

    auto compute = [&](int s) {
        uint32_t sA = sptr(gsm + s * GP_STAGE);
        uint32_t sAo = sA + (uint32_t)((m_off + a_r) * 72 + a_c) * 2;
        uint32_t sBo = sA + 18432 + (uint32_t)((n_off + b_r) * 72 + b_c) * 2;
#pragma unroll
        for (int ks = 0; ks < 64; ks += 16) {
            uint32_t ah[4][4], bh4[2][4];
#pragma unroll
            for (int mf = 0; mf < 4; mf++)
                ldsm4(ah[mf], sAo + (uint32_t)(mf * 16 * 72 + ks) * 2);
#pragma unroll
            for (int nh = 0; nh < 2; nh++)
                ldsm4(bh4[nh], sBo + (uint32_t)(nh * 16 * 72 + ks) * 2);
#pragma unroll
            for (int nf = 0; nf < 4; nf++) {
                const uint32_t* bh = &bh4[nf >> 1][(nf & 1) * 2];
#pragma unroll
                for (int mf = 0; mf < 4; mf++)
                    mma16816h(acc[mf][nf], ah[mf], bh);
            }
        }
    };

    const int KT = EMBED / 64;
    load_stage(0, 0);
    for (int kt = 0; kt < KT; kt++) {
        if (kt + 1 < KT) load_stage((kt + 1) & 1, (kt + 1) * 64);
        if (kt + 1 < KT) cpa_wait1(); else cpa_wait0();
        __syncthreads();
        compute(kt & 1);
        __syncthreads();
    }

#pragma unroll
    for (int mf = 0; mf < 4; mf++)
#pragma unroll
        for (int nf = 0; nf < 4; nf++) {
            int row = m0 + m_off + mf * 16 + gid;
            int col = n0 + n_off + nf * 8 + kb;
            float b0 = g_bsum[col], b1 = g_bsum[col + 1];
            if (row < TSTEPS * BATCH) {
                g_P[(size_t)row * NG + col]     = acc[mf][nf][0] + b0;
                g_P[(size_t)row * NG + col + 1] = acc[mf][nf][1] + b1;
            }
            if (row + 8 < TSTEPS * BATCH) {
                g_P[(size_t)(row + 8) * NG + col]     = acc[mf][nf][2] + b0;
                g_P[(size_t)(row + 8) * NG + col + 1] = acc[mf][nf][3] + b1;
            }
        }
}

// ---------------- persistent recurrent kernel -----------------------------
// 128 CTAs = 64 col-groups x 2 batch-halves. Each CTA: 64 gate-cols x 32
// batch rows, K=1024. 8 warps = 4 K-quarters x 2 N-halves; weights register-
// resident (Breg[16][8]); fine-grained sync via 8 (quarter, half) counters.
__global__ __launch_bounds__(256, 1)
void lstm_persist(const float* __restrict__ c0, const float* __restrict__ w_ans,
                  float* __restrict__ out) {
    extern __shared__ char smc[];
    const int tid = threadIdx.x, warp = tid >> 5, lane = tid & 31;
    const int gid = lane >> 2, kb = (lane & 3) << 1;
    const int kq = warp >> 1;             // 0..3 K quarter
    const int nh = warp & 1;              // 0..1 N half (32 cols)
    const int cg = blockIdx.x >> 1;       // column group 0..63
    const int bh = blockIdx.x & 1;        // batch half
    const int n0 = cg << 6;               // 64 gate cols
    const int j0 = cg << 4;               // 16 j's
    const int b0 = bh << 5;               // 32 batch rows
    const int a_r = (lane & 7) + (lane & 8);
    const int a_c = (lane & 16) >> 1;
    const int b_r = (lane & 7) + ((lane & 16) >> 1);
    const int b_c = (lane & 8);
    const int grp_c = kq * 2 + bh;            // counter this warp consumes
    const int grp_p = (cg >> 4) * 2 + bh;     // counter this CTA produces

    float* part = (float*)(smc + OFF_PART);   // [4][32][68]
    float* cs   = (float*)(smc + OFF_CC);     // [32][16]
    float* was  = (float*)(smc + OFF_WAS);    // [16]

    // ---- stage W (64 cols x 1024) through h region in two 32-col passes ----
    uint32_t Breg[16][8];
#pragma unroll
    for (int st = 0; st < 2; st++) {
#pragma unroll
        for (int it = 0; it < 16; it++) {
            int op = it * 256 + tid;          // 0..4095
            int r = op >> 7, c = op & 127;
            cpa16(smc + OFF_H + (size_t)r * 2064 + c * 16,
                  g_Whh + (size_t)(n0 + st * 32 + r) * HDIM + c * 8);
        }
        cpa_commit(); cpa_wait0();
        __syncthreads();
        if (nh == st) {
            uint32_t sW = sptr(smc + OFF_H) + (uint32_t)(b_r * 2064) + (uint32_t)b_c * 2;
#pragma unroll
            for (int kf = 0; kf < 16; kf++) {
                uint32_t koff = (uint32_t)(kq * 256 + kf * 16) * 2;
                ldsm4(&Breg[kf][0], sW + koff);
                ldsm4(&Breg[kf][4], sW + 16u * 2064 + koff);
            }
        }
        __syncthreads();
    }

    // ---- state: c slice + w_ans slice ----
    if (tid < 128) {
        int b = tid >> 2, q = tid & 3;
        float4 v = *(const float4*)(c0 + (size_t)(b0 + b) * HDIM + j0 + q * 4);
        *(float4*)(cs + b * 16 + q * 4) = v;
    }
    if (tid < 16) was[tid] = w_ans[j0 + tid];
    __syncthreads();

    const uint32_t sAB = sptr(smc + OFF_H) + (uint32_t)(a_r * 2064) + (uint32_t)a_c * 2;

    // P(0) prologue load into Ps buf 0
    {
#pragma unroll
        for (int it = 0; it < 2; it++) {
            int op = it * 256 + tid;          // 0..511
            int r = op >> 4, c = op & 15;
            cpa16(smc + OFF_PS + r * 256 + c * 16,
                  g_P + (size_t)(b0 + r) * NG + n0 + c * 4);
        }
        cpa_commit();
    }

    for (int t = 0; t < TSTEPS; t++) {
        const __half* hsrc = g_h2 + (size_t)(t & 1) * (BATCH * HDIM);
        __half* hdst = g_h2 + (size_t)((t + 1) & 1) * (BATCH * HDIM);

        // ---- prefetch P(t+1) (independent of h; overlaps poll) ----
        {
            int tp = (t + 1 < TSTEPS) ? (t + 1) : 0;
#pragma unroll
            for (int it = 0; it < 2; it++) {
                int op = it * 256 + tid;
                int r = op >> 4, c = op & 15;
                cpa16(smc + OFF_PS + ((t + 1) & 1) * 8192 + r * 256 + c * 16,
                      g_P + ((size_t)tp * BATCH + b0 + r) * NG + n0 + c * 4);
            }
            cpa_commit();
        }

        // ---- fine-grained wait: this warp's h quarter ready ----
        if (lane == 0) {
            unsigned tgt = 16u * (unsigned)t;
            while (ldv(&g_cnt[grp_c][0]) < tgt) { }
            __threadfence();
        }
        __syncwarp();

        // ---- load my half of the pair's h quarter: 16 rows x 256 cols ----
#pragma unroll
        for (int it = 0; it < 16; it++) {
            int idx = it * 32 + lane;         // 0..511
            int r = nh * 16 + (idx >> 5), ch = idx & 31;
            cpa16(smc + OFF_H + (size_t)r * 2064 + (size_t)(kq * 512 + ch * 16),
                  hsrc + (size_t)(b0 + r) * HDIM + kq * 256 + ch * 8);
        }
        cpa_commit();
        cpa_wait0();                          // h quarter + P(t+1) done
        asm volatile("bar.sync %0, 64;" :: "r"(1 + kq) : "memory");

        // ---- MMA: A ldsm only; B fragments resident ----
        float acc[2][4][4];
#pragma unroll
        for (int a = 0; a < 2; a++)
#pragma unroll
            for (int b = 0; b < 4; b++)
#pragma unroll
                for (int q = 0; q < 4; q++) acc[a][b][q] = 0.0f;

#pragma unroll
        for (int kf = 0; kf < 16; kf++) {
            uint32_t koff = (uint32_t)(kq * 256 + kf * 16) * 2;
            uint32_t ah[2][4];
            ldsm4(ah[0], sAB + koff);
            ldsm4(ah[1], sAB + 16u * 2064 + koff);
#pragma unroll
            for (int mf = 0; mf < 2; mf++)
#pragma unroll
                for (int nf = 0; nf < 4; nf++)
                    mma16816h(acc[mf][nf], ah[mf], &Breg[kf][nf * 2]);
        }

        // ---- store K-partials: part[kq][row 0..31][col 0..63] ----
        {
            float* pk = part + kq * 2176;     // 32*68
#pragma unroll
            for (int mf = 0; mf < 2; mf++)
#pragma unroll
                for (int nf = 0; nf < 4; nf++) {
                    int col = nh * 32 + nf * 8 + kb;
                    int row = mf * 16 + gid;
                    *(float2*)(pk + row * 68 + col)       = make_float2(acc[mf][nf][0], acc[mf][nf][1]);
                    *(float2*)(pk + (row + 8) * 68 + col) = make_float2(acc[mf][nf][2], acc[mf][nf][3]);
                }
        }
        __syncthreads();

        // ---- reduce partials + cell + answer dot: 512 items = (b, jj) ----
        const float* Ps = (const float*)(smc + OFF_PS + (t & 1) * 8192);
#pragma unroll
        for (int half = 0; half < 2; half++) {
            int idx = tid + half * 256;
            int b = idx >> 4, jj = idx & 15;
            const float* pb = part + b * 68 + jj * 4;
            float4 s0 = *(const float4*)(pb);
            float4 s1 = *(const float4*)(pb + 2176);
            float4 s2 = *(const float4*)(pb + 4352);
            float4 s3 = *(const float4*)(pb + 6528);
            float4 pv = *(const float4*)(Ps + b * 64 + jj * 4);
            float gi = s0.x + s1.x + s2.x + s3.x + pv.x;
            float gf = s0.y + s1.y + s2.y + s3.y + pv.y;
            float gg = s0.z + s1.z + s2.z + s3.z + pv.z;
            float go = s0.w + s1.w + s2.w + s3.w + pv.w;
            gi = fminf(fmaxf(gi, -15.0f), 15.0f);
            gf = fminf(fmaxf(gf, -15.0f), 15.0f);
            gg = fminf(fmaxf(gg, -15.0f), 15.0f);
            go = fminf(fmaxf(go, -15.0f), 15.0f);
            float ei = ex2f(-gi * L2E);
            float ef = ex2f(-gf * L2E);
            float eo = ex2f(-go * L2E);
            float d1 = 1.0f + ei, d2 = 1.0f + ef, d3 = 1.0f + eo;
            float m12 = d1 * d2, m23 = d2 * d3, m13 = d1 * d3;
            float r = rcpf(m12 * d3);
            float si = r * m23, sf = r * m13, so = r * m12;
            float eg = ex2f(gg * L2E2);
            float tg = (eg - 1.0f) * rcpf(eg + 1.0f);
            float c = sf * cs[b * 16 + jj] + si * tg;
            cs[b * 16 + jj] = c;
            float ac = fminf(fmaxf(c * L2E2, -60.0f), 60.0f);
            float ec = ex2f(ac);
            float tc = (ec - 1.0f) * rcpf(ec + 1.0f);
            float h = so * tc;
            hdst[(size_t)(b0 + b) * HDIM + j0 + jj] = __float2half_rn(h);
            float p = h * was[jj];
            p += __shfl_xor_sync(0xFFFFFFFFu, p, 8);
            p += __shfl_xor_sync(0xFFFFFFFFu, p, 4);
            p += __shfl_xor_sync(0xFFFFFFFFu, p, 2);
            p += __shfl_xor_sync(0xFFFFFFFFu, p, 1);
            if (t >= SEL_START && (lane & 15) == 0)
                atomicAdd(&out[(b0 + b) * SEL_COUNT + (t - SEL_START)], p);
        }

        // ---- publish h(t+1): fence, then single arrival on our counter ----
        __threadfence();
        __syncthreads();
        if (tid == 0) atomicAdd(&g_cnt[grp_p][0], 1u);
    }
}

// ---------------- launch ----------------
extern "C" void kernel_launch(void* const* d_in, const int* in_sizes, int n_in,
                              void* d_out, int out_size) {
    (void)in_sizes; (void)n_in; (void)out_size;
    const void*  prob  = d_in[0];
    const float* table = (const float*)d_in[2];
    const float* w_ih  = (const float*)d_in[3];
    const float* w_hh  = (const float*)d_in[4];
    const float* b_ih  = (const float*)d_in[5];
    const float* b_hh  = (const float*)d_in[6];
    const float* w_ans = (const float*)d_in[7];
    const float* b_ans = (const float*)d_in[8];
    const float* h0    = (const float*)d_in[9];
    const float* c0    = (const float*)d_in[10];
    float* out = (float*)d_out;

    static bool inited = false;
    if (!inited) {
        cudaFuncSetAttribute(gemm_pre,     cudaFuncAttributeMaxDynamicSharedMemorySize, GP_SMEM);
        cudaFuncSetAttribute(lstm_persist, cudaFuncAttributeMaxDynamicSharedMemorySize, SMEM_PERSIST);
        inited = true;
    }

    fused_init<<<69, 1024>>>((const int*)prob, h0, out, b_ans);
    gather_split<<<TSTEPS * BATCH, 128>>>(prob, table);
    convert_all<<<2 * NG, 256>>>(w_ih, w_hh, b_ih, b_hh);
    gemm_pre<<<dim3(NG / 128, MPAD / 128), 256, GP_SMEM>>>();
    lstm_persist<<<NCTA, 256, SMEM_PERSIST>>>(c0, w_ans, out);
}

// round 12
// speedup vs baseline: 8.5715x; 1.0185x over previous
#include <cuda_runtime.h>
#include <cuda_bf16.h>
#include <cuda_fp16.h>
#include <cstdint>

#define SEQ       128
#define BATCH     64
#define EMBED     512
#define HDIM      1024
#define NG        4096
#define TSTEPS    127
#define SEL_START 65
#define SEL_COUNT 62
#define MPAD      8192
#define NCTA      128

// ---------------- device scratch ----------------
__device__ __half g_Xh[MPAD * EMBED];          // fp16 embeddings (t-major)
__device__ __half g_Wih[NG * EMBED];           // fp16 w_ih, gate-interleaved rows
__device__ __half g_Whh[NG * HDIM];            // fp16 w_hh, gate-interleaved rows
__device__ float g_bsum[NG];
__device__ float g_P[TSTEPS * BATCH * NG];     // preacts, gate-interleaved cols
__device__ __half g_h2[2 * BATCH * HDIM];      // ping-pong h (fp16)
__device__ unsigned g_cnt[8][32];              // [quarter*2+half], 128B-spaced
__device__ int g_is64;

// ---------------- smem layout for lstm_persist (bytes) ----------------
#define OFF_H    0        // [32][1032] fp16 = 66048 (also W staging pre-loop)
#define OFF_PART 66048    // [4][32][68] f32 = 34816
#define OFF_PS   100864   // 2 x [32][64] f32 = 16384
#define SMEM_PERSIST 117248

// ---------------- gemm_pre smem: 3 stages x (A[128][72] + B[128][72]) fp16
#define GP_STAGE 36864
#define GP_SMEM  110592

// ---------------- helpers ----------------
__device__ __forceinline__ void mma16816h(float* c, const uint32_t* a, const uint32_t* b) {
    asm volatile(
        "mma.sync.aligned.m16n8k16.row.col.f32.f16.f16.f32 "
        "{%0,%1,%2,%3}, {%4,%5,%6,%7}, {%8,%9}, {%0,%1,%2,%3};\n"
        : "+f"(c[0]), "+f"(c[1]), "+f"(c[2]), "+f"(c[3])
        : "r"(a[0]), "r"(a[1]), "r"(a[2]), "r"(a[3]), "r"(b[0]), "r"(b[1]));
}
__device__ __forceinline__ void ldsm4(uint32_t* r, uint32_t saddr) {
    asm volatile("ldmatrix.sync.aligned.m8n8.x4.shared.b16 {%0,%1,%2,%3}, [%4];"
        : "=r"(r[0]), "=r"(r[1]), "=r"(r[2]), "=r"(r[3]) : "r"(saddr));
}
__device__ __forceinline__ uint32_t sptr(const void* p) {
    return (uint32_t)__cvta_generic_to_shared(p);
}
__device__ __forceinline__ void cpa16(void* smem, const void* g) {
    uint32_t s = sptr(smem);
    asm volatile("cp.async.cg.shared.global [%0], [%1], 16;\n" :: "r"(s), "l"(g));
}
__device__ __forceinline__ void cpa_commit() { asm volatile("cp.async.commit_group;\n"); }
__device__ __forceinline__ void cpa_wait1()  { asm volatile("cp.async.wait_group 1;\n"); }
__device__ __forceinline__ void cpa_wait0()  { asm volatile("cp.async.wait_group 0;\n"); }
__device__ __forceinline__ unsigned ldv(const unsigned* p) { return *(volatile const unsigned*)p; }
__device__ __forceinline__ float ex2f(float x) {
    float y; asm("ex2.approx.f32 %0, %1;" : "=f"(y) : "f"(x)); return y;
}
__device__ __forceinline__ float rcpf(float x) {
    float y; asm("rcp.approx.f32 %0, %1;" : "=f"(y) : "f"(x)); return y;
}
#define L2E  1.4426950408889634f
#define L2E2 2.8853900817779268f

// ---------------- fused init (detect + h0 + out) ----------------
__global__ void fused_init(const int* __restrict__ prob32, const float* __restrict__ h0,
                           float* __restrict__ out, const float* __restrict__ b_ans) {
    int bid = blockIdx.x;
    if (bid == 0) {
        __shared__ int any;
        if (threadIdx.x == 0) any = 0;
        __syncthreads();
        int local = 0;
        for (int i = 2 * threadIdx.x + 1; i < BATCH * SEQ; i += 2 * blockDim.x)
            local |= prob32[i];
        if (local) atomicOr(&any, 1);
        __syncthreads();
        if (threadIdx.x == 0) g_is64 = (any == 0) ? 1 : 0;
        if (threadIdx.x < 8) g_cnt[threadIdx.x][0] = 0u;
    } else if (bid <= 64) {
        int i = (bid - 1) * 1024 + threadIdx.x;
        g_h2[i] = __float2half_rn(h0[i]);
    } else {
        int i = (bid - 65) * 1024 + threadIdx.x;
        if (i < BATCH * SEL_COUNT) out[i] = b_ans[0];
    }
}

// ---------------- merged prep: gather + weight conversion ----------------
// blocks [0,4096): w_ih; [4096,8192): w_hh; [8192,12256): gather (2 rows each)
__global__ void prep_all(const void* __restrict__ prob, const float* __restrict__ table,
                         const float* __restrict__ w_ih, const float* __restrict__ w_hh,
                         const float* __restrict__ b_ih, const float* __restrict__ b_hh) {
    int bid = blockIdx.x;
    int tid = threadIdx.x;
    if (bid < NG) {                       // w_ih -> fp16 (gate-interleaved)
        int n = bid;
        int j = n >> 2, g = n & 3;
        int r = g * HDIM + j;
        if (tid < 128) {
            float4 v = ((const float4*)(w_ih + (size_t)r * EMBED))[tid];
            int o = n * EMBED + tid * 4;
            g_Wih[o + 0] = __float2half_rn(v.x);
            g_Wih[o + 1] = __float2half_rn(v.y);
            g_Wih[o + 2] = __float2half_rn(v.z);
            g_Wih[o + 3] = __float2half_rn(v.w);
        }
        if (tid == 0) g_bsum[n] = b_ih[r] + b_hh[r];
    } else if (bid < 2 * NG) {            // w_hh -> fp16 (gate-interleaved)
        int n = bid - NG;
        int j = n >> 2, g = n & 3;
        int r = g * HDIM + j;
        float4 v = ((const float4*)(w_hh + (size_t)r * HDIM))[tid];
        int o = n * HDIM + tid * 4;
        g_Whh[o + 0] = __float2half_rn(v.x);
        g_Whh[o + 1] = __float2half_rn(v.y);
        g_Whh[o + 2] = __float2half_rn(v.z);
        g_Whh[o + 3] = __float2half_rn(v.w);
    } else {                              // gather: 2 rows per block
        int row = (bid - 2 * NG) * 2 + (tid >> 7);
        if (row < TSTEPS * BATCH) {
            int t = row >> 6, b = row & 63;
            long long tok;
            if (g_is64) tok = ((const long long*)prob)[b * SEQ + t];
            else        tok = (long long)((const int*)prob)[b * SEQ + t];
            int lt = tid & 127;
            float4 v = ((const float4*)(table + (size_t)tok * EMBED))[lt];
            int o = row * EMBED + lt * 4;
            g_Xh[o + 0] = __float2half_rn(v.x);
            g_Xh[o + 1] = __float2half_rn(v.y);
            g_Xh[o + 2] = __float2half_rn(v.z);
            g_Xh[o + 3] = __float2half_rn(v.w);
        }
    }
}

// ---------------- pre-GEMM: P = Xh @ Wih^T + bsum  [8192x4096, K=512] -----
// fp16, BM=128 BN=128 BK=64, 3-stage cp.async pipeline, 1 sync/iter.
__global__ __launch_bounds__(256, 2)
void gemm_pre() {
    extern __shared__ char gsm[];
    const int tid = threadIdx.x, warp = tid >> 5, lane = tid & 31;
    const int gid = lane >> 2, kb = (lane & 3) << 1;
    const int m_off = (warp >> 2) << 6;   // 0,64
    const int n_off = (warp & 3) << 5;    // 0,32,64,96
    const int m0 = blockIdx.y << 7;
    const int n0 = blockIdx.x << 7;
    const int a_r = (lane & 7) + (lane & 8);
    const int a_c = (lane & 16) >> 1;
    const int b_r = (lane & 7) + ((lane & 16) >> 1);
    const int b_c = (lane & 8);

    float acc[4][4][4];
#pragma unroll
    for (int a = 0; a < 4; a++)
#pragma unroll
        for (int b = 0; b < 4; b++)
#pragma unroll
            for (int cc = 0; cc < 4; cc++) acc[a][b][cc] = 0.0f;

    auto load_stage = [&](int s, int k0) {
        char* base = gsm + s * GP_STAGE;
#pragma unroll
        for (int it = 0; it < 8; it++) {
            int op = it * 256 + tid;
            int r = (op & 1023) >> 3;
            int c = op & 7;
            if (op < 1024)
                cpa16(base + r * 144 + c * 16,
                      g_Xh + (size_t)(m0 + r) * EMBED + k0 + c * 8);
            else
                cpa16(base + 18432 + r * 144 + c * 16,
                      g_Wih + (size_t)(n0 + r) * EMBED + k0 + c * 8);
        }
        cpa_commit();
    };

    auto compute = [&](int s) {
        uint32_t sA = sptr(gsm + s * GP_STAGE);
        uint32_t sAo = sA + (uint32_t)((m_off + a_r) * 72 + a_c) * 2;
        uint32_t sBo = sA + 18432 + (uint32_t)((n_off + b_r) * 72 + b_c) * 2;
#pragma unroll
        for (int ks = 0; ks < 64; ks += 16) {
            uint32_t ah[4][4], bh4[2][4];
#pragma unroll
            for (int mf = 0; mf < 4; mf++)
                ldsm4(ah[mf], sAo + (uint32_t)(mf * 16 * 72 + ks) * 2);
#pragma unroll
            for (int nh = 0; nh < 2; nh++)
                ldsm4(bh4[nh], sBo + (uint32_t)(nh * 16 * 72 + ks) * 2);
#pragma unroll
            for (int nf = 0; nf < 4; nf++) {
                const uint32_t* bh = &bh4[nf >> 1][(nf & 1) * 2];
#pragma unroll
                for (int mf = 0; mf < 4; mf++)
                    mma16816h(acc[mf][nf], ah[mf], bh);
            }
        }
    };

    const int KT = EMBED / 64;   // 8
    load_stage(0, 0);
    load_stage(1, 64);
    for (int kt = 0; kt < KT; kt++) {
        if (kt < KT - 1) cpa_wait1(); else cpa_wait0();
        __syncthreads();
        if (kt + 2 < KT) load_stage((kt + 2) % 3, (kt + 2) * 64);
        compute(kt % 3);
    }

#pragma unroll
    for (int mf = 0; mf < 4; mf++)
#pragma unroll
        for (int nf = 0; nf < 4; nf++) {
            int row = m0 + m_off + mf * 16 + gid;
            int col = n0 + n_off + nf * 8 + kb;
            float b0 = g_bsum[col], b1 = g_bsum[col + 1];
            if (row < TSTEPS * BATCH) {
                g_P[(size_t)row * NG + col]     = acc[mf][nf][0] + b0;
                g_P[(size_t)row * NG + col + 1] = acc[mf][nf][1] + b1;
            }
            if (row + 8 < TSTEPS * BATCH) {
                g_P[(size_t)(row + 8) * NG + col]     = acc[mf][nf][2] + b0;
                g_P[(size_t)(row + 8) * NG + col + 1] = acc[mf][nf][3] + b1;
            }
        }
}

// ---------------- persistent recurrent kernel -----------------------------
// 128 CTAs = 64 col-groups x 2 batch-halves; 8 warps = 4 K-quarters x 2
// N-halves; weights register-resident; c-state & w_ans in registers;
// publish-early: h store + counter bump BEFORE the answer-dot epilogue.
__global__ __launch_bounds__(256, 1)
void lstm_persist(const float* __restrict__ c0, const float* __restrict__ w_ans,
                  float* __restrict__ out) {
    extern __shared__ char smc[];
    const int tid = threadIdx.x, warp = tid >> 5, lane = tid & 31;
    const int gid = lane >> 2, kb = (lane & 3) << 1;
    const int kq = warp >> 1;             // 0..3 K quarter
    const int nh = warp & 1;              // 0..1 N half (32 cols)
    const int cg = blockIdx.x >> 1;       // column group 0..63
    const int bh = blockIdx.x & 1;        // batch half
    const int n0 = cg << 6;               // 64 gate cols
    const int j0 = cg << 4;               // 16 j's
    const int b0 = bh << 5;               // 32 batch rows
    const int a_r = (lane & 7) + (lane & 8);
    const int a_c = (lane & 16) >> 1;
    const int b_r = (lane & 7) + ((lane & 16) >> 1);
    const int b_c = (lane & 8);
    const int grp_c = kq * 2 + bh;            // counter this warp consumes
    const int grp_p = (cg >> 4) * 2 + bh;     // counter this CTA produces

    float* part = (float*)(smc + OFF_PART);   // [4][32][68]

    // ---- stage W (64 cols x 1024) through h region in two 32-col passes ----
    uint32_t Breg[16][8];
#pragma unroll
    for (int st = 0; st < 2; st++) {
#pragma unroll
        for (int it = 0; it < 16; it++) {
            int op = it * 256 + tid;          // 0..4095
            int r = op >> 7, c = op & 127;
            cpa16(smc + OFF_H + (size_t)r * 2064 + c * 16,
                  g_Whh + (size_t)(n0 + st * 32 + r) * HDIM + c * 8);
        }
        cpa_commit(); cpa_wait0();
        __syncthreads();
        if (nh == st) {
            uint32_t sW = sptr(smc + OFF_H) + (uint32_t)(b_r * 2064) + (uint32_t)b_c * 2;
#pragma unroll
            for (int kf = 0; kf < 16; kf++) {
                uint32_t koff = (uint32_t)(kq * 256 + kf * 16) * 2;
                ldsm4(&Breg[kf][0], sW + koff);
                ldsm4(&Breg[kf][4], sW + 16u * 2064 + koff);
            }
        }
        __syncthreads();
    }

    // ---- per-thread state in registers: c and w_ans for (b, jj) items ----
    float c_reg[2], was_reg[2];
#pragma unroll
    for (int half = 0; half < 2; half++) {
        int idx = tid + half * 256;
        int b = idx >> 4, jj = idx & 15;
        c_reg[half]   = c0[(size_t)(b0 + b) * HDIM + j0 + jj];
        was_reg[half] = w_ans[j0 + jj];
    }

    const uint32_t sAB = sptr(smc + OFF_H) + (uint32_t)(a_r * 2064) + (uint32_t)a_c * 2;

    // P(0) prologue load into Ps buf 0
    {
#pragma unroll
        for (int it = 0; it < 2; it++) {
            int op = it * 256 + tid;          // 0..511
            int r = op >> 4, c = op & 15;
            cpa16(smc + OFF_PS + r * 256 + c * 16,
                  g_P + (size_t)(b0 + r) * NG + n0 + c * 4);
        }
        cpa_commit();
    }

    for (int t = 0; t < TSTEPS; t++) {
        const __half* hsrc = g_h2 + (size_t)(t & 1) * (BATCH * HDIM);
        __half* hdst = g_h2 + (size_t)((t + 1) & 1) * (BATCH * HDIM);

        // ---- prefetch P(t+1) (independent of h; overlaps poll) ----
        {
            int tp = (t + 1 < TSTEPS) ? (t + 1) : 0;
#pragma unroll
            for (int it = 0; it < 2; it++) {
                int op = it * 256 + tid;
                int r = op >> 4, c = op & 15;
                cpa16(smc + OFF_PS + ((t + 1) & 1) * 8192 + r * 256 + c * 16,
                      g_P + ((size_t)tp * BATCH + b0 + r) * NG + n0 + c * 4);
            }
            cpa_commit();
        }

        // ---- fine-grained wait: this warp's h quarter ready ----
        if (lane == 0) {
            unsigned tgt = 16u * (unsigned)t;
            while (ldv(&g_cnt[grp_c][0]) < tgt) { }
            __threadfence();
        }
        __syncwarp();

        // ---- load my half of the pair's h quarter: 16 rows x 256 cols ----
#pragma unroll
        for (int it = 0; it < 16; it++) {
            int idx = it * 32 + lane;         // 0..511
            int r = nh * 16 + (idx >> 5), ch = idx & 31;
            cpa16(smc + OFF_H + (size_t)r * 2064 + (size_t)(kq * 512 + ch * 16),
                  hsrc + (size_t)(b0 + r) * HDIM + kq * 256 + ch * 8);
        }
        cpa_commit();
        cpa_wait0();                          // h quarter + P(t+1) done
        asm volatile("bar.sync %0, 64;" :: "r"(1 + kq) : "memory");

        // ---- MMA: A ldsm only; B fragments resident ----
        float acc[2][4][4];
#pragma unroll
        for (int a = 0; a < 2; a++)
#pragma unroll
            for (int b = 0; b < 4; b++)
#pragma unroll
                for (int q = 0; q < 4; q++) acc[a][b][q] = 0.0f;

#pragma unroll
        for (int kf = 0; kf < 16; kf++) {
            uint32_t koff = (uint32_t)(kq * 256 + kf * 16) * 2;
            uint32_t ah[2][4];
            ldsm4(ah[0], sAB + koff);
            ldsm4(ah[1], sAB + 16u * 2064 + koff);
#pragma unroll
            for (int mf = 0; mf < 2; mf++)
#pragma unroll
                for (int nf = 0; nf < 4; nf++)
                    mma16816h(acc[mf][nf], ah[mf], &Breg[kf][nf * 2]);
        }

        // ---- store K-partials: part[kq][row 0..31][col 0..63] ----
        {
            float* pk = part + kq * 2176;     // 32*68
#pragma unroll
            for (int mf = 0; mf < 2; mf++)
#pragma unroll
                for (int nf = 0; nf < 4; nf++) {
                    int col = nh * 32 + nf * 8 + kb;
                    int row = mf * 16 + gid;
                    *(float2*)(pk + row * 68 + col)       = make_float2(acc[mf][nf][0], acc[mf][nf][1]);
                    *(float2*)(pk + (row + 8) * 68 + col) = make_float2(acc[mf][nf][2], acc[mf][nf][3]);
                }
        }
        __syncthreads();

        // ---- reduce partials + cell; store h; stash answer-dot term ----
        const float* Ps = (const float*)(smc + OFF_PS + (t & 1) * 8192);
        float pstash[2];
#pragma unroll
        for (int half = 0; half < 2; half++) {
            int idx = tid + half * 256;
            int b = idx >> 4, jj = idx & 15;
            const float* pb = part + b * 68 + jj * 4;
            float4 s0 = *(const float4*)(pb);
            float4 s1 = *(const float4*)(pb + 2176);
            float4 s2 = *(const float4*)(pb + 4352);
            float4 s3 = *(const float4*)(pb + 6528);
            float4 pv = *(const float4*)(Ps + b * 64 + jj * 4);
            float gi = s0.x + s1.x + s2.x + s3.x + pv.x;
            float gf = s0.y + s1.y + s2.y + s3.y + pv.y;
            float gg = s0.z + s1.z + s2.z + s3.z + pv.z;
            float go = s0.w + s1.w + s2.w + s3.w + pv.w;
            gi = fminf(fmaxf(gi, -15.0f), 15.0f);
            gf = fminf(fmaxf(gf, -15.0f), 15.0f);
            gg = fminf(fmaxf(gg, -15.0f), 15.0f);
            go = fminf(fmaxf(go, -15.0f), 15.0f);
            float ei = ex2f(-gi * L2E);
            float ef = ex2f(-gf * L2E);
            float eo = ex2f(-go * L2E);
            float d1 = 1.0f + ei, d2 = 1.0f + ef, d3 = 1.0f + eo;
            float m12 = d1 * d2, m23 = d2 * d3, m13 = d1 * d3;
            float r = rcpf(m12 * d3);
            float si = r * m23, sf = r * m13, so = r * m12;
            float eg = ex2f(gg * L2E2);
            float tg = (eg - 1.0f) * rcpf(eg + 1.0f);
            float c = sf * c_reg[half] + si * tg;
            c_reg[half] = c;
            float ac = fminf(fmaxf(c * L2E2, -60.0f), 60.0f);
            float ec = ex2f(ac);
            float tc = (ec - 1.0f) * rcpf(ec + 1.0f);
            float h = so * tc;
            hdst[(size_t)(b0 + b) * HDIM + j0 + jj] = __float2half_rn(h);
            pstash[half] = h * was_reg[half];
        }

        // ---- publish h(t+1) FIRST (critical path), epilogue after ----
        __threadfence();
        __syncthreads();
        if (tid == 0) atomicAdd(&g_cnt[grp_p][0], 1u);

        if (t >= SEL_START) {
#pragma unroll
            for (int half = 0; half < 2; half++) {
                int idx = tid + half * 256;
                int b = idx >> 4;
                float p = pstash[half];
                p += __shfl_xor_sync(0xFFFFFFFFu, p, 8);
                p += __shfl_xor_sync(0xFFFFFFFFu, p, 4);
                p += __shfl_xor_sync(0xFFFFFFFFu, p, 2);
                p += __shfl_xor_sync(0xFFFFFFFFu, p, 1);
                if ((lane & 15) == 0)
                    atomicAdd(&out[(b0 + b) * SEL_COUNT + (t - SEL_START)], p);
            }
        }
    }
}

// ---------------- launch ----------------
extern "C" void kernel_launch(void* const* d_in, const int* in_sizes, int n_in,
                              void* d_out, int out_size) {
    (void)in_sizes; (void)n_in; (void)out_size;
    const void*  prob  = d_in[0];
    const float* table = (const float*)d_in[2];
    const float* w_ih  = (const float*)d_in[3];
    const float* w_hh  = (const float*)d_in[4];
    const float* b_ih  = (const float*)d_in[5];
    const float* b_hh  = (const float*)d_in[6];
    const float* w_ans = (const float*)d_in[7];
    const float* b_ans = (const float*)d_in[8];
    const float* h0    = (const float*)d_in[9];
    const float* c0    = (const float*)d_in[10];
    float* out = (float*)d_out;

    static bool inited = false;
    if (!inited) {
        cudaFuncSetAttribute(gemm_pre,     cudaFuncAttributeMaxDynamicSharedMemorySize, GP_SMEM);
        cudaFuncSetAttribute(lstm_persist, cudaFuncAttributeMaxDynamicSharedMemorySize, SMEM_PERSIST);
        inited = true;
    }

    fused_init<<<69, 1024>>>((const int*)prob, h0, out, b_ans);
    prep_all<<<2 * NG + (TSTEPS * BATCH + 1) / 2, 256>>>(prob, table, w_ih, w_hh, b_ih, b_hh);
    gemm_pre<<<dim3(NG / 128, MPAD / 128), 256, GP_SMEM>>>();
    lstm_persist<<<NCTA, 256, SMEM_PERSIST>>>(c0, w_ans, out);
}

// round 13
// speedup vs baseline: 8.8453x; 1.0319x over previous
#include <cuda_runtime.h>
#include <cuda_bf16.h>
#include <cuda_fp16.h>
#include <cstdint>

#define SEQ       128
#define BATCH     64
#define EMBED     512
#define HDIM      1024
#define NG        4096
#define TSTEPS    127
#define SEL_START 65
#define SEL_COUNT 62
#define MPAD      8192
#define NCTA      128

// ---------------- device scratch ----------------
__device__ __half g_Xh[MPAD * EMBED];          // fp16 embeddings (t-major)
__device__ __half g_Wih[NG * EMBED];           // fp16 w_ih, gate-interleaved rows
__device__ __half g_Whh[NG * HDIM];            // fp16 w_hh, gate-interleaved rows
__device__ float g_bsum[NG];
__device__ float g_P[TSTEPS * BATCH * NG];     // preacts, gate-interleaved cols
__device__ __half g_h2[2 * BATCH * HDIM];      // ping-pong h (fp16)
__device__ unsigned g_cnt[8][32];              // [quarter*2+half], 128B-spaced
__device__ int g_is64;

// ---------------- smem layout for lstm_persist (bytes) ----------------
#define OFF_H    0        // [32][1032] fp16 = 66048 (also W staging pre-loop)
#define OFF_PART 66048    // [4][32][68] f32 = 34816
#define OFF_PS   100864   // 2 x [32][64] f32 = 16384
#define SMEM_PERSIST 117248

// ---------------- gemm_pre smem: 3 stages x (A[128][72] + B[128][72]) fp16
#define GP_STAGE 36864
#define GP_SMEM  110592

// ---------------- helpers ----------------
__device__ __forceinline__ void mma16816h(float* c, const uint32_t* a, const uint32_t* b) {
    asm volatile(
        "mma.sync.aligned.m16n8k16.row.col.f32.f16.f16.f32 "
        "{%0,%1,%2,%3}, {%4,%5,%6,%7}, {%8,%9}, {%0,%1,%2,%3};\n"
        : "+f"(c[0]), "+f"(c[1]), "+f"(c[2]), "+f"(c[3])
        : "r"(a[0]), "r"(a[1]), "r"(a[2]), "r"(a[3]), "r"(b[0]), "r"(b[1]));
}
__device__ __forceinline__ void ldsm4(uint32_t* r, uint32_t saddr) {
    asm volatile("ldmatrix.sync.aligned.m8n8.x4.shared.b16 {%0,%1,%2,%3}, [%4];"
        : "=r"(r[0]), "=r"(r[1]), "=r"(r[2]), "=r"(r[3]) : "r"(saddr));
}
__device__ __forceinline__ uint32_t sptr(const void* p) {
    return (uint32_t)__cvta_generic_to_shared(p);
}
__device__ __forceinline__ void cpa16(void* smem, const void* g) {
    uint32_t s = sptr(smem);
    asm volatile("cp.async.cg.shared.global [%0], [%1], 16;\n" :: "r"(s), "l"(g));
}
__device__ __forceinline__ void cpa_commit() { asm volatile("cp.async.commit_group;\n"); }
__device__ __forceinline__ void cpa_wait2()  { asm volatile("cp.async.wait_group 2;\n"); }
__device__ __forceinline__ void cpa_wait1()  { asm volatile("cp.async.wait_group 1;\n"); }
__device__ __forceinline__ void cpa_wait0()  { asm volatile("cp.async.wait_group 0;\n"); }
__device__ __forceinline__ unsigned ldv(const unsigned* p) { return *(volatile const unsigned*)p; }
__device__ __forceinline__ float ex2f(float x) {
    float y; asm("ex2.approx.f32 %0, %1;" : "=f"(y) : "f"(x)); return y;
}
__device__ __forceinline__ float rcpf(float x) {
    float y; asm("rcp.approx.f32 %0, %1;" : "=f"(y) : "f"(x)); return y;
}
#define L2E  1.4426950408889634f
#define L2E2 2.8853900817779268f

// ---------------- fused init (detect + h0 + out) ----------------
__global__ void fused_init(const int* __restrict__ prob32, const float* __restrict__ h0,
                           float* __restrict__ out, const float* __restrict__ b_ans) {
    int bid = blockIdx.x;
    if (bid == 0) {
        __shared__ int any;
        if (threadIdx.x == 0) any = 0;
        __syncthreads();
        int local = 0;
        for (int i = 2 * threadIdx.x + 1; i < BATCH * SEQ; i += 2 * blockDim.x)
            local |= prob32[i];
        if (local) atomicOr(&any, 1);
        __syncthreads();
        if (threadIdx.x == 0) g_is64 = (any == 0) ? 1 : 0;
        if (threadIdx.x < 8) g_cnt[threadIdx.x][0] = 0u;
    } else if (bid <= 64) {
        int i = (bid - 1) * 1024 + threadIdx.x;
        g_h2[i] = __float2half_rn(h0[i]);
    } else {
        int i = (bid - 65) * 1024 + threadIdx.x;
        if (i < BATCH * SEL_COUNT) out[i] = b_ans[0];
    }
}

// ---------------- merged prep: gather + weight conversion ----------------
__global__ void prep_all(const void* __restrict__ prob, const float* __restrict__ table,
                         const float* __restrict__ w_ih, const float* __restrict__ w_hh,
                         const float* __restrict__ b_ih, const float* __restrict__ b_hh) {
    int bid = blockIdx.x;
    int tid = threadIdx.x;
    if (bid < NG) {                       // w_ih -> fp16 (gate-interleaved)
        int n = bid;
        int j = n >> 2, g = n & 3;
        int r = g * HDIM + j;
        if (tid < 128) {
            float4 v = ((const float4*)(w_ih + (size_t)r * EMBED))[tid];
            int o = n * EMBED + tid * 4;
            g_Wih[o + 0] = __float2half_rn(v.x);
            g_Wih[o + 1] = __float2half_rn(v.y);
            g_Wih[o + 2] = __float2half_rn(v.z);
            g_Wih[o + 3] = __float2half_rn(v.w);
        }
        if (tid == 0) g_bsum[n] = b_ih[r] + b_hh[r];
    } else if (bid < 2 * NG) {            // w_hh -> fp16 (gate-interleaved)
        int n = bid - NG;
        int j = n >> 2, g = n & 3;
        int r = g * HDIM + j;
        float4 v = ((const float4*)(w_hh + (size_t)r * HDIM))[tid];
        int o = n * HDIM + tid * 4;
        g_Whh[o + 0] = __float2half_rn(v.x);
        g_Whh[o + 1] = __float2half_rn(v.y);
        g_Whh[o + 2] = __float2half_rn(v.z);
        g_Whh[o + 3] = __float2half_rn(v.w);
    } else {                              // gather: 2 rows per block
        int row = (bid - 2 * NG) * 2 + (tid >> 7);
        if (row < TSTEPS * BATCH) {
            int t = row >> 6, b = row & 63;
            long long tok;
            if (g_is64) tok = ((const long long*)prob)[b * SEQ + t];
            else        tok = (long long)((const int*)prob)[b * SEQ + t];
            int lt = tid & 127;
            float4 v = ((const float4*)(table + (size_t)tok * EMBED))[lt];
            int o = row * EMBED + lt * 4;
            g_Xh[o + 0] = __float2half_rn(v.x);
            g_Xh[o + 1] = __float2half_rn(v.y);
            g_Xh[o + 2] = __float2half_rn(v.z);
            g_Xh[o + 3] = __float2half_rn(v.w);
        }
    }
}

// ---------------- pre-GEMM: P = Xh @ Wih^T + bsum  [8192x4096, K=512] -----
__global__ __launch_bounds__(256, 2)
void gemm_pre() {
    extern __shared__ char gsm[];
    const int tid = threadIdx.x, warp = tid >> 5, lane = tid & 31;
    const int gid = lane >> 2, kb = (lane & 3) << 1;
    const int m_off = (warp >> 2) << 6;   // 0,64
    const int n_off = (warp & 3) << 5;    // 0,32,64,96
    const int m0 = blockIdx.y << 7;
    const int n0 = blockIdx.x << 7;
    const int a_r = (lane & 7) + (lane & 8);
    const int a_c = (lane & 16) >> 1;
    const int b_r = (lane & 7) + ((lane & 16) >> 1);
    const int b_c = (lane & 8);

    float acc[4][4][4];
#pragma unroll
    for (int a = 0; a < 4; a++)
#pragma unroll
        for (int b = 0; b < 4; b++)
#pragma unroll
            for (int cc = 0; cc < 4; cc++) acc[a][b][cc] = 0.0f;

    auto load_stage = [&](int s, int k0) {
        char* base = gsm + s * GP_STAGE;
#pragma unroll
        for (int it = 0; it < 8; it++) {
            int op = it * 256 + tid;
            int r = (op & 1023) >> 3;
            int c = op & 7;
            if (op < 1024)
                cpa16(base + r * 144 + c * 16,
                      g_Xh + (size_t)(m0 + r) * EMBED + k0 + c * 8);
            else
                cpa16(base + 18432 + r * 144 + c * 16,
                      g_Wih + (size_t)(n0 + r) * EMBED + k0 + c * 8);
        }
        cpa_commit();
    };

    auto compute = [&](int s) {
        uint32_t sA = sptr(gsm + s * GP_STAGE);
        uint32_t sAo = sA + (uint32_t)((m_off + a_r) * 72 + a_c) * 2;
        uint32_t sBo = sA + 18432 + (uint32_t)((n_off + b_r) * 72 + b_c) * 2;
#pragma unroll
        for (int ks = 0; ks < 64; ks += 16) {
            uint32_t ah[4][4], bh4[2][4];
#pragma unroll
            for (int mf = 0; mf < 4; mf++)
                ldsm4(ah[mf], sAo + (uint32_t)(mf * 16 * 72 + ks) * 2);
#pragma unroll
            for (int nh = 0; nh < 2; nh++)
                ldsm4(bh4[nh], sBo + (uint32_t)(nh * 16 * 72 + ks) * 2);
#pragma unroll
            for (int nf = 0; nf < 4; nf++) {
                const uint32_t* bh = &bh4[nf >> 1][(nf & 1) * 2];
#pragma unroll
                for (int mf = 0; mf < 4; mf++)
                    mma16816h(acc[mf][nf], ah[mf], bh);
            }
        }
    };

    const int KT = EMBED / 64;   // 8
    load_stage(0, 0);
    load_stage(1, 64);
    for (int kt = 0; kt < KT; kt++) {
        if (kt < KT - 1) cpa_wait1(); else cpa_wait0();
        __syncthreads();
        if (kt + 2 < KT) load_stage((kt + 2) % 3, (kt + 2) * 64);
        compute(kt % 3);
    }

#pragma unroll
    for (int mf = 0; mf < 4; mf++)
#pragma unroll
        for (int nf = 0; nf < 4; nf++) {
            int row = m0 + m_off + mf * 16 + gid;
            int col = n0 + n_off + nf * 8 + kb;
            float b0 = g_bsum[col], b1 = g_bsum[col + 1];
            if (row < TSTEPS * BATCH) {
                g_P[(size_t)row * NG + col]     = acc[mf][nf][0] + b0;
                g_P[(size_t)row * NG + col + 1] = acc[mf][nf][1] + b1;
            }
            if (row + 8 < TSTEPS * BATCH) {
                g_P[(size_t)(row + 8) * NG + col]     = acc[mf][nf][2] + b0;
                g_P[(size_t)(row + 8) * NG + col + 1] = acc[mf][nf][3] + b1;
            }
        }
}

// ---------------- persistent recurrent kernel -----------------------------
// 128 CTAs = 64 col-groups x 2 batch-halves; 8 warps = 4 K-quarters x 2
// N-halves; weights register-resident; h load split in 2 K-chunks pipelined
// against MMA; publish-early epilogue.
__global__ __launch_bounds__(256, 1)
void lstm_persist(const float* __restrict__ c0, const float* __restrict__ w_ans,
                  float* __restrict__ out) {
    extern __shared__ char smc[];
    const int tid = threadIdx.x, warp = tid >> 5, lane = tid & 31;
    const int gid = lane >> 2, kb = (lane & 3) << 1;
    const int kq = warp >> 1;             // 0..3 K quarter
    const int nh = warp & 1;              // 0..1 N half (32 cols)
    const int cg = blockIdx.x >> 1;       // column group 0..63
    const int bh = blockIdx.x & 1;        // batch half
    const int n0 = cg << 6;               // 64 gate cols
    const int j0 = cg << 4;               // 16 j's
    const int b0 = bh << 5;               // 32 batch rows
    const int a_r = (lane & 7) + (lane & 8);
    const int a_c = (lane & 16) >> 1;
    const int b_r = (lane & 7) + ((lane & 16) >> 1);
    const int b_c = (lane & 8);
    const int grp_c = kq * 2 + bh;            // counter this warp consumes
    const int grp_p = (cg >> 4) * 2 + bh;     // counter this CTA produces

    float* part = (float*)(smc + OFF_PART);   // [4][32][68]

    // ---- stage W (64 cols x 1024) through h region in two 32-col passes ----
    uint32_t Breg[16][8];
#pragma unroll
    for (int st = 0; st < 2; st++) {
#pragma unroll
        for (int it = 0; it < 16; it++) {
            int op = it * 256 + tid;          // 0..4095
            int r = op >> 7, c = op & 127;
            cpa16(smc + OFF_H + (size_t)r * 2064 + c * 16,
                  g_Whh + (size_t)(n0 + st * 32 + r) * HDIM + c * 8);
        }
        cpa_commit(); cpa_wait0();
        __syncthreads();
        if (nh == st) {
            uint32_t sW = sptr(smc + OFF_H) + (uint32_t)(b_r * 2064) + (uint32_t)b_c * 2;
#pragma unroll
            for (int kf = 0; kf < 16; kf++) {
                uint32_t koff = (uint32_t)(kq * 256 + kf * 16) * 2;
                ldsm4(&Breg[kf][0], sW + koff);
                ldsm4(&Breg[kf][4], sW + 16u * 2064 + koff);
            }
        }
        __syncthreads();
    }

    // ---- per-thread state in registers: c and w_ans for (b, jj) items ----
    float c_reg[2], was_reg[2];
#pragma unroll
    for (int half = 0; half < 2; half++) {
        int idx = tid + half * 256;
        int b = idx >> 4, jj = idx & 15;
        c_reg[half]   = c0[(size_t)(b0 + b) * HDIM + j0 + jj];
        was_reg[half] = w_ans[j0 + jj];
    }

    const uint32_t sAB = sptr(smc + OFF_H) + (uint32_t)(a_r * 2064) + (uint32_t)a_c * 2;

    // P(0) prologue load into Ps buf 0
    {
#pragma unroll
        for (int it = 0; it < 2; it++) {
            int op = it * 256 + tid;          // 0..511
            int r = op >> 4, c = op & 15;
            cpa16(smc + OFF_PS + r * 256 + c * 16,
                  g_P + (size_t)(b0 + r) * NG + n0 + c * 4);
        }
        cpa_commit();
    }

    for (int t = 0; t < TSTEPS; t++) {
        const __half* hsrc = g_h2 + (size_t)(t & 1) * (BATCH * HDIM);
        __half* hdst = g_h2 + (size_t)((t + 1) & 1) * (BATCH * HDIM);

        // ---- fine-grained wait: this warp's h quarter ready ----
        if (lane == 0) {
            unsigned tgt = 16u * (unsigned)t;
            while (ldv(&g_cnt[grp_c][0]) < tgt) { }
            __threadfence();
        }
        __syncwarp();

        // ---- h quarter in 2 K-chunks (16 rows x 128 cols each per warp) ----
#pragma unroll
        for (int ck = 0; ck < 2; ck++) {
#pragma unroll
            for (int it = 0; it < 8; it++) {
                int idx = it * 32 + lane;         // 0..255
                int r = nh * 16 + (idx >> 4), ch = (idx & 15) + ck * 16;
                cpa16(smc + OFF_H + (size_t)r * 2064 + (size_t)(kq * 512 + ch * 16),
                      hsrc + (size_t)(b0 + r) * HDIM + kq * 256 + ch * 8);
            }
            cpa_commit();
        }
        // ---- prefetch P(t+1) last (consumed next step; stays in flight) ----
        {
            int tp = (t + 1 < TSTEPS) ? (t + 1) : 0;
#pragma unroll
            for (int it = 0; it < 2; it++) {
                int op = it * 256 + tid;
                int r = op >> 4, c = op & 15;
                cpa16(smc + OFF_PS + ((t + 1) & 1) * 8192 + r * 256 + c * 16,
                      g_P + ((size_t)tp * BATCH + b0 + r) * NG + n0 + c * 4);
            }
            cpa_commit();
        }

        float acc[2][4][4];
#pragma unroll
        for (int a = 0; a < 2; a++)
#pragma unroll
            for (int b = 0; b < 4; b++)
#pragma unroll
                for (int q = 0; q < 4; q++) acc[a][b][q] = 0.0f;

        // ---- chunk0 ready (also drains P(t) from last step) -> MMA kf 0..7
        cpa_wait2();
        asm volatile("bar.sync %0, 64;" :: "r"(1 + kq) : "memory");
#pragma unroll
        for (int kf = 0; kf < 8; kf++) {
            uint32_t koff = (uint32_t)(kq * 256 + kf * 16) * 2;
            uint32_t ah[2][4];
            ldsm4(ah[0], sAB + koff);
            ldsm4(ah[1], sAB + 16u * 2064 + koff);
#pragma unroll
            for (int mf = 0; mf < 2; mf++)
#pragma unroll
                for (int nf = 0; nf < 4; nf++)
                    mma16816h(acc[mf][nf], ah[mf], &Breg[kf][nf * 2]);
        }
        // ---- chunk1 ready -> MMA kf 8..15 (P(t+1) still in flight) ----
        cpa_wait1();
        asm volatile("bar.sync %0, 64;" :: "r"(1 + kq) : "memory");
#pragma unroll
        for (int kf = 8; kf < 16; kf++) {
            uint32_t koff = (uint32_t)(kq * 256 + kf * 16) * 2;
            uint32_t ah[2][4];
            ldsm4(ah[0], sAB + koff);
            ldsm4(ah[1], sAB + 16u * 2064 + koff);
#pragma unroll
            for (int mf = 0; mf < 2; mf++)
#pragma unroll
                for (int nf = 0; nf < 4; nf++)
                    mma16816h(acc[mf][nf], ah[mf], &Breg[kf][nf * 2]);
        }

        // ---- store K-partials: part[kq][row 0..31][col 0..63] ----
        {
            float* pk = part + kq * 2176;     // 32*68
#pragma unroll
            for (int mf = 0; mf < 2; mf++)
#pragma unroll
                for (int nf = 0; nf < 4; nf++) {
                    int col = nh * 32 + nf * 8 + kb;
                    int row = mf * 16 + gid;
                    *(float2*)(pk + row * 68 + col)       = make_float2(acc[mf][nf][0], acc[mf][nf][1]);
                    *(float2*)(pk + (row + 8) * 68 + col) = make_float2(acc[mf][nf][2], acc[mf][nf][3]);
                }
        }
        __syncthreads();

        // ---- reduce partials + cell; store h; stash answer-dot term ----
        const float* Ps = (const float*)(smc + OFF_PS + (t & 1) * 8192);
        float pstash[2];
#pragma unroll
        for (int half = 0; half < 2; half++) {
            int idx = tid + half * 256;
            int b = idx >> 4, jj = idx & 15;
            const float* pb = part + b * 68 + jj * 4;
            float4 s0 = *(const float4*)(pb);
            float4 s1 = *(const float4*)(pb + 2176);
            float4 s2 = *(const float4*)(pb + 4352);
            float4 s3 = *(const float4*)(pb + 6528);
            float4 pv = *(const float4*)(Ps + b * 64 + jj * 4);
            float gi = s0.x + s1.x + s2.x + s3.x + pv.x;
            float gf = s0.y + s1.y + s2.y + s3.y + pv.y;
            float gg = s0.z + s1.z + s2.z + s3.z + pv.z;
            float go = s0.w + s1.w + s2.w + s3.w + pv.w;
            gi = fminf(fmaxf(gi, -15.0f), 15.0f);
            gf = fminf(fmaxf(gf, -15.0f), 15.0f);
            gg = fminf(fmaxf(gg, -15.0f), 15.0f);
            go = fminf(fmaxf(go, -15.0f), 15.0f);
            float ei = ex2f(-gi * L2E);
            float ef = ex2f(-gf * L2E);
            float eo = ex2f(-go * L2E);
            float d1 = 1.0f + ei, d2 = 1.0f + ef, d3 = 1.0f + eo;
            float m12 = d1 * d2, m23 = d2 * d3, m13 = d1 * d3;
            float r = rcpf(m12 * d3);
            float si = r * m23, sf = r * m13, so = r * m12;
            float eg = ex2f(gg * L2E2);
            float tg = (eg - 1.0f) * rcpf(eg + 1.0f);
            float c = sf * c_reg[half] + si * tg;
            c_reg[half] = c;
            float ac = fminf(fmaxf(c * L2E2, -60.0f), 60.0f);
            float ec = ex2f(ac);
            float tc = (ec - 1.0f) * rcpf(ec + 1.0f);
            float h = so * tc;
            hdst[(size_t)(b0 + b) * HDIM + j0 + jj] = __float2half_rn(h);
            pstash[half] = h * was_reg[half];
        }

        // ---- publish h(t+1) FIRST (critical path), epilogue after ----
        __threadfence();
        __syncthreads();
        if (tid == 0) atomicAdd(&g_cnt[grp_p][0], 1u);

        if (t >= SEL_START) {
#pragma unroll
            for (int half = 0; half < 2; half++) {
                int idx = tid + half * 256;
                int b = idx >> 4;
                float p = pstash[half];
                p += __shfl_xor_sync(0xFFFFFFFFu, p, 8);
                p += __shfl_xor_sync(0xFFFFFFFFu, p, 4);
                p += __shfl_xor_sync(0xFFFFFFFFu, p, 2);
                p += __shfl_xor_sync(0xFFFFFFFFu, p, 1);
                if ((lane & 15) == 0)
                    atomicAdd(&out[(b0 + b) * SEL_COUNT + (t - SEL_START)], p);
            }
        }
    }
}

// ---------------- launch ----------------
extern "C" void kernel_launch(void* const* d_in, const int* in_sizes, int n_in,
                              void* d_out, int out_size) {
    (void)in_sizes; (void)n_in; (void)out_size;
    const void*  prob  = d_in[0];
    const float* table = (const float*)d_in[2];
    const float* w_ih  = (const float*)d_in[3];
    const float* w_hh  = (const float*)d_in[4];
    const float* b_ih  = (const float*)d_in[5];
    const float* b_hh  = (const float*)d_in[6];
    const float* w_ans = (const float*)d_in[7];
    const float* b_ans = (const float*)d_in[8];
    const float* h0    = (const float*)d_in[9];
    const float* c0    = (const float*)d_in[10];
    float* out = (float*)d_out;

    static bool inited = false;
    if (!inited) {
        cudaFuncSetAttribute(gemm_pre,     cudaFuncAttributeMaxDynamicSharedMemorySize, GP_SMEM);
        cudaFuncSetAttribute(lstm_persist, cudaFuncAttributeMaxDynamicSharedMemorySize, SMEM_PERSIST);
        inited = true;
    }

    fused_init<<<69, 1024>>>((const int*)prob, h0, out, b_ans);
    prep_all<<<2 * NG + (TSTEPS * BATCH + 1) / 2, 256>>>(prob, table, w_ih, w_hh, b_ih, b_hh);
    gemm_pre<<<dim3(NG / 128, MPAD / 128), 256, GP_SMEM>>>();
    lstm_persist<<<NCTA, 256, SMEM_PERSIST>>>(c0, w_ans, out);
}